// round 8
// baseline (speedup 1.0000x reference)
#include <cuda_runtime.h>
#include <cuda_fp16.h>
#include <math.h>
#include <stdint.h>

#define B_   2
#define S_   1024
#define HID_ 2048
#define NH_  16
#define NKV_ 2
#define HD_  128
#define G_   (NH_/NKV_)
#define TOK  (B_*S_)

#define KPRIME 4096        // fp16 2-term split on A side: [Ah | Al]; B indexed k&2047
#define NQKV   2560

// ---------------- scratch (float offsets, 16B-aligned) ----------------
#define OFF_EFF  0              // 2 (+2 pad)
#define OFF_BIAS 4              // 2560
#define OFF_APK  2564           // 2048*4096 fp16 = 4194304 floats
#define OFF_BQKV 4196868        // 2560*2048 fp16 = 2621440 floats
#define OFF_BOW  6818308        // 2048*2048 fp16 = 2097152 floats
#define OFF_QPK  8915460        // 32768*128 fp16 = 2097152 floats (plain fp16 Q)
#define OFF_KPK  11012612       // 4096*128 fp16  = 262144 floats
#define OFF_VPK  11274756       // 262144 floats
#define SCRATCH_F 11536900
__device__ __align__(256) float g_scratch[SCRATCH_F];

// ---------------- helpers ----------------
__device__ __forceinline__ uint32_t smem_u32(const void* p) {
    uint32_t a;
    asm("{ .reg .u64 t; cvta.to.shared.u64 t, %1; cvt.u32.u64 %0, t; }" : "=r"(a) : "l"(p));
    return a;
}
__device__ __forceinline__ void split_h(float f, unsigned short& h, unsigned short& l) {
    __half hh = __float2half_rn(f);
    float r = f - __half2float(hh);
    __half ll = __float2half_rn(r);
    h = __half_as_ushort(hh);
    l = __half_as_ushort(ll);
}
__device__ __forceinline__ uint32_t pack2(unsigned short a, unsigned short b) {
    return (uint32_t)a | ((uint32_t)b << 16);
}
__device__ __forceinline__ void cp_async16(uint32_t saddr, const void* gaddr) {
    asm volatile("cp.async.cg.shared.global [%0], [%1], 16;" :: "r"(saddr), "l"(gaddr));
}
__device__ __forceinline__ void cp_commit() {
    asm volatile("cp.async.commit_group;");
}
template <int N>
__device__ __forceinline__ void cp_wait() {
    asm volatile("cp.async.wait_group %0;" :: "n"(N));
}
__device__ __forceinline__ void ldsm_x4(uint32_t* f, uint32_t addr) {
    asm volatile("ldmatrix.sync.aligned.m8n8.x4.shared.b16 {%0,%1,%2,%3}, [%4];"
                 : "=r"(f[0]), "=r"(f[1]), "=r"(f[2]), "=r"(f[3]) : "r"(addr));
}
__device__ __forceinline__ void ldsm_x4_t(uint32_t* f, uint32_t addr) {
    asm volatile("ldmatrix.sync.aligned.m8n8.x4.trans.shared.b16 {%0,%1,%2,%3}, [%4];"
                 : "=r"(f[0]), "=r"(f[1]), "=r"(f[2]), "=r"(f[3]) : "r"(addr));
}
__device__ __forceinline__ void mma_16816(float* c, const uint32_t* a, uint32_t b0, uint32_t b1) {
    asm volatile(
        "mma.sync.aligned.m16n8k16.row.col.f32.f16.f16.f32 "
        "{%0,%1,%2,%3}, {%4,%5,%6,%7}, {%8,%9}, {%0,%1,%2,%3};"
        : "+f"(c[0]), "+f"(c[1]), "+f"(c[2]), "+f"(c[3])
        : "r"(a[0]), "r"(a[1]), "r"(a[2]), "r"(a[3]), "r"(b0), "r"(b1));
}
__device__ __forceinline__ uint32_t csw8(uint32_t c, uint32_t row) {  // 256B rows (16 chunks)
    return (c & 0x8u) | ((c ^ (row & 7u)) & 0x7u);
}

// ---------------- prep: eff + bias concat in one launch ----------------
__global__ void prep_kernel(const float* __restrict__ mask,
                            const float* __restrict__ qb, const float* __restrict__ kb,
                            const float* __restrict__ vb,
                            float* __restrict__ eff, float* __restrict__ bias) {
    int bx = blockIdx.x;
    if (bx < 2) {
        float s = 0.f;
        for (int i = threadIdx.x; i < S_; i += blockDim.x) s += mask[bx * S_ + i];
        #pragma unroll
        for (int off = 16; off; off >>= 1) s += __shfl_xor_sync(0xffffffffu, s, off);
        __shared__ float red[8];
        if ((threadIdx.x & 31) == 0) red[threadIdx.x >> 5] = s;
        __syncthreads();
        if (threadIdx.x == 0) {
            float t = 0.f;
            for (int i = 0; i < 8; i++) t += red[i];
            eff[bx] = t;
        }
    } else {
        int i = (bx - 2) * 256 + threadIdx.x;
        if (i < 2048) bias[i] = qb[i];
        else if (i < 2304) bias[i] = kb[i - 2048];
        else if (i < 2560) bias[i] = vb[i - 2304];
    }
}

// ---------------- pack activations X[2048x2048] f32 -> [Xh | Xl] fp16 rows of 4096 ----------------
__global__ void __launch_bounds__(256) convA_kernel(const float* __restrict__ X,
                                                    __half* __restrict__ Ap) {
    int g = blockIdx.x * 256 + threadIdx.x;
    int m = g >> 8;
    int kg = (g & 255) << 3;
    const float* xp = X + ((size_t)m << 11) + kg;
    float f[8];
    *(float4*)f       = *(const float4*)xp;
    *(float4*)(f + 4) = *(const float4*)(xp + 4);
    unsigned short h[8], l[8];
    #pragma unroll
    for (int i = 0; i < 8; i++) split_h(f[i], h[i], l[i]);
    uint4 Hi = make_uint4(pack2(h[0],h[1]), pack2(h[2],h[3]), pack2(h[4],h[5]), pack2(h[6],h[7]));
    uint4 Lo = make_uint4(pack2(l[0],l[1]), pack2(l[2],l[3]), pack2(l[4],l[5]), pack2(l[6],l[7]));
    __half* base = Ap + (size_t)m * KPRIME;
    *(uint4*)(base + kg)        = Hi;
    *(uint4*)(base + 2048 + kg) = Lo;
}

// ---------------- all weight packs in one launch ----------------
__global__ void __launch_bounds__(256) convB_all(
    const float* __restrict__ qw, const float* __restrict__ kw,
    const float* __restrict__ vw, const float* __restrict__ ow,
    __half* __restrict__ Bqkv, __half* __restrict__ Bow)
{
    __shared__ float s[32][33];
    int bx = blockIdx.x;
    const float* W; __half* Bp; int N, noff, nx;
    if (bx < 64)      { W = qw; Bp = Bqkv; N = 2048; noff = 0;    nx = bx; }
    else if (bx < 72) { W = kw; Bp = Bqkv; N = 256;  noff = 2048; nx = bx - 64; }
    else if (bx < 80) { W = vw; Bp = Bqkv; N = 256;  noff = 2304; nx = bx - 72; }
    else              { W = ow; Bp = Bow;  N = 2048; noff = 0;    nx = bx - 80; }
    int n0 = nx << 5, k0 = blockIdx.y << 5;
    int tid = threadIdx.x;
    #pragma unroll
    for (int p = 0; p < 4; p++) {
        int e = tid + p * 256;
        int ki = e >> 5, ni = e & 31;
        s[ki][ni] = W[(size_t)(k0 + ki) * N + n0 + ni];
    }
    __syncthreads();
    if (tid < 128) {
        int ni = tid >> 2, kg = (tid & 3) << 3;
        unsigned short h[8];
        #pragma unroll
        for (int j = 0; j < 8; j++) h[j] = __half_as_ushort(__float2half_rn(s[kg + j][ni]));
        uint4 Hi = make_uint4(pack2(h[0],h[1]), pack2(h[2],h[3]), pack2(h[4],h[5]), pack2(h[6],h[7]));
        *(uint4*)(Bp + (size_t)(noff + n0 + ni) * 2048 + k0 + kg) = Hi;
    }
}

// ---------------- HMMA GEMM: 128x128 CTA, 4 warps (64x64 warp tile), BK=64, 3-stage ----------------
#define BKC 64
#define STAGE_B 32768            // 16KB A + 16KB B
#define GEMM_SMEM (3 * STAGE_B)  // 98304
#define KITERS (KPRIME / BKC)    // 64

__device__ __forceinline__ void stage_load(uint32_t sbase, int stage,
                                           const __half* Ag, const __half* Bg,
                                           int k0, int tid) {
    uint32_t sa = sbase + stage * STAGE_B;
    uint32_t sb = sa + 16384;
    int kb = k0 & 2047;
    int row = tid;                       // 0..127
    uint32_t rbase = (uint32_t)row * 128;
    uint32_t r7 = row & 7u;
    const __half* ar = Ag + (size_t)row * KPRIME + k0;
    const __half* br = Bg + (size_t)row * 2048 + kb;
    #pragma unroll
    for (int c = 0; c < 8; c++) {
        uint32_t sw = ((c ^ r7) & 7u) * 16;
        cp_async16(sa + rbase + sw, ar + c * 8);
        cp_async16(sb + rbase + sw, br + c * 8);
    }
}

#define GEMM_PREAMBLE()                                                               \
    extern __shared__ char smc[];                                                     \
    uint32_t sbase = smem_u32(smc);                                                   \
    const int tid = threadIdx.x;                                                      \
    const int mt = blockIdx.y, nt = blockIdx.x;                                       \
    const int warp = tid >> 5, lane = tid & 31;                                       \
    const int wm = warp >> 1, wn = warp & 1;                                          \
    const int arow_b = wm * 64 + ((lane >> 3) & 1) * 8 + (lane & 7);                  \
    const int achi = (lane >> 4) & 1;                                                 \
    const int brow_b = wn * 64 + ((lane >> 4) & 1) * 8 + (lane & 7);                  \
    const int bclo = (lane >> 3) & 1;                                                 \
    float acc[32][4];                                                                 \
    _Pragma("unroll")                                                                 \
    for (int i = 0; i < 32; i++) { acc[i][0]=0.f; acc[i][1]=0.f; acc[i][2]=0.f; acc[i][3]=0.f; }

#define GEMM_MAINLOOP()                                                               \
    {                                                                                 \
        stage_load(sbase, 0, Ag, Bg, 0, tid);  cp_commit();                           \
        stage_load(sbase, 1, Ag, Bg, BKC, tid); cp_commit();                          \
        int cst = 0;                                                                  \
        for (int kt = 0; kt < KITERS; kt++) {                                         \
            cp_wait<1>();                                                             \
            __syncthreads();                                                          \
            if (kt + 2 < KITERS) {                                                    \
                int lst = cst + 2; if (lst >= 3) lst -= 3;                            \
                stage_load(sbase, lst, Ag, Bg, (kt + 2) * BKC, tid);                  \
            }                                                                         \
            cp_commit();                                                              \
            uint32_t sa = sbase + cst * STAGE_B;                                      \
            uint32_t sb = sa + 16384;                                                 \
            _Pragma("unroll")                                                         \
            for (int ks = 0; ks < 4; ks++) {                                          \
                uint32_t af[4][4], bf[4][4];                                          \
                _Pragma("unroll")                                                     \
                for (int m = 0; m < 4; m++) {                                         \
                    int r = arow_b + m * 16;                                          \
                    uint32_t ch = (uint32_t)(ks * 2 + achi);                          \
                    ldsm_x4(af[m], sa + r * 128 + ((ch ^ (r & 7)) & 7u) * 16);        \
                }                                                                     \
                _Pragma("unroll")                                                     \
                for (int nf = 0; nf < 4; nf++) {                                      \
                    int r = brow_b + nf * 16;                                         \
                    uint32_t ch = (uint32_t)(ks * 2 + bclo);                          \
                    ldsm_x4(bf[nf], sb + r * 128 + ((ch ^ (r & 7)) & 7u) * 16);       \
                }                                                                     \
                _Pragma("unroll")                                                     \
                for (int m = 0; m < 4; m++)                                           \
                    _Pragma("unroll")                                                 \
                    for (int nf = 0; nf < 4; nf++) {                                  \
                        mma_16816(acc[m*8 + nf*2],     af[m], bf[nf][0], bf[nf][1]);  \
                        mma_16816(acc[m*8 + nf*2 + 1], af[m], bf[nf][2], bf[nf][3]);  \
                    }                                                                 \
            }                                                                         \
            cst = (cst + 1 == 3) ? 0 : cst + 1;                                       \
        }                                                                             \
    }

// ---------------- generic GEMM (O-projection): f32 output ----------------
__global__ void __launch_bounds__(128, 2) gemm_mma_kernel(
    const __half* __restrict__ A, const __half* __restrict__ Bm,
    float* __restrict__ C, int Ntot)
{
    GEMM_PREAMBLE();
    const __half* Ag = A  + (size_t)(mt * 128) * KPRIME;
    const __half* Bg = Bm + (size_t)(nt * 128) * 2048;
    GEMM_MAINLOOP();

    #pragma unroll
    for (int m = 0; m < 4; m++) {
        int row = mt * 128 + wm * 64 + m * 16 + (lane >> 2);
        #pragma unroll
        for (int nf = 0; nf < 4; nf++) {
            #pragma unroll
            for (int hf = 0; hf < 2; hf++) {
                int idx = m*8 + nf*2 + hf;
                int col = nt * 128 + wn * 64 + nf * 16 + hf * 8 + (lane & 3) * 2;
                *(float2*)(C + (size_t)row * Ntot + col)       = make_float2(acc[idx][0], acc[idx][1]);
                *(float2*)(C + (size_t)(row + 8) * Ntot + col) = make_float2(acc[idx][2], acc[idx][3]);
            }
        }
    }
}

// ---------------- fused QKV GEMM: bias + RMSNorm + RoPE + mask + pack ----------------
__global__ void __launch_bounds__(128, 2) gemm_qkv_fused(
    const __half* __restrict__ A, const __half* __restrict__ Bm,
    const float* __restrict__ bias,
    const float* __restrict__ cosb, const float* __restrict__ sinb,
    const float* __restrict__ mask,
    const float* __restrict__ q_gamma, const float* __restrict__ k_gamma,
    __half* __restrict__ Qpk, __half* __restrict__ Kpk, __half* __restrict__ Vpk)
{
    __shared__ float ssq[2][128];
    GEMM_PREAMBLE();
    const __half* Ag = A  + (size_t)(mt * 128) * KPRIME;
    const __half* Bg = Bm + (size_t)(nt * 128) * 2048;
    GEMM_MAINLOOP();

    cp_wait<0>();
    __syncthreads();   // pipeline smem reusable

    // bias add
    #pragma unroll
    for (int nf = 0; nf < 4; nf++) {
        #pragma unroll
        for (int hf = 0; hf < 2; hf++) {
            int col = wn * 64 + nf * 16 + hf * 8 + (lane & 3) * 2;
            float b0 = bias[nt * 128 + col];
            float b1 = bias[nt * 128 + col + 1];
            #pragma unroll
            for (int m = 0; m < 4; m++) {
                int idx = m*8 + nf*2 + hf;
                acc[idx][0] += b0; acc[idx][1] += b1;
                acc[idx][2] += b0; acc[idx][3] += b1;
            }
        }
    }

    if (nt >= 18) {
        // ---- V: mask-mul, plain fp16 ----
        int kh = nt - 18;
        #pragma unroll
        for (int m = 0; m < 4; m++) {
            int t0 = mt * 128 + wm * 64 + m * 16 + (lane >> 2);
            int b0g = t0 >> 10, s0g = t0 & 1023;
            float mv0 = mask[t0], mv1 = mask[t0 + 8];
            __half* vp0 = Vpk + ((size_t)(b0g * NKV_ + kh) * S_ + s0g) * 128;
            __half* vp1 = vp0 + 8 * 128;
            #pragma unroll
            for (int nf = 0; nf < 4; nf++) {
                #pragma unroll
                for (int hf = 0; hf < 2; hf++) {
                    int idx = m*8 + nf*2 + hf;
                    int col = wn * 64 + nf * 16 + hf * 8 + (lane & 3) * 2;
                    *(__half2*)(vp0 + col) = __floats2half2_rn(acc[idx][0] * mv0, acc[idx][1] * mv0);
                    *(__half2*)(vp1 + col) = __floats2half2_rn(acc[idx][2] * mv1, acc[idx][3] * mv1);
                }
            }
        }
        return;
    }

    // ---- Q or K: RMSNorm over 128 head dims ----
    const bool isQ = (nt < 16);
    const float* gamma = isQ ? q_gamma : k_gamma;
    float* snv = (float*)smc;   // 128 x 128 f32, col rotated by 4*row

    #pragma unroll
    for (int m = 0; m < 4; m++) {
        float a0 = 0.f, a1 = 0.f;
        #pragma unroll
        for (int q = 0; q < 8; q++) {
            int idx = m*8 + q;
            a0 += acc[idx][0]*acc[idx][0] + acc[idx][1]*acc[idx][1];
            a1 += acc[idx][2]*acc[idx][2] + acc[idx][3]*acc[idx][3];
        }
        a0 += __shfl_xor_sync(0xffffffffu, a0, 1);
        a0 += __shfl_xor_sync(0xffffffffu, a0, 2);
        a1 += __shfl_xor_sync(0xffffffffu, a1, 1);
        a1 += __shfl_xor_sync(0xffffffffu, a1, 2);
        if ((lane & 3) == 0) {
            int r0 = wm * 64 + m * 16 + (lane >> 2);
            ssq[wn][r0]     = a0;
            ssq[wn][r0 + 8] = a1;
        }
    }
    __syncthreads();

    #pragma unroll
    for (int m = 0; m < 4; m++) {
        int r0 = wm * 64 + m * 16 + (lane >> 2);
        int r1 = r0 + 8;
        float rms0 = rsqrtf((ssq[0][r0] + ssq[1][r0]) * (1.0f / HD_) + 1e-6f);
        float rms1 = rsqrtf((ssq[0][r1] + ssq[1][r1]) * (1.0f / HD_) + 1e-6f);
        #pragma unroll
        for (int nf = 0; nf < 4; nf++) {
            #pragma unroll
            for (int hf = 0; hf < 2; hf++) {
                int idx = m*8 + nf*2 + hf;
                int d0 = wn * 64 + nf * 16 + hf * 8 + (lane & 3) * 2;
                float g0 = gamma[d0], g1 = gamma[d0 + 1];
                snv[r0 * 128 + ((d0     + 4 * r0) & 127)] = acc[idx][0] * rms0 * g0;
                snv[r0 * 128 + ((d0 + 1 + 4 * r0) & 127)] = acc[idx][1] * rms0 * g1;
                snv[r1 * 128 + ((d0     + 4 * r1) & 127)] = acc[idx][2] * rms1 * g0;
                snv[r1 * 128 + ((d0 + 1 + 4 * r1) & 127)] = acc[idx][3] * rms1 * g1;
            }
        }
    }
    __syncthreads();

    // RoPE + pack + write: warp owns 32 rows, lane owns 4 dims
    int hh = isQ ? nt : (nt - 16);
    int d0 = lane * 4;
    int sec = (d0 < 16) ? 0 : (d0 < 40) ? 1 : (d0 < 64) ? 2 : (d0 < 80) ? 0 : (d0 < 104) ? 1 : 2;
    #pragma unroll 1
    for (int rr = 0; rr < 32; rr++) {
        int row = warp * 32 + rr;
        int t = mt * 128 + row;
        int bb = t >> 10, s = t & 1023;
        size_t ci = (((size_t)sec * B_ + bb) * S_ + s) * HD_ + d0;
        float c4[4], s4[4];
        *(float4*)c4 = *(const float4*)(cosb + ci);
        *(float4*)s4 = *(const float4*)(sinb + ci);
        float outv[4];
        #pragma unroll
        for (int j = 0; j < 4; j++) {
            int d = d0 + j;
            float nv = snv[row * 128 + ((d + 4 * row) & 127)];
            float pn = snv[row * 128 + (((d ^ 64) + 4 * row) & 127)];
            float part = (d < 64) ? -pn : pn;
            outv[j] = nv * c4[j] + part * s4[j];
        }
        unsigned short h[4];
        if (isQ) {
            #pragma unroll
            for (int j = 0; j < 4; j++) h[j] = __half_as_ushort(__float2half_rn(outv[j]));
            __half* qp = Qpk + ((size_t)(bb * NH_ + hh) * S_ + s) * 128;
            *(uint2*)(qp + d0) = make_uint2(pack2(h[0], h[1]), pack2(h[2], h[3]));
        } else {
            float mval = mask[t];
            #pragma unroll
            for (int j = 0; j < 4; j++) h[j] = __half_as_ushort(__float2half_rn(outv[j] * mval));
            __half* kp = Kpk + ((size_t)(bb * NKV_ + hh) * S_ + s) * 128;
            *(uint2*)(kp + d0) = make_uint2(pack2(h[0], h[1]), pack2(h[2], h[3]));
        }
    }
}

// ---------------- tensor-core flash attention (fp16, plain Q) ----------------
// CTA = 64 q-rows (4 warps x 16), 128 threads, 2 CTAs/SM.
// smem: Q 16KB + 2 x (K 16KB + V 16KB) = 80KB.
#define ATTN_SMEM 81920

__global__ void __launch_bounds__(128, 2) attn_tc_kernel(
    const __half* __restrict__ Qpk, const __half* __restrict__ Kpk,
    const __half* __restrict__ Vpk, const float* __restrict__ eff,
    __half* __restrict__ Apk)
{
    extern __shared__ char smc[];
    uint32_t sbase = smem_u32(smc);

    int bid = blockIdx.x;
    int qt = 15 - (bid >> 5);
    int rem = bid & 31;
    int h = rem >> 1, b = rem & 1;
    int kvh = h / G_;
    int tid = threadIdx.x, warp = tid >> 5, lane = tid & 31;

    const __half* Qg = Qpk + ((size_t)(b * NH_ + h) * S_ + qt * 64) * 128;
    const __half* Kg = Kpk + ((size_t)(b * NKV_ + kvh) * S_) * 128;
    const __half* Vg = Vpk + ((size_t)(b * NKV_ + kvh) * S_) * 128;

    // ---- stage Q (64 rows x 256B) ----
    #pragma unroll
    for (int it = 0; it < 8; it++) {
        int idx = it * 128 + tid;
        int r = idx >> 4, c = idx & 15;
        cp_async16(sbase + r * 256 + csw8(c, r) * 16, Qg + (size_t)r * 128 + c * 8);
    }
    cp_commit();
    cp_wait<0>();
    __syncthreads();

    // ---- extract Q fragments ----
    uint32_t qh[8][4];
    {
        int row = warp * 16 + ((lane >> 3) & 1) * 8 + (lane & 7);
        uint32_t roff = sbase + row * 256;
        uint32_t r7 = row & 7;
        int chi = (lane >> 4) & 1;
        #pragma unroll
        for (int j = 0; j < 8; j++) {
            uint32_t ch = 2 * j + chi;
            ldsm_x4(qh[j], roff + ((ch & 8u) | ((ch ^ r7) & 7u)) * 16);
        }
    }

    int ntiles = qt + 1;
    int eff_i = (int)(eff[b] + 0.5f);

    // ---- prologue KV tiles ----
    #pragma unroll
    for (int pt = 0; pt < 2; pt++) {
        if (pt < ntiles) {
            #pragma unroll
            for (int it = 0; it < 8; it++) {
                int idx = it * 128 + tid;
                int r = idx >> 4, c = idx & 15;
                uint32_t ds = 16384u + (uint32_t)pt * 32768 + r * 256 + csw8(c, r) * 16;
                size_t go = (size_t)(pt * 64 + r) * 128 + c * 8;
                cp_async16(sbase + ds,         Kg + go);
                cp_async16(sbase + ds + 16384, Vg + go);
            }
        }
        cp_commit();
    }

    float m0 = -1e30f, m1 = -1e30f, ls0 = 0.f, ls1 = 0.f;
    float o[16][4];
    #pragma unroll
    for (int i = 0; i < 16; i++) { o[i][0] = o[i][1] = o[i][2] = o[i][3] = 0.f; }

    const float scale = 0.08838834764831845f;
    int row0 = qt * 64 + warp * 16 + (lane >> 2);
    int colb = (lane & 3) * 2;
    int krbase = ((lane >> 4) & 1) * 8 + (lane & 7);
    int kchi = (lane >> 3) & 1;
    int vrbase = ((lane >> 3) & 1) * 8 + (lane & 7);
    int vchi = (lane >> 4) & 1;

    for (int kt = 0; kt < ntiles; kt++) {
        cp_wait<1>();
        __syncthreads();
        uint32_t sk = sbase + 16384u + (uint32_t)(kt & 1) * 32768;
        uint32_t sv = sk + 16384;

        // ---- S = Q K (plain fp16 both) ----
        float s[8][4];
        #pragma unroll
        for (int i = 0; i < 8; i++) { s[i][0] = s[i][1] = s[i][2] = s[i][3] = 0.f; }

        #pragma unroll
        for (int nbp = 0; nbp < 4; nbp++) {
            int krow = nbp * 16 + krbase;
            uint32_t kroff = sk + krow * 256;
            uint32_t kr7 = krow & 7;
            #pragma unroll
            for (int j = 0; j < 8; j++) {
                uint32_t ch = 2 * j + kchi;
                uint32_t kf[4];
                ldsm_x4(kf, kroff + ((ch & 8u) | ((ch ^ kr7) & 7u)) * 16);
                mma_16816(s[2*nbp],   qh[j], kf[0], kf[1]);
                mma_16816(s[2*nbp+1], qh[j], kf[2], kf[3]);
            }
        }

        // ---- mask + online softmax ----
        float mx0 = -1e30f, mx1 = -1e30f;
        #pragma unroll
        for (int nb = 0; nb < 8; nb++) {
            int c0 = kt * 64 + nb * 8 + colb;
            #pragma unroll
            for (int e = 0; e < 2; e++) {
                int cc = c0 + e;
                float v0 = (cc <= row0     && cc < eff_i) ? s[nb][e]   * scale : -1e9f;
                float v1 = (cc <= row0 + 8 && cc < eff_i) ? s[nb][2+e] * scale : -1e9f;
                s[nb][e] = v0; s[nb][2+e] = v1;
                mx0 = fmaxf(mx0, v0); mx1 = fmaxf(mx1, v1);
            }
        }
        mx0 = fmaxf(mx0, __shfl_xor_sync(0xffffffffu, mx0, 1));
        mx0 = fmaxf(mx0, __shfl_xor_sync(0xffffffffu, mx0, 2));
        mx1 = fmaxf(mx1, __shfl_xor_sync(0xffffffffu, mx1, 1));
        mx1 = fmaxf(mx1, __shfl_xor_sync(0xffffffffu, mx1, 2));
        float m0n = fmaxf(m0, mx0), m1n = fmaxf(m1, mx1);
        float cr0 = __expf(m0 - m0n), cr1 = __expf(m1 - m1n);
        float sum0 = 0.f, sum1 = 0.f;
        #pragma unroll
        for (int nb = 0; nb < 8; nb++) {
            #pragma unroll
            for (int e = 0; e < 2; e++) {
                float p0 = __expf(s[nb][e]   - m0n);
                float p1 = __expf(s[nb][2+e] - m1n);
                s[nb][e] = p0; s[nb][2+e] = p1;
                sum0 += p0; sum1 += p1;
            }
        }
        sum0 += __shfl_xor_sync(0xffffffffu, sum0, 1);
        sum0 += __shfl_xor_sync(0xffffffffu, sum0, 2);
        sum1 += __shfl_xor_sync(0xffffffffu, sum1, 1);
        sum1 += __shfl_xor_sync(0xffffffffu, sum1, 2);
        ls0 = ls0 * cr0 + sum0; m0 = m0n;
        ls1 = ls1 * cr1 + sum1; m1 = m1n;
        #pragma unroll
        for (int i = 0; i < 16; i++) {
            o[i][0] *= cr0; o[i][1] *= cr0;
            o[i][2] *= cr1; o[i][3] *= cr1;
        }

        // ---- P -> split fp16 A-fragments (keep Pl for accuracy) ----
        uint32_t ph[4][4], pl[4][4];
        #pragma unroll
        for (int j2 = 0; j2 < 4; j2++) {
            #pragma unroll
            for (int q = 0; q < 4; q++) {
                int nb = 2 * j2 + (q >> 1);
                int e  = (q & 1) * 2;
                unsigned short ha, la, hb, lb2;
                split_h(s[nb][e],     ha, la);
                split_h(s[nb][e + 1], hb, lb2);
                int slot = (q >> 1) * 2 + (q & 1);
                ph[j2][slot] = pack2(ha, hb);
                pl[j2][slot] = pack2(la, lb2);
            }
        }

        // ---- O += (Ph + Pl) V ----
        #pragma unroll
        for (int j2 = 0; j2 < 4; j2++) {
            int vrow = j2 * 16 + vrbase;
            uint32_t vroff = sv + vrow * 256;
            uint32_t vr7 = vrow & 7;
            #pragma unroll
            for (int nbp = 0; nbp < 8; nbp++) {
                uint32_t ch = 2 * nbp + vchi;
                uint32_t vf[4];
                ldsm_x4_t(vf, vroff + ((ch & 8u) | ((ch ^ vr7) & 7u)) * 16);
                mma_16816(o[2*nbp],   ph[j2], vf[0], vf[1]);
                mma_16816(o[2*nbp+1], ph[j2], vf[2], vf[3]);
                mma_16816(o[2*nbp],   pl[j2], vf[0], vf[1]);
                mma_16816(o[2*nbp+1], pl[j2], vf[2], vf[3]);
            }
        }

        __syncthreads();
        int nxt = kt + 2;
        if (nxt < ntiles) {
            #pragma unroll
            for (int it = 0; it < 8; it++) {
                int idx = it * 128 + tid;
                int r = idx >> 4, c = idx & 15;
                uint32_t ds = 16384u + (uint32_t)(kt & 1) * 32768 + r * 256 + csw8(c, r) * 16;
                size_t go = (size_t)(nxt * 64 + r) * 128 + c * 8;
                cp_async16(sbase + ds,         Kg + go);
                cp_async16(sbase + ds + 16384, Vg + go);
            }
        }
        cp_commit();
    }

    // ---- epilogue: write split fp16 rows of Apack ----
    float inv0 = 1.0f / ls0, inv1 = 1.0f / ls1;
    int t0 = b * S_ + qt * 64 + warp * 16 + (lane >> 2);
    size_t r0b = (size_t)t0 * KPRIME;
    size_t r1b = (size_t)(t0 + 8) * KPRIME;
    #pragma unroll
    for (int db = 0; db < 16; db++) {
        int c = h * 128 + db * 8 + colb;
        unsigned short h0, l0, h1, l1;
        split_h(o[db][0] * inv0, h0, l0);
        split_h(o[db][1] * inv0, h1, l1);
        *(uint32_t*)(Apk + r0b + c)        = pack2(h0, h1);
        *(uint32_t*)(Apk + r0b + 2048 + c) = pack2(l0, l1);
        split_h(o[db][2] * inv1, h0, l0);
        split_h(o[db][3] * inv1, h1, l1);
        *(uint32_t*)(Apk + r1b + c)        = pack2(h0, h1);
        *(uint32_t*)(Apk + r1b + 2048 + c) = pack2(l0, l1);
    }
}

// ---------------- launcher ----------------
extern "C" void kernel_launch(void* const* d_in, const int* in_sizes, int n_in,
                              void* d_out, int out_size)
{
    const float* x       = (const float*)d_in[0];
    const float* cosb    = (const float*)d_in[1];
    const float* sinb    = (const float*)d_in[2];
    const float* mask    = (const float*)d_in[3];
    const float* q_w     = (const float*)d_in[4];
    const float* q_b     = (const float*)d_in[5];
    const float* k_w     = (const float*)d_in[6];
    const float* k_b     = (const float*)d_in[7];
    const float* v_w     = (const float*)d_in[8];
    const float* v_b     = (const float*)d_in[9];
    const float* q_gamma = (const float*)d_in[10];
    const float* k_gamma = (const float*)d_in[11];
    const float* o_w     = (const float*)d_in[12];
    float* out = (float*)d_out;

    float* scratch = nullptr;
    cudaGetSymbolAddress((void**)&scratch, g_scratch);
    float* geff = scratch + OFF_EFF;
    float* bias = scratch + OFF_BIAS;
    __half* Apack = (__half*)(scratch + OFF_APK);
    __half* Bqkv  = (__half*)(scratch + OFF_BQKV);
    __half* Bow   = (__half*)(scratch + OFF_BOW);
    __half* Qpk   = (__half*)(scratch + OFF_QPK);
    __half* Kpk   = (__half*)(scratch + OFF_KPK);
    __half* Vpk   = (__half*)(scratch + OFF_VPK);

    cudaFuncSetAttribute(gemm_mma_kernel, cudaFuncAttributeMaxDynamicSharedMemorySize, GEMM_SMEM);
    cudaFuncSetAttribute(gemm_qkv_fused,  cudaFuncAttributeMaxDynamicSharedMemorySize, GEMM_SMEM);
    cudaFuncSetAttribute(attn_tc_kernel,  cudaFuncAttributeMaxDynamicSharedMemorySize, ATTN_SMEM);

    // launch order chosen so ncu (-s 5 -c 1) captures the O-proj GEMM (index 5)
    prep_kernel<<<12, 256>>>(mask, q_b, k_b, v_b, geff, bias);                      // 0
    convA_kernel<<<2048, 256>>>(x, Apack);                                          // 1
    convB_all<<<dim3(144, 64), 256>>>(q_w, k_w, v_w, o_w, Bqkv, Bow);               // 2
    gemm_qkv_fused<<<dim3(NQKV / 128, 16), 128, GEMM_SMEM>>>(                        // 3
        Apack, Bqkv, bias, cosb, sinb, mask, q_gamma, k_gamma, Qpk, Kpk, Vpk);
    attn_tc_kernel<<<512, 128, ATTN_SMEM>>>(Qpk, Kpk, Vpk, geff, Apack);            // 4
    gemm_mma_kernel<<<dim3(16, 16), 128, GEMM_SMEM>>>(Apack, Bow, out, 2048);       // 5
}

// round 9
// speedup vs baseline: 1.3474x; 1.3474x over previous
#include <cuda_runtime.h>
#include <cuda_fp16.h>
#include <math.h>
#include <stdint.h>

#define B_   2
#define S_   1024
#define HID_ 2048
#define NH_  16
#define NKV_ 2
#define HD_  128
#define G_   (NH_/NKV_)
#define TOK  (B_*S_)

#define KPRIME 4096        // fp16 2-term split on A side: [Ah | Al]; B indexed k&2047
#define NQKV   2560

// ---------------- scratch (float offsets, 16B-aligned) ----------------
#define OFF_EFF  0              // 2 (+2 pad)
#define OFF_BIAS 4              // 2560
#define OFF_APK  2564           // 2048*4096 fp16 = 4194304 floats
#define OFF_BQKV 4196868        // 2560*2048 fp16 = 2621440 floats
#define OFF_BOW  6818308        // 2048*2048 fp16 = 2097152 floats
#define OFF_QPK  8915460        // 32768*128 fp16 = 2097152 floats (plain fp16 Q)
#define OFF_KPK  11012612       // 4096*128 fp16  = 262144 floats
#define OFF_VPK  11274756       // 262144 floats
#define SCRATCH_F 11536900
__device__ __align__(256) float g_scratch[SCRATCH_F];

// ---------------- helpers ----------------
__device__ __forceinline__ uint32_t smem_u32(const void* p) {
    uint32_t a;
    asm("{ .reg .u64 t; cvta.to.shared.u64 t, %1; cvt.u32.u64 %0, t; }" : "=r"(a) : "l"(p));
    return a;
}
__device__ __forceinline__ void split_h(float f, unsigned short& h, unsigned short& l) {
    __half hh = __float2half_rn(f);
    float r = f - __half2float(hh);
    __half ll = __float2half_rn(r);
    h = __half_as_ushort(hh);
    l = __half_as_ushort(ll);
}
__device__ __forceinline__ uint32_t pack2(unsigned short a, unsigned short b) {
    return (uint32_t)a | ((uint32_t)b << 16);
}
__device__ __forceinline__ void cp_async16(uint32_t saddr, const void* gaddr) {
    asm volatile("cp.async.cg.shared.global [%0], [%1], 16;" :: "r"(saddr), "l"(gaddr));
}
__device__ __forceinline__ void cp_commit() {
    asm volatile("cp.async.commit_group;");
}
template <int N>
__device__ __forceinline__ void cp_wait() {
    asm volatile("cp.async.wait_group %0;" :: "n"(N));
}
__device__ __forceinline__ void ldsm_x4(uint32_t* f, uint32_t addr) {
    asm volatile("ldmatrix.sync.aligned.m8n8.x4.shared.b16 {%0,%1,%2,%3}, [%4];"
                 : "=r"(f[0]), "=r"(f[1]), "=r"(f[2]), "=r"(f[3]) : "r"(addr));
}
__device__ __forceinline__ void ldsm_x4_t(uint32_t* f, uint32_t addr) {
    asm volatile("ldmatrix.sync.aligned.m8n8.x4.trans.shared.b16 {%0,%1,%2,%3}, [%4];"
                 : "=r"(f[0]), "=r"(f[1]), "=r"(f[2]), "=r"(f[3]) : "r"(addr));
}
__device__ __forceinline__ void mma_16816(float* c, const uint32_t* a, uint32_t b0, uint32_t b1) {
    asm volatile(
        "mma.sync.aligned.m16n8k16.row.col.f32.f16.f16.f32 "
        "{%0,%1,%2,%3}, {%4,%5,%6,%7}, {%8,%9}, {%0,%1,%2,%3};"
        : "+f"(c[0]), "+f"(c[1]), "+f"(c[2]), "+f"(c[3])
        : "r"(a[0]), "r"(a[1]), "r"(a[2]), "r"(a[3]), "r"(b0), "r"(b1));
}
__device__ __forceinline__ uint32_t csw8(uint32_t c, uint32_t row) {  // 256B rows (16 chunks)
    return (c & 0x8u) | ((c ^ (row & 7u)) & 0x7u);
}

// ---------------- prep: eff + bias concat ----------------
__global__ void prep_kernel(const float* __restrict__ mask,
                            const float* __restrict__ qb, const float* __restrict__ kb,
                            const float* __restrict__ vb,
                            float* __restrict__ eff, float* __restrict__ bias) {
    int bx = blockIdx.x;
    if (bx < 2) {
        float s = 0.f;
        for (int i = threadIdx.x; i < S_; i += blockDim.x) s += mask[bx * S_ + i];
        #pragma unroll
        for (int off = 16; off; off >>= 1) s += __shfl_xor_sync(0xffffffffu, s, off);
        __shared__ float red[8];
        if ((threadIdx.x & 31) == 0) red[threadIdx.x >> 5] = s;
        __syncthreads();
        if (threadIdx.x == 0) {
            float t = 0.f;
            for (int i = 0; i < 8; i++) t += red[i];
            eff[bx] = t;
        }
    } else {
        int i = (bx - 2) * 256 + threadIdx.x;
        if (i < 2048) bias[i] = qb[i];
        else if (i < 2304) bias[i] = kb[i - 2048];
        else if (i < 2560) bias[i] = vb[i - 2304];
    }
}

// ---------------- pack activations X[2048x2048] f32 -> [Xh | Xl] fp16 rows of 4096 ----------------
__global__ void __launch_bounds__(256) convA_kernel(const float* __restrict__ X,
                                                    __half* __restrict__ Ap) {
    int g = blockIdx.x * 256 + threadIdx.x;
    int m = g >> 8;
    int kg = (g & 255) << 3;
    const float* xp = X + ((size_t)m << 11) + kg;
    float f[8];
    *(float4*)f       = *(const float4*)xp;
    *(float4*)(f + 4) = *(const float4*)(xp + 4);
    unsigned short h[8], l[8];
    #pragma unroll
    for (int i = 0; i < 8; i++) split_h(f[i], h[i], l[i]);
    uint4 Hi = make_uint4(pack2(h[0],h[1]), pack2(h[2],h[3]), pack2(h[4],h[5]), pack2(h[6],h[7]));
    uint4 Lo = make_uint4(pack2(l[0],l[1]), pack2(l[2],l[3]), pack2(l[4],l[5]), pack2(l[6],l[7]));
    __half* base = Ap + (size_t)m * KPRIME;
    *(uint4*)(base + kg)        = Hi;
    *(uint4*)(base + 2048 + kg) = Lo;
}

// ---------------- all weight packs in one launch ----------------
__global__ void __launch_bounds__(256) convB_all(
    const float* __restrict__ qw, const float* __restrict__ kw,
    const float* __restrict__ vw, const float* __restrict__ ow,
    __half* __restrict__ Bqkv, __half* __restrict__ Bow)
{
    __shared__ float s[32][33];
    int bx = blockIdx.x;
    const float* W; __half* Bp; int N, noff, nx;
    if (bx < 64)      { W = qw; Bp = Bqkv; N = 2048; noff = 0;    nx = bx; }
    else if (bx < 72) { W = kw; Bp = Bqkv; N = 256;  noff = 2048; nx = bx - 64; }
    else if (bx < 80) { W = vw; Bp = Bqkv; N = 256;  noff = 2304; nx = bx - 72; }
    else              { W = ow; Bp = Bow;  N = 2048; noff = 0;    nx = bx - 80; }
    int n0 = nx << 5, k0 = blockIdx.y << 5;
    int tid = threadIdx.x;
    #pragma unroll
    for (int p = 0; p < 4; p++) {
        int e = tid + p * 256;
        int ki = e >> 5, ni = e & 31;
        s[ki][ni] = W[(size_t)(k0 + ki) * N + n0 + ni];
    }
    __syncthreads();
    if (tid < 128) {
        int ni = tid >> 2, kg = (tid & 3) << 3;
        unsigned short h[8];
        #pragma unroll
        for (int j = 0; j < 8; j++) h[j] = __half_as_ushort(__float2half_rn(s[kg + j][ni]));
        uint4 Hi = make_uint4(pack2(h[0],h[1]), pack2(h[2],h[3]), pack2(h[4],h[5]), pack2(h[6],h[7]));
        *(uint4*)(Bp + (size_t)(noff + n0 + ni) * 2048 + k0 + kg) = Hi;
    }
}

// ---------------- HMMA GEMM (R7 shape): 128x128 CTA, 8 warps (64x32 tile), BK=32, 4-stage ----------------
#define BKC 32
#define STAGE_B 16384
#define GEMM_SMEM 65536
#define KITERS (KPRIME / BKC)   // 128

__device__ __forceinline__ void stage_load(uint32_t sbase, int stage,
                                           const __half* Ag, const __half* Bg,
                                           int k0, int lrow, int lchunk) {
    uint32_t sa = sbase + stage * STAGE_B;
    int kb = k0 & 2047;
    #pragma unroll
    for (int i = 0; i < 2; i++) {
        int row = lrow + i * 64;
        uint32_t sw = (uint32_t)((lchunk ^ ((row >> 1) & 3)) << 4);
        cp_async16(sa + row * 64 + sw,        Ag + (size_t)row * KPRIME + k0 + lchunk * 8);
        cp_async16(sa + 8192 + row * 64 + sw, Bg + (size_t)row * 2048   + kb + lchunk * 8);
    }
}

#define GEMM_PREAMBLE()                                                               \
    extern __shared__ char smc[];                                                     \
    uint32_t sbase = smem_u32(smc);                                                   \
    const int tid = threadIdx.x;                                                      \
    const int mt = blockIdx.y, nt = blockIdx.x;                                       \
    const int warp = tid >> 5, lane = tid & 31;                                       \
    const int wm = warp >> 2, wn = warp & 3;                                          \
    const int lrow = tid >> 2;                                                        \
    const int lchunk = tid & 3;                                                       \
    const int arow = wm * 64 + ((lane >> 3) & 1) * 8 + (lane & 7);                    \
    const int achi = (lane >> 4) & 1;                                                 \
    const uint32_t asw = (uint32_t)((arow >> 1) & 3);                                 \
    const uint32_t abase = (uint32_t)(arow * 64);                                     \
    const int brow = wn * 32 + ((lane >> 4) & 1) * 8 + (lane & 7);                    \
    const int bclo = (lane >> 3) & 1;                                                 \
    const uint32_t bsw = (uint32_t)((brow >> 1) & 3);                                 \
    const uint32_t bbase = (uint32_t)(brow * 64);                                     \
    float acc[16][4];                                                                 \
    _Pragma("unroll")                                                                 \
    for (int i = 0; i < 16; i++) { acc[i][0]=0.f; acc[i][1]=0.f; acc[i][2]=0.f; acc[i][3]=0.f; }

#define GEMM_MAINLOOP()                                                               \
    {                                                                                 \
        _Pragma("unroll")                                                             \
        for (int s = 0; s < 3; s++) { stage_load(sbase, s, Ag, Bg, s * BKC, lrow, lchunk); cp_commit(); } \
        for (int kt = 0; kt < KITERS; kt++) {                                         \
            cp_wait<2>();                                                             \
            __syncthreads();                                                          \
            int nxt = kt + 3;                                                         \
            if (nxt < KITERS) stage_load(sbase, nxt & 3, Ag, Bg, nxt * BKC, lrow, lchunk); \
            cp_commit();                                                              \
            uint32_t sa = sbase + (kt & 3) * STAGE_B;                                 \
            uint32_t sb = sa + 8192;                                                  \
            _Pragma("unroll")                                                         \
            for (int ks = 0; ks < 2; ks++) {                                          \
                uint32_t af[4][4];                                                    \
                _Pragma("unroll")                                                     \
                for (int m = 0; m < 4; m++)                                           \
                    ldsm_x4(af[m], sa + abase + m * 1024 + ((((uint32_t)(ks * 2 + achi)) ^ asw) << 4)); \
                uint32_t bf0[4], bf1[4];                                              \
                ldsm_x4(bf0, sb + bbase +        ((((uint32_t)(ks * 2 + bclo)) ^ bsw) << 4)); \
                ldsm_x4(bf1, sb + bbase + 1024 + ((((uint32_t)(ks * 2 + bclo)) ^ bsw) << 4)); \
                _Pragma("unroll")                                                     \
                for (int m = 0; m < 4; m++) {                                         \
                    mma_16816(acc[m * 4 + 0], af[m], bf0[0], bf0[1]);                 \
                    mma_16816(acc[m * 4 + 1], af[m], bf0[2], bf0[3]);                 \
                    mma_16816(acc[m * 4 + 2], af[m], bf1[0], bf1[1]);                 \
                    mma_16816(acc[m * 4 + 3], af[m], bf1[2], bf1[3]);                 \
                }                                                                     \
            }                                                                         \
        }                                                                             \
    }

// ---------------- generic GEMM (O-projection): f32 output ----------------
__global__ void __launch_bounds__(256, 2) gemm_mma_kernel(
    const __half* __restrict__ A, const __half* __restrict__ Bm,
    float* __restrict__ C, int Ntot)
{
    GEMM_PREAMBLE();
    const __half* Ag = A  + (size_t)(mt * 128) * KPRIME;
    const __half* Bg = Bm + (size_t)(nt * 128) * 2048;
    GEMM_MAINLOOP();

    #pragma unroll
    for (int n = 0; n < 4; n++) {
        int col = nt * 128 + wn * 32 + n * 8 + (lane & 3) * 2;
        #pragma unroll
        for (int m = 0; m < 4; m++) {
            int row = mt * 128 + wm * 64 + m * 16 + (lane >> 2);
            *(float2*)(C + (size_t)row * Ntot + col)       = make_float2(acc[m*4+n][0], acc[m*4+n][1]);
            *(float2*)(C + (size_t)(row + 8) * Ntot + col) = make_float2(acc[m*4+n][2], acc[m*4+n][3]);
        }
    }
}

// ---------------- fused QKV GEMM: bias + RMSNorm + RoPE + mask + pack ----------------
__global__ void __launch_bounds__(256, 2) gemm_qkv_fused(
    const __half* __restrict__ A, const __half* __restrict__ Bm,
    const float* __restrict__ bias,
    const float* __restrict__ cosb, const float* __restrict__ sinb,
    const float* __restrict__ mask,
    const float* __restrict__ q_gamma, const float* __restrict__ k_gamma,
    __half* __restrict__ Qpk, __half* __restrict__ Kpk, __half* __restrict__ Vpk)
{
    __shared__ float ssq[4][128];
    GEMM_PREAMBLE();
    const __half* Ag = A  + (size_t)(mt * 128) * KPRIME;
    const __half* Bg = Bm + (size_t)(nt * 128) * 2048;
    GEMM_MAINLOOP();

    cp_wait<0>();
    __syncthreads();   // pipeline smem reusable

    // bias add
    #pragma unroll
    for (int n = 0; n < 4; n++) {
        int col = wn * 32 + n * 8 + (lane & 3) * 2;
        float b0 = bias[nt * 128 + col];
        float b1 = bias[nt * 128 + col + 1];
        #pragma unroll
        for (int m = 0; m < 4; m++) {
            acc[m*4+n][0] += b0; acc[m*4+n][1] += b1;
            acc[m*4+n][2] += b0; acc[m*4+n][3] += b1;
        }
    }

    if (nt >= 18) {
        // ---- V: mask-mul, plain fp16 ----
        int kh = nt - 18;
        #pragma unroll
        for (int m = 0; m < 4; m++) {
            int t0 = mt * 128 + wm * 64 + m * 16 + (lane >> 2);
            int b0g = t0 >> 10, s0g = t0 & 1023;
            float mv0 = mask[t0], mv1 = mask[t0 + 8];
            __half* vp0 = Vpk + ((size_t)(b0g * NKV_ + kh) * S_ + s0g) * 128;
            __half* vp1 = vp0 + 8 * 128;
            #pragma unroll
            for (int n = 0; n < 4; n++) {
                int col = wn * 32 + n * 8 + (lane & 3) * 2;
                *(__half2*)(vp0 + col) = __floats2half2_rn(acc[m*4+n][0] * mv0, acc[m*4+n][1] * mv0);
                *(__half2*)(vp1 + col) = __floats2half2_rn(acc[m*4+n][2] * mv1, acc[m*4+n][3] * mv1);
            }
        }
        return;
    }

    // ---- Q or K: RMSNorm over 128 head dims ----
    const bool isQ = (nt < 16);
    const float* gamma = isQ ? q_gamma : k_gamma;
    float* snv = (float*)smc;   // 128 x 128 f32, col rotated by 4*row

    #pragma unroll
    for (int m = 0; m < 4; m++) {
        float a0 = 0.f, a1 = 0.f;
        #pragma unroll
        for (int n = 0; n < 4; n++) {
            a0 += acc[m*4+n][0]*acc[m*4+n][0] + acc[m*4+n][1]*acc[m*4+n][1];
            a1 += acc[m*4+n][2]*acc[m*4+n][2] + acc[m*4+n][3]*acc[m*4+n][3];
        }
        a0 += __shfl_xor_sync(0xffffffffu, a0, 1);
        a0 += __shfl_xor_sync(0xffffffffu, a0, 2);
        a1 += __shfl_xor_sync(0xffffffffu, a1, 1);
        a1 += __shfl_xor_sync(0xffffffffu, a1, 2);
        if ((lane & 3) == 0) {
            int r0 = wm * 64 + m * 16 + (lane >> 2);
            ssq[wn][r0]     = a0;
            ssq[wn][r0 + 8] = a1;
        }
    }
    __syncthreads();

    #pragma unroll
    for (int m = 0; m < 4; m++) {
        int r0 = wm * 64 + m * 16 + (lane >> 2);
        int r1 = r0 + 8;
        float tot0 = ssq[0][r0] + ssq[1][r0] + ssq[2][r0] + ssq[3][r0];
        float tot1 = ssq[0][r1] + ssq[1][r1] + ssq[2][r1] + ssq[3][r1];
        float rms0 = rsqrtf(tot0 * (1.0f / HD_) + 1e-6f);
        float rms1 = rsqrtf(tot1 * (1.0f / HD_) + 1e-6f);
        #pragma unroll
        for (int n = 0; n < 4; n++) {
            int d0 = wn * 32 + n * 8 + (lane & 3) * 2;
            float g0 = gamma[d0], g1 = gamma[d0 + 1];
            snv[r0 * 128 + ((d0     + 4 * r0) & 127)] = acc[m*4+n][0] * rms0 * g0;
            snv[r0 * 128 + ((d0 + 1 + 4 * r0) & 127)] = acc[m*4+n][1] * rms0 * g1;
            snv[r1 * 128 + ((d0     + 4 * r1) & 127)] = acc[m*4+n][2] * rms1 * g0;
            snv[r1 * 128 + ((d0 + 1 + 4 * r1) & 127)] = acc[m*4+n][3] * rms1 * g1;
        }
    }
    __syncthreads();

    // RoPE + pack + write: warp owns 16 rows, lane owns 4 dims
    int hh = isQ ? nt : (nt - 16);
    int d0 = lane * 4;
    int sec = (d0 < 16) ? 0 : (d0 < 40) ? 1 : (d0 < 64) ? 2 : (d0 < 80) ? 0 : (d0 < 104) ? 1 : 2;
    #pragma unroll 1
    for (int rr = 0; rr < 16; rr++) {
        int row = warp * 16 + rr;
        int t = mt * 128 + row;
        int bb = t >> 10, s = t & 1023;
        size_t ci = (((size_t)sec * B_ + bb) * S_ + s) * HD_ + d0;
        float c4[4], s4[4];
        *(float4*)c4 = *(const float4*)(cosb + ci);
        *(float4*)s4 = *(const float4*)(sinb + ci);
        float outv[4];
        #pragma unroll
        for (int j = 0; j < 4; j++) {
            int d = d0 + j;
            float nv = snv[row * 128 + ((d + 4 * row) & 127)];
            float pn = snv[row * 128 + (((d ^ 64) + 4 * row) & 127)];
            float part = (d < 64) ? -pn : pn;
            outv[j] = nv * c4[j] + part * s4[j];
        }
        unsigned short h[4];
        if (isQ) {
            #pragma unroll
            for (int j = 0; j < 4; j++) h[j] = __half_as_ushort(__float2half_rn(outv[j]));
            __half* qp = Qpk + ((size_t)(bb * NH_ + hh) * S_ + s) * 128;
            *(uint2*)(qp + d0) = make_uint2(pack2(h[0], h[1]), pack2(h[2], h[3]));
        } else {
            float mval = mask[t];
            #pragma unroll
            for (int j = 0; j < 4; j++) h[j] = __half_as_ushort(__float2half_rn(outv[j] * mval));
            __half* kp = Kpk + ((size_t)(bb * NKV_ + hh) * S_ + s) * 128;
            *(uint2*)(kp + d0) = make_uint2(pack2(h[0], h[1]), pack2(h[2], h[3]));
        }
    }
}

// ---------------- tensor-core flash attention (fp16, plain Q) ----------------
#define ATTN_SMEM 81920

__global__ void __launch_bounds__(128, 2) attn_tc_kernel(
    const __half* __restrict__ Qpk, const __half* __restrict__ Kpk,
    const __half* __restrict__ Vpk, const float* __restrict__ eff,
    __half* __restrict__ Apk)
{
    extern __shared__ char smc[];
    uint32_t sbase = smem_u32(smc);

    int bid = blockIdx.x;
    int qt = 15 - (bid >> 5);
    int rem = bid & 31;
    int h = rem >> 1, b = rem & 1;
    int kvh = h / G_;
    int tid = threadIdx.x, warp = tid >> 5, lane = tid & 31;

    const __half* Qg = Qpk + ((size_t)(b * NH_ + h) * S_ + qt * 64) * 128;
    const __half* Kg = Kpk + ((size_t)(b * NKV_ + kvh) * S_) * 128;
    const __half* Vg = Vpk + ((size_t)(b * NKV_ + kvh) * S_) * 128;

    #pragma unroll
    for (int it = 0; it < 8; it++) {
        int idx = it * 128 + tid;
        int r = idx >> 4, c = idx & 15;
        cp_async16(sbase + r * 256 + csw8(c, r) * 16, Qg + (size_t)r * 128 + c * 8);
    }
    cp_commit();
    cp_wait<0>();
    __syncthreads();

    uint32_t qh[8][4];
    {
        int row = warp * 16 + ((lane >> 3) & 1) * 8 + (lane & 7);
        uint32_t roff = sbase + row * 256;
        uint32_t r7 = row & 7;
        int chi = (lane >> 4) & 1;
        #pragma unroll
        for (int j = 0; j < 8; j++) {
            uint32_t ch = 2 * j + chi;
            ldsm_x4(qh[j], roff + ((ch & 8u) | ((ch ^ r7) & 7u)) * 16);
        }
    }

    int ntiles = qt + 1;
    int eff_i = (int)(eff[b] + 0.5f);

    #pragma unroll
    for (int pt = 0; pt < 2; pt++) {
        if (pt < ntiles) {
            #pragma unroll
            for (int it = 0; it < 8; it++) {
                int idx = it * 128 + tid;
                int r = idx >> 4, c = idx & 15;
                uint32_t ds = 16384u + (uint32_t)pt * 32768 + r * 256 + csw8(c, r) * 16;
                size_t go = (size_t)(pt * 64 + r) * 128 + c * 8;
                cp_async16(sbase + ds,         Kg + go);
                cp_async16(sbase + ds + 16384, Vg + go);
            }
        }
        cp_commit();
    }

    float m0 = -1e30f, m1 = -1e30f, ls0 = 0.f, ls1 = 0.f;
    float o[16][4];
    #pragma unroll
    for (int i = 0; i < 16; i++) { o[i][0] = o[i][1] = o[i][2] = o[i][3] = 0.f; }

    const float scale = 0.08838834764831845f;
    int row0 = qt * 64 + warp * 16 + (lane >> 2);
    int colb = (lane & 3) * 2;
    int krbase = ((lane >> 4) & 1) * 8 + (lane & 7);
    int kchi = (lane >> 3) & 1;
    int vrbase = ((lane >> 3) & 1) * 8 + (lane & 7);
    int vchi = (lane >> 4) & 1;

    for (int kt = 0; kt < ntiles; kt++) {
        cp_wait<1>();
        __syncthreads();
        uint32_t sk = sbase + 16384u + (uint32_t)(kt & 1) * 32768;
        uint32_t sv = sk + 16384;

        float s[8][4];
        #pragma unroll
        for (int i = 0; i < 8; i++) { s[i][0] = s[i][1] = s[i][2] = s[i][3] = 0.f; }

        #pragma unroll
        for (int nbp = 0; nbp < 4; nbp++) {
            int krow = nbp * 16 + krbase;
            uint32_t kroff = sk + krow * 256;
            uint32_t kr7 = krow & 7;
            #pragma unroll
            for (int j = 0; j < 8; j++) {
                uint32_t ch = 2 * j + kchi;
                uint32_t kf[4];
                ldsm_x4(kf, kroff + ((ch & 8u) | ((ch ^ kr7) & 7u)) * 16);
                mma_16816(s[2*nbp],   qh[j], kf[0], kf[1]);
                mma_16816(s[2*nbp+1], qh[j], kf[2], kf[3]);
            }
        }

        float mx0 = -1e30f, mx1 = -1e30f;
        #pragma unroll
        for (int nb = 0; nb < 8; nb++) {
            int c0 = kt * 64 + nb * 8 + colb;
            #pragma unroll
            for (int e = 0; e < 2; e++) {
                int cc = c0 + e;
                float v0 = (cc <= row0     && cc < eff_i) ? s[nb][e]   * scale : -1e9f;
                float v1 = (cc <= row0 + 8 && cc < eff_i) ? s[nb][2+e] * scale : -1e9f;
                s[nb][e] = v0; s[nb][2+e] = v1;
                mx0 = fmaxf(mx0, v0); mx1 = fmaxf(mx1, v1);
            }
        }
        mx0 = fmaxf(mx0, __shfl_xor_sync(0xffffffffu, mx0, 1));
        mx0 = fmaxf(mx0, __shfl_xor_sync(0xffffffffu, mx0, 2));
        mx1 = fmaxf(mx1, __shfl_xor_sync(0xffffffffu, mx1, 1));
        mx1 = fmaxf(mx1, __shfl_xor_sync(0xffffffffu, mx1, 2));
        float m0n = fmaxf(m0, mx0), m1n = fmaxf(m1, mx1);
        float cr0 = __expf(m0 - m0n), cr1 = __expf(m1 - m1n);
        float sum0 = 0.f, sum1 = 0.f;
        #pragma unroll
        for (int nb = 0; nb < 8; nb++) {
            #pragma unroll
            for (int e = 0; e < 2; e++) {
                float p0 = __expf(s[nb][e]   - m0n);
                float p1 = __expf(s[nb][2+e] - m1n);
                s[nb][e] = p0; s[nb][2+e] = p1;
                sum0 += p0; sum1 += p1;
            }
        }
        sum0 += __shfl_xor_sync(0xffffffffu, sum0, 1);
        sum0 += __shfl_xor_sync(0xffffffffu, sum0, 2);
        sum1 += __shfl_xor_sync(0xffffffffu, sum1, 1);
        sum1 += __shfl_xor_sync(0xffffffffu, sum1, 2);
        ls0 = ls0 * cr0 + sum0; m0 = m0n;
        ls1 = ls1 * cr1 + sum1; m1 = m1n;
        #pragma unroll
        for (int i = 0; i < 16; i++) {
            o[i][0] *= cr0; o[i][1] *= cr0;
            o[i][2] *= cr1; o[i][3] *= cr1;
        }

        uint32_t ph[4][4], pl[4][4];
        #pragma unroll
        for (int j2 = 0; j2 < 4; j2++) {
            #pragma unroll
            for (int q = 0; q < 4; q++) {
                int nb = 2 * j2 + (q >> 1);
                int e  = (q & 1) * 2;
                unsigned short ha, la, hb, lb2;
                split_h(s[nb][e],     ha, la);
                split_h(s[nb][e + 1], hb, lb2);
                int slot = (q >> 1) * 2 + (q & 1);
                ph[j2][slot] = pack2(ha, hb);
                pl[j2][slot] = pack2(la, lb2);
            }
        }

        #pragma unroll
        for (int j2 = 0; j2 < 4; j2++) {
            int vrow = j2 * 16 + vrbase;
            uint32_t vroff = sv + vrow * 256;
            uint32_t vr7 = vrow & 7;
            #pragma unroll
            for (int nbp = 0; nbp < 8; nbp++) {
                uint32_t ch = 2 * nbp + vchi;
                uint32_t vf[4];
                ldsm_x4_t(vf, vroff + ((ch & 8u) | ((ch ^ vr7) & 7u)) * 16);
                mma_16816(o[2*nbp],   ph[j2], vf[0], vf[1]);
                mma_16816(o[2*nbp+1], ph[j2], vf[2], vf[3]);
                mma_16816(o[2*nbp],   pl[j2], vf[0], vf[1]);
                mma_16816(o[2*nbp+1], pl[j2], vf[2], vf[3]);
            }
        }

        __syncthreads();
        int nxt = kt + 2;
        if (nxt < ntiles) {
            #pragma unroll
            for (int it = 0; it < 8; it++) {
                int idx = it * 128 + tid;
                int r = idx >> 4, c = idx & 15;
                uint32_t ds = 16384u + (uint32_t)(kt & 1) * 32768 + r * 256 + csw8(c, r) * 16;
                size_t go = (size_t)(nxt * 64 + r) * 128 + c * 8;
                cp_async16(sbase + ds,         Kg + go);
                cp_async16(sbase + ds + 16384, Vg + go);
            }
        }
        cp_commit();
    }

    float inv0 = 1.0f / ls0, inv1 = 1.0f / ls1;
    int t0 = b * S_ + qt * 64 + warp * 16 + (lane >> 2);
    size_t r0b = (size_t)t0 * KPRIME;
    size_t r1b = (size_t)(t0 + 8) * KPRIME;
    #pragma unroll
    for (int db = 0; db < 16; db++) {
        int c = h * 128 + db * 8 + colb;
        unsigned short h0, l0, h1, l1;
        split_h(o[db][0] * inv0, h0, l0);
        split_h(o[db][1] * inv0, h1, l1);
        *(uint32_t*)(Apk + r0b + c)        = pack2(h0, h1);
        *(uint32_t*)(Apk + r0b + 2048 + c) = pack2(l0, l1);
        split_h(o[db][2] * inv1, h0, l0);
        split_h(o[db][3] * inv1, h1, l1);
        *(uint32_t*)(Apk + r1b + c)        = pack2(h0, h1);
        *(uint32_t*)(Apk + r1b + 2048 + c) = pack2(l0, l1);
    }
}

// ---------------- launcher ----------------
extern "C" void kernel_launch(void* const* d_in, const int* in_sizes, int n_in,
                              void* d_out, int out_size)
{
    const float* x       = (const float*)d_in[0];
    const float* cosb    = (const float*)d_in[1];
    const float* sinb    = (const float*)d_in[2];
    const float* mask    = (const float*)d_in[3];
    const float* q_w     = (const float*)d_in[4];
    const float* q_b     = (const float*)d_in[5];
    const float* k_w     = (const float*)d_in[6];
    const float* k_b     = (const float*)d_in[7];
    const float* v_w     = (const float*)d_in[8];
    const float* v_b     = (const float*)d_in[9];
    const float* q_gamma = (const float*)d_in[10];
    const float* k_gamma = (const float*)d_in[11];
    const float* o_w     = (const float*)d_in[12];
    float* out = (float*)d_out;

    float* scratch = nullptr;
    cudaGetSymbolAddress((void**)&scratch, g_scratch);
    float* geff = scratch + OFF_EFF;
    float* bias = scratch + OFF_BIAS;
    __half* Apack = (__half*)(scratch + OFF_APK);
    __half* Bqkv  = (__half*)(scratch + OFF_BQKV);
    __half* Bow   = (__half*)(scratch + OFF_BOW);
    __half* Qpk   = (__half*)(scratch + OFF_QPK);
    __half* Kpk   = (__half*)(scratch + OFF_KPK);
    __half* Vpk   = (__half*)(scratch + OFF_VPK);

    cudaFuncSetAttribute(gemm_mma_kernel, cudaFuncAttributeMaxDynamicSharedMemorySize, GEMM_SMEM);
    cudaFuncSetAttribute(gemm_qkv_fused,  cudaFuncAttributeMaxDynamicSharedMemorySize, GEMM_SMEM);
    cudaFuncSetAttribute(attn_tc_kernel,  cudaFuncAttributeMaxDynamicSharedMemorySize, ATTN_SMEM);

    // launch order: ncu (-s 5 -c 1) captures index 5 = O-proj GEMM
    prep_kernel<<<12, 256>>>(mask, q_b, k_b, v_b, geff, bias);                      // 0
    convA_kernel<<<2048, 256>>>(x, Apack);                                          // 1
    convB_all<<<dim3(144, 64), 256>>>(q_w, k_w, v_w, o_w, Bqkv, Bow);               // 2
    gemm_qkv_fused<<<dim3(NQKV / 128, 16), 256, GEMM_SMEM>>>(                        // 3
        Apack, Bqkv, bias, cosb, sinb, mask, q_gamma, k_gamma, Qpk, Kpk, Vpk);
    attn_tc_kernel<<<512, 128, ATTN_SMEM>>>(Qpk, Kpk, Vpk, geff, Apack);            // 4
    gemm_mma_kernel<<<dim3(16, 16), 256, GEMM_SMEM>>>(Apack, Bow, out, 2048);       // 5
}

// round 10
// speedup vs baseline: 2.2167x; 1.6451x over previous
#include <cuda_runtime.h>
#include <cuda_fp16.h>
#include <math.h>
#include <stdint.h>

#define B_   2
#define S_   1024
#define HID_ 2048
#define NH_  16
#define NKV_ 2
#define HD_  128
#define G_   (NH_/NKV_)
#define TOK  (B_*S_)

#define KP   2048          // plain fp16 A; B fp16. One K pass.
#define NQKV 2560

// ---------------- scratch (float offsets, 16B-aligned) ----------------
#define OFF_EFF  0              // 2 (+2 pad)
#define OFF_BIAS 4              // 2560
#define OFF_APK  2564           // 2048*2048 fp16 = 2097152 floats
#define OFF_BQKV 2099716        // 2560*2048 fp16 = 2621440 floats
#define OFF_BOW  4721156        // 2048*2048 fp16 = 2097152 floats
#define OFF_QPK  6818308        // 2*16*1024*128 fp16 = 2097152 floats
#define OFF_KPK  8915460        // 2*2*1024*128 fp16  = 262144 floats
#define OFF_VPK  9177604        // 262144 floats
#define SCRATCH_F 9439748
__device__ __align__(256) float g_scratch[SCRATCH_F];

// ---------------- helpers ----------------
__device__ __forceinline__ uint32_t smem_u32(const void* p) {
    uint32_t a;
    asm("{ .reg .u64 t; cvta.to.shared.u64 t, %1; cvt.u32.u64 %0, t; }" : "=r"(a) : "l"(p));
    return a;
}
__device__ __forceinline__ void split_h(float f, unsigned short& h, unsigned short& l) {
    __half hh = __float2half_rn(f);
    float r = f - __half2float(hh);
    __half ll = __float2half_rn(r);
    h = __half_as_ushort(hh);
    l = __half_as_ushort(ll);
}
__device__ __forceinline__ uint32_t pack2(unsigned short a, unsigned short b) {
    return (uint32_t)a | ((uint32_t)b << 16);
}
__device__ __forceinline__ void cp_async16(uint32_t saddr, const void* gaddr) {
    asm volatile("cp.async.cg.shared.global [%0], [%1], 16;" :: "r"(saddr), "l"(gaddr));
}
__device__ __forceinline__ void cp_commit() {
    asm volatile("cp.async.commit_group;");
}
template <int N>
__device__ __forceinline__ void cp_wait() {
    asm volatile("cp.async.wait_group %0;" :: "n"(N));
}
__device__ __forceinline__ void ldsm_x4(uint32_t* f, uint32_t addr) {
    asm volatile("ldmatrix.sync.aligned.m8n8.x4.shared.b16 {%0,%1,%2,%3}, [%4];"
                 : "=r"(f[0]), "=r"(f[1]), "=r"(f[2]), "=r"(f[3]) : "r"(addr));
}
__device__ __forceinline__ void ldsm_x4_t(uint32_t* f, uint32_t addr) {
    asm volatile("ldmatrix.sync.aligned.m8n8.x4.trans.shared.b16 {%0,%1,%2,%3}, [%4];"
                 : "=r"(f[0]), "=r"(f[1]), "=r"(f[2]), "=r"(f[3]) : "r"(addr));
}
__device__ __forceinline__ void mma_16816(float* c, const uint32_t* a, uint32_t b0, uint32_t b1) {
    asm volatile(
        "mma.sync.aligned.m16n8k16.row.col.f32.f16.f16.f32 "
        "{%0,%1,%2,%3}, {%4,%5,%6,%7}, {%8,%9}, {%0,%1,%2,%3};"
        : "+f"(c[0]), "+f"(c[1]), "+f"(c[2]), "+f"(c[3])
        : "r"(a[0]), "r"(a[1]), "r"(a[2]), "r"(a[3]), "r"(b0), "r"(b1));
}
__device__ __forceinline__ uint32_t csw8(uint32_t c, uint32_t row) {  // 256B rows (16 chunks)
    return (c & 0x8u) | ((c ^ (row & 7u)) & 0x7u);
}

// ---------------- prep: eff + bias concat ----------------
__global__ void prep_kernel(const float* __restrict__ mask,
                            const float* __restrict__ qb, const float* __restrict__ kb,
                            const float* __restrict__ vb,
                            float* __restrict__ eff, float* __restrict__ bias) {
    int bx = blockIdx.x;
    if (bx < 2) {
        float s = 0.f;
        for (int i = threadIdx.x; i < S_; i += blockDim.x) s += mask[bx * S_ + i];
        #pragma unroll
        for (int off = 16; off; off >>= 1) s += __shfl_xor_sync(0xffffffffu, s, off);
        __shared__ float red[8];
        if ((threadIdx.x & 31) == 0) red[threadIdx.x >> 5] = s;
        __syncthreads();
        if (threadIdx.x == 0) {
            float t = 0.f;
            for (int i = 0; i < 8; i++) t += red[i];
            eff[bx] = t;
        }
    } else {
        int i = (bx - 2) * 256 + threadIdx.x;
        if (i < 2048) bias[i] = qb[i];
        else if (i < 2304) bias[i] = kb[i - 2048];
        else if (i < 2560) bias[i] = vb[i - 2304];
    }
}

// ---------------- pack activations X[2048x2048] f32 -> fp16 rows of 2048 ----------------
__global__ void __launch_bounds__(256) convA_kernel(const float* __restrict__ X,
                                                    __half* __restrict__ Ap) {
    int g = blockIdx.x * 256 + threadIdx.x;
    int m = g >> 8;
    int kg = (g & 255) << 3;
    const float* xp = X + ((size_t)m << 11) + kg;
    float f[8];
    *(float4*)f       = *(const float4*)xp;
    *(float4*)(f + 4) = *(const float4*)(xp + 4);
    unsigned short h[8];
    #pragma unroll
    for (int i = 0; i < 8; i++) h[i] = __half_as_ushort(__float2half_rn(f[i]));
    uint4 Hi = make_uint4(pack2(h[0],h[1]), pack2(h[2],h[3]), pack2(h[4],h[5]), pack2(h[6],h[7]));
    *(uint4*)(Ap + (size_t)m * KP + kg) = Hi;
}

// ---------------- all weight packs in one launch ----------------
__global__ void __launch_bounds__(256) convB_all(
    const float* __restrict__ qw, const float* __restrict__ kw,
    const float* __restrict__ vw, const float* __restrict__ ow,
    __half* __restrict__ Bqkv, __half* __restrict__ Bow)
{
    __shared__ float s[32][33];
    int bx = blockIdx.x;
    const float* W; __half* Bp; int N, noff, nx;
    if (bx < 64)      { W = qw; Bp = Bqkv; N = 2048; noff = 0;    nx = bx; }
    else if (bx < 72) { W = kw; Bp = Bqkv; N = 256;  noff = 2048; nx = bx - 64; }
    else if (bx < 80) { W = vw; Bp = Bqkv; N = 256;  noff = 2304; nx = bx - 72; }
    else              { W = ow; Bp = Bow;  N = 2048; noff = 0;    nx = bx - 80; }
    int n0 = nx << 5, k0 = blockIdx.y << 5;
    int tid = threadIdx.x;
    #pragma unroll
    for (int p = 0; p < 4; p++) {
        int e = tid + p * 256;
        int ki = e >> 5, ni = e & 31;
        s[ki][ni] = W[(size_t)(k0 + ki) * N + n0 + ni];
    }
    __syncthreads();
    if (tid < 128) {
        int ni = tid >> 2, kg = (tid & 3) << 3;
        unsigned short h[8];
        #pragma unroll
        for (int j = 0; j < 8; j++) h[j] = __half_as_ushort(__float2half_rn(s[kg + j][ni]));
        uint4 Hi = make_uint4(pack2(h[0],h[1]), pack2(h[2],h[3]), pack2(h[4],h[5]), pack2(h[6],h[7]));
        *(uint4*)(Bp + (size_t)(noff + n0 + ni) * KP + k0 + kg) = Hi;
    }
}

// ---------------- HMMA GEMM: 128x128 CTA, 8 warps (64x32 tile), BK=32, 4-stage, K=2048 ----------------
#define BKC 32
#define STAGE_B 16384
#define GEMM_SMEM 65536
#define KITERS (KP / BKC)   // 64

__device__ __forceinline__ void stage_load(uint32_t sbase, int stage,
                                           const __half* Ag, const __half* Bg,
                                           int k0, int lrow, int lchunk) {
    uint32_t sa = sbase + stage * STAGE_B;
    #pragma unroll
    for (int i = 0; i < 2; i++) {
        int row = lrow + i * 64;
        uint32_t sw = (uint32_t)((lchunk ^ ((row >> 1) & 3)) << 4);
        cp_async16(sa + row * 64 + sw,        Ag + (size_t)row * KP + k0 + lchunk * 8);
        cp_async16(sa + 8192 + row * 64 + sw, Bg + (size_t)row * KP + k0 + lchunk * 8);
    }
}

#define GEMM_PREAMBLE()                                                               \
    extern __shared__ char smc[];                                                     \
    uint32_t sbase = smem_u32(smc);                                                   \
    const int tid = threadIdx.x;                                                      \
    const int mt = blockIdx.y, nt = blockIdx.x;                                       \
    const int warp = tid >> 5, lane = tid & 31;                                       \
    const int wm = warp >> 2, wn = warp & 3;                                          \
    const int lrow = tid >> 2;                                                        \
    const int lchunk = tid & 3;                                                       \
    const int arow = wm * 64 + ((lane >> 3) & 1) * 8 + (lane & 7);                    \
    const int achi = (lane >> 4) & 1;                                                 \
    const uint32_t asw = (uint32_t)((arow >> 1) & 3);                                 \
    const uint32_t abase = (uint32_t)(arow * 64);                                     \
    const int brow = wn * 32 + ((lane >> 4) & 1) * 8 + (lane & 7);                    \
    const int bclo = (lane >> 3) & 1;                                                 \
    const uint32_t bsw = (uint32_t)((brow >> 1) & 3);                                 \
    const uint32_t bbase = (uint32_t)(brow * 64);                                     \
    float acc[16][4];                                                                 \
    _Pragma("unroll")                                                                 \
    for (int i = 0; i < 16; i++) { acc[i][0]=0.f; acc[i][1]=0.f; acc[i][2]=0.f; acc[i][3]=0.f; }

#define GEMM_MAINLOOP()                                                               \
    {                                                                                 \
        _Pragma("unroll")                                                             \
        for (int s = 0; s < 3; s++) { stage_load(sbase, s, Ag, Bg, s * BKC, lrow, lchunk); cp_commit(); } \
        for (int kt = 0; kt < KITERS; kt++) {                                         \
            cp_wait<2>();                                                             \
            __syncthreads();                                                          \
            int nxt = kt + 3;                                                         \
            if (nxt < KITERS) stage_load(sbase, nxt & 3, Ag, Bg, nxt * BKC, lrow, lchunk); \
            cp_commit();                                                              \
            uint32_t sa = sbase + (kt & 3) * STAGE_B;                                 \
            uint32_t sb = sa + 8192;                                                  \
            _Pragma("unroll")                                                         \
            for (int ks = 0; ks < 2; ks++) {                                          \
                uint32_t af[4][4];                                                    \
                _Pragma("unroll")                                                     \
                for (int m = 0; m < 4; m++)                                           \
                    ldsm_x4(af[m], sa + abase + m * 1024 + ((((uint32_t)(ks * 2 + achi)) ^ asw) << 4)); \
                uint32_t bf0[4], bf1[4];                                              \
                ldsm_x4(bf0, sb + bbase +        ((((uint32_t)(ks * 2 + bclo)) ^ bsw) << 4)); \
                ldsm_x4(bf1, sb + bbase + 1024 + ((((uint32_t)(ks * 2 + bclo)) ^ bsw) << 4)); \
                _Pragma("unroll")                                                     \
                for (int m = 0; m < 4; m++) {                                         \
                    mma_16816(acc[m * 4 + 0], af[m], bf0[0], bf0[1]);                 \
                    mma_16816(acc[m * 4 + 1], af[m], bf0[2], bf0[3]);                 \
                    mma_16816(acc[m * 4 + 2], af[m], bf1[0], bf1[1]);                 \
                    mma_16816(acc[m * 4 + 3], af[m], bf1[2], bf1[3]);                 \
                }                                                                     \
            }                                                                         \
        }                                                                             \
    }

// ---------------- generic GEMM (O-projection): f32 output ----------------
__global__ void __launch_bounds__(256, 2) gemm_mma_kernel(
    const __half* __restrict__ A, const __half* __restrict__ Bm,
    float* __restrict__ C, int Ntot)
{
    GEMM_PREAMBLE();
    const __half* Ag = A  + (size_t)(mt * 128) * KP;
    const __half* Bg = Bm + (size_t)(nt * 128) * KP;
    GEMM_MAINLOOP();

    #pragma unroll
    for (int n = 0; n < 4; n++) {
        int col = nt * 128 + wn * 32 + n * 8 + (lane & 3) * 2;
        #pragma unroll
        for (int m = 0; m < 4; m++) {
            int row = mt * 128 + wm * 64 + m * 16 + (lane >> 2);
            *(float2*)(C + (size_t)row * Ntot + col)       = make_float2(acc[m*4+n][0], acc[m*4+n][1]);
            *(float2*)(C + (size_t)(row + 8) * Ntot + col) = make_float2(acc[m*4+n][2], acc[m*4+n][3]);
        }
    }
}

// ---------------- fused QKV GEMM: bias + RMSNorm + RoPE + mask + pack ----------------
__global__ void __launch_bounds__(256, 2) gemm_qkv_fused(
    const __half* __restrict__ A, const __half* __restrict__ Bm,
    const float* __restrict__ bias,
    const float* __restrict__ cosb, const float* __restrict__ sinb,
    const float* __restrict__ mask,
    const float* __restrict__ q_gamma, const float* __restrict__ k_gamma,
    __half* __restrict__ Qpk, __half* __restrict__ Kpk, __half* __restrict__ Vpk)
{
    __shared__ float ssq[4][128];
    GEMM_PREAMBLE();
    const __half* Ag = A  + (size_t)(mt * 128) * KP;
    const __half* Bg = Bm + (size_t)(nt * 128) * KP;
    GEMM_MAINLOOP();

    cp_wait<0>();
    __syncthreads();   // pipeline smem reusable

    // bias add
    #pragma unroll
    for (int n = 0; n < 4; n++) {
        int col = wn * 32 + n * 8 + (lane & 3) * 2;
        float b0 = bias[nt * 128 + col];
        float b1 = bias[nt * 128 + col + 1];
        #pragma unroll
        for (int m = 0; m < 4; m++) {
            acc[m*4+n][0] += b0; acc[m*4+n][1] += b1;
            acc[m*4+n][2] += b0; acc[m*4+n][3] += b1;
        }
    }

    if (nt >= 18) {
        // ---- V: mask-mul, plain fp16 ----
        int kh = nt - 18;
        #pragma unroll
        for (int m = 0; m < 4; m++) {
            int t0 = mt * 128 + wm * 64 + m * 16 + (lane >> 2);
            int b0g = t0 >> 10, s0g = t0 & 1023;
            float mv0 = mask[t0], mv1 = mask[t0 + 8];
            __half* vp0 = Vpk + ((size_t)(b0g * NKV_ + kh) * S_ + s0g) * 128;
            __half* vp1 = vp0 + 8 * 128;
            #pragma unroll
            for (int n = 0; n < 4; n++) {
                int col = wn * 32 + n * 8 + (lane & 3) * 2;
                *(__half2*)(vp0 + col) = __floats2half2_rn(acc[m*4+n][0] * mv0, acc[m*4+n][1] * mv0);
                *(__half2*)(vp1 + col) = __floats2half2_rn(acc[m*4+n][2] * mv1, acc[m*4+n][3] * mv1);
            }
        }
        return;
    }

    // ---- Q or K: RMSNorm over 128 head dims ----
    const bool isQ = (nt < 16);
    const float* gamma = isQ ? q_gamma : k_gamma;
    float* snv = (float*)smc;   // 128 x 128 f32, col rotated by 4*row

    #pragma unroll
    for (int m = 0; m < 4; m++) {
        float a0 = 0.f, a1 = 0.f;
        #pragma unroll
        for (int n = 0; n < 4; n++) {
            a0 += acc[m*4+n][0]*acc[m*4+n][0] + acc[m*4+n][1]*acc[m*4+n][1];
            a1 += acc[m*4+n][2]*acc[m*4+n][2] + acc[m*4+n][3]*acc[m*4+n][3];
        }
        a0 += __shfl_xor_sync(0xffffffffu, a0, 1);
        a0 += __shfl_xor_sync(0xffffffffu, a0, 2);
        a1 += __shfl_xor_sync(0xffffffffu, a1, 1);
        a1 += __shfl_xor_sync(0xffffffffu, a1, 2);
        if ((lane & 3) == 0) {
            int r0 = wm * 64 + m * 16 + (lane >> 2);
            ssq[wn][r0]     = a0;
            ssq[wn][r0 + 8] = a1;
        }
    }
    __syncthreads();

    #pragma unroll
    for (int m = 0; m < 4; m++) {
        int r0 = wm * 64 + m * 16 + (lane >> 2);
        int r1 = r0 + 8;
        float tot0 = ssq[0][r0] + ssq[1][r0] + ssq[2][r0] + ssq[3][r0];
        float tot1 = ssq[0][r1] + ssq[1][r1] + ssq[2][r1] + ssq[3][r1];
        float rms0 = rsqrtf(tot0 * (1.0f / HD_) + 1e-6f);
        float rms1 = rsqrtf(tot1 * (1.0f / HD_) + 1e-6f);
        #pragma unroll
        for (int n = 0; n < 4; n++) {
            int d0 = wn * 32 + n * 8 + (lane & 3) * 2;
            float g0 = gamma[d0], g1 = gamma[d0 + 1];
            snv[r0 * 128 + ((d0     + 4 * r0) & 127)] = acc[m*4+n][0] * rms0 * g0;
            snv[r0 * 128 + ((d0 + 1 + 4 * r0) & 127)] = acc[m*4+n][1] * rms0 * g1;
            snv[r1 * 128 + ((d0     + 4 * r1) & 127)] = acc[m*4+n][2] * rms1 * g0;
            snv[r1 * 128 + ((d0 + 1 + 4 * r1) & 127)] = acc[m*4+n][3] * rms1 * g1;
        }
    }
    __syncthreads();

    // RoPE + pack + write: warp owns 16 rows, lane owns 4 dims
    int hh = isQ ? nt : (nt - 16);
    int d0 = lane * 4;
    int sec = (d0 < 16) ? 0 : (d0 < 40) ? 1 : (d0 < 64) ? 2 : (d0 < 80) ? 0 : (d0 < 104) ? 1 : 2;
    #pragma unroll 1
    for (int rr = 0; rr < 16; rr++) {
        int row = warp * 16 + rr;
        int t = mt * 128 + row;
        int bb = t >> 10, s = t & 1023;
        size_t ci = (((size_t)sec * B_ + bb) * S_ + s) * HD_ + d0;
        float c4[4], s4[4];
        *(float4*)c4 = *(const float4*)(cosb + ci);
        *(float4*)s4 = *(const float4*)(sinb + ci);
        float outv[4];
        #pragma unroll
        for (int j = 0; j < 4; j++) {
            int d = d0 + j;
            float nv = snv[row * 128 + ((d + 4 * row) & 127)];
            float pn = snv[row * 128 + (((d ^ 64) + 4 * row) & 127)];
            float part = (d < 64) ? -pn : pn;
            outv[j] = nv * c4[j] + part * s4[j];
        }
        unsigned short h[4];
        if (isQ) {
            #pragma unroll
            for (int j = 0; j < 4; j++) h[j] = __half_as_ushort(__float2half_rn(outv[j]));
            __half* qp = Qpk + ((size_t)(bb * NH_ + hh) * S_ + s) * 128;
            *(uint2*)(qp + d0) = make_uint2(pack2(h[0], h[1]), pack2(h[2], h[3]));
        } else {
            float mval = mask[t];
            #pragma unroll
            for (int j = 0; j < 4; j++) h[j] = __half_as_ushort(__float2half_rn(outv[j] * mval));
            __half* kp = Kpk + ((size_t)(bb * NKV_ + hh) * S_ + s) * 128;
            *(uint2*)(kp + d0) = make_uint2(pack2(h[0], h[1]), pack2(h[2], h[3]));
        }
    }
}

// ---------------- tensor-core flash attention (fp16, plain Q; P kept split) ----------------
#define ATTN_SMEM 81920

__global__ void __launch_bounds__(128, 2) attn_tc_kernel(
    const __half* __restrict__ Qpk, const __half* __restrict__ Kpk,
    const __half* __restrict__ Vpk, const float* __restrict__ eff,
    __half* __restrict__ Apk)
{
    extern __shared__ char smc[];
    uint32_t sbase = smem_u32(smc);

    int bid = blockIdx.x;
    int qt = 15 - (bid >> 5);
    int rem = bid & 31;
    int h = rem >> 1, b = rem & 1;
    int kvh = h / G_;
    int tid = threadIdx.x, warp = tid >> 5, lane = tid & 31;

    const __half* Qg = Qpk + ((size_t)(b * NH_ + h) * S_ + qt * 64) * 128;
    const __half* Kg = Kpk + ((size_t)(b * NKV_ + kvh) * S_) * 128;
    const __half* Vg = Vpk + ((size_t)(b * NKV_ + kvh) * S_) * 128;

    #pragma unroll
    for (int it = 0; it < 8; it++) {
        int idx = it * 128 + tid;
        int r = idx >> 4, c = idx & 15;
        cp_async16(sbase + r * 256 + csw8(c, r) * 16, Qg + (size_t)r * 128 + c * 8);
    }
    cp_commit();
    cp_wait<0>();
    __syncthreads();

    uint32_t qh[8][4];
    {
        int row = warp * 16 + ((lane >> 3) & 1) * 8 + (lane & 7);
        uint32_t roff = sbase + row * 256;
        uint32_t r7 = row & 7;
        int chi = (lane >> 4) & 1;
        #pragma unroll
        for (int j = 0; j < 8; j++) {
            uint32_t ch = 2 * j + chi;
            ldsm_x4(qh[j], roff + ((ch & 8u) | ((ch ^ r7) & 7u)) * 16);
        }
    }

    int ntiles = qt + 1;
    int eff_i = (int)(eff[b] + 0.5f);

    #pragma unroll
    for (int pt = 0; pt < 2; pt++) {
        if (pt < ntiles) {
            #pragma unroll
            for (int it = 0; it < 8; it++) {
                int idx = it * 128 + tid;
                int r = idx >> 4, c = idx & 15;
                uint32_t ds = 16384u + (uint32_t)pt * 32768 + r * 256 + csw8(c, r) * 16;
                size_t go = (size_t)(pt * 64 + r) * 128 + c * 8;
                cp_async16(sbase + ds,         Kg + go);
                cp_async16(sbase + ds + 16384, Vg + go);
            }
        }
        cp_commit();
    }

    float m0 = -1e30f, m1 = -1e30f, ls0 = 0.f, ls1 = 0.f;
    float o[16][4];
    #pragma unroll
    for (int i = 0; i < 16; i++) { o[i][0] = o[i][1] = o[i][2] = o[i][3] = 0.f; }

    const float scale = 0.08838834764831845f;
    int row0 = qt * 64 + warp * 16 + (lane >> 2);
    int colb = (lane & 3) * 2;
    int krbase = ((lane >> 4) & 1) * 8 + (lane & 7);
    int kchi = (lane >> 3) & 1;
    int vrbase = ((lane >> 3) & 1) * 8 + (lane & 7);
    int vchi = (lane >> 4) & 1;

    for (int kt = 0; kt < ntiles; kt++) {
        cp_wait<1>();
        __syncthreads();
        uint32_t sk = sbase + 16384u + (uint32_t)(kt & 1) * 32768;
        uint32_t sv = sk + 16384;

        float s[8][4];
        #pragma unroll
        for (int i = 0; i < 8; i++) { s[i][0] = s[i][1] = s[i][2] = s[i][3] = 0.f; }

        #pragma unroll
        for (int nbp = 0; nbp < 4; nbp++) {
            int krow = nbp * 16 + krbase;
            uint32_t kroff = sk + krow * 256;
            uint32_t kr7 = krow & 7;
            #pragma unroll
            for (int j = 0; j < 8; j++) {
                uint32_t ch = 2 * j + kchi;
                uint32_t kf[4];
                ldsm_x4(kf, kroff + ((ch & 8u) | ((ch ^ kr7) & 7u)) * 16);
                mma_16816(s[2*nbp],   qh[j], kf[0], kf[1]);
                mma_16816(s[2*nbp+1], qh[j], kf[2], kf[3]);
            }
        }

        float mx0 = -1e30f, mx1 = -1e30f;
        #pragma unroll
        for (int nb = 0; nb < 8; nb++) {
            int c0 = kt * 64 + nb * 8 + colb;
            #pragma unroll
            for (int e = 0; e < 2; e++) {
                int cc = c0 + e;
                float v0 = (cc <= row0     && cc < eff_i) ? s[nb][e]   * scale : -1e9f;
                float v1 = (cc <= row0 + 8 && cc < eff_i) ? s[nb][2+e] * scale : -1e9f;
                s[nb][e] = v0; s[nb][2+e] = v1;
                mx0 = fmaxf(mx0, v0); mx1 = fmaxf(mx1, v1);
            }
        }
        mx0 = fmaxf(mx0, __shfl_xor_sync(0xffffffffu, mx0, 1));
        mx0 = fmaxf(mx0, __shfl_xor_sync(0xffffffffu, mx0, 2));
        mx1 = fmaxf(mx1, __shfl_xor_sync(0xffffffffu, mx1, 1));
        mx1 = fmaxf(mx1, __shfl_xor_sync(0xffffffffu, mx1, 2));
        float m0n = fmaxf(m0, mx0), m1n = fmaxf(m1, mx1);
        float cr0 = __expf(m0 - m0n), cr1 = __expf(m1 - m1n);
        float sum0 = 0.f, sum1 = 0.f;
        #pragma unroll
        for (int nb = 0; nb < 8; nb++) {
            #pragma unroll
            for (int e = 0; e < 2; e++) {
                float p0 = __expf(s[nb][e]   - m0n);
                float p1 = __expf(s[nb][2+e] - m1n);
                s[nb][e] = p0; s[nb][2+e] = p1;
                sum0 += p0; sum1 += p1;
            }
        }
        sum0 += __shfl_xor_sync(0xffffffffu, sum0, 1);
        sum0 += __shfl_xor_sync(0xffffffffu, sum0, 2);
        sum1 += __shfl_xor_sync(0xffffffffu, sum1, 1);
        sum1 += __shfl_xor_sync(0xffffffffu, sum1, 2);
        ls0 = ls0 * cr0 + sum0; m0 = m0n;
        ls1 = ls1 * cr1 + sum1; m1 = m1n;
        #pragma unroll
        for (int i = 0; i < 16; i++) {
            o[i][0] *= cr0; o[i][1] *= cr0;
            o[i][2] *= cr1; o[i][3] *= cr1;
        }

        uint32_t ph[4][4], pl[4][4];
        #pragma unroll
        for (int j2 = 0; j2 < 4; j2++) {
            #pragma unroll
            for (int q = 0; q < 4; q++) {
                int nb = 2 * j2 + (q >> 1);
                int e  = (q & 1) * 2;
                unsigned short ha, la, hb, lb2;
                split_h(s[nb][e],     ha, la);
                split_h(s[nb][e + 1], hb, lb2);
                int slot = (q >> 1) * 2 + (q & 1);
                ph[j2][slot] = pack2(ha, hb);
                pl[j2][slot] = pack2(la, lb2);
            }
        }

        #pragma unroll
        for (int j2 = 0; j2 < 4; j2++) {
            int vrow = j2 * 16 + vrbase;
            uint32_t vroff = sv + vrow * 256;
            uint32_t vr7 = vrow & 7;
            #pragma unroll
            for (int nbp = 0; nbp < 8; nbp++) {
                uint32_t ch = 2 * nbp + vchi;
                uint32_t vf[4];
                ldsm_x4_t(vf, vroff + ((ch & 8u) | ((ch ^ vr7) & 7u)) * 16);
                mma_16816(o[2*nbp],   ph[j2], vf[0], vf[1]);
                mma_16816(o[2*nbp+1], ph[j2], vf[2], vf[3]);
                mma_16816(o[2*nbp],   pl[j2], vf[0], vf[1]);
                mma_16816(o[2*nbp+1], pl[j2], vf[2], vf[3]);
            }
        }

        __syncthreads();
        int nxt = kt + 2;
        if (nxt < ntiles) {
            #pragma unroll
            for (int it = 0; it < 8; it++) {
                int idx = it * 128 + tid;
                int r = idx >> 4, c = idx & 15;
                uint32_t ds = 16384u + (uint32_t)(kt & 1) * 32768 + r * 256 + csw8(c, r) * 16;
                size_t go = (size_t)(nxt * 64 + r) * 128 + c * 8;
                cp_async16(sbase + ds,         Kg + go);
                cp_async16(sbase + ds + 16384, Vg + go);
            }
        }
        cp_commit();
    }

    // ---- epilogue: write plain fp16 rows of Apack (K stride 2048) ----
    float inv0 = 1.0f / ls0, inv1 = 1.0f / ls1;
    int t0 = b * S_ + qt * 64 + warp * 16 + (lane >> 2);
    size_t r0b = (size_t)t0 * KP;
    size_t r1b = (size_t)(t0 + 8) * KP;
    #pragma unroll
    for (int db = 0; db < 16; db++) {
        int c = h * 128 + db * 8 + colb;
        __half h0 = __float2half_rn(o[db][0] * inv0);
        __half h1 = __float2half_rn(o[db][1] * inv0);
        *(uint32_t*)(Apk + r0b + c) = pack2(__half_as_ushort(h0), __half_as_ushort(h1));
        h0 = __float2half_rn(o[db][2] * inv1);
        h1 = __float2half_rn(o[db][3] * inv1);
        *(uint32_t*)(Apk + r1b + c) = pack2(__half_as_ushort(h0), __half_as_ushort(h1));
    }
}

// ---------------- launcher ----------------
extern "C" void kernel_launch(void* const* d_in, const int* in_sizes, int n_in,
                              void* d_out, int out_size)
{
    const float* x       = (const float*)d_in[0];
    const float* cosb    = (const float*)d_in[1];
    const float* sinb    = (const float*)d_in[2];
    const float* mask    = (const float*)d_in[3];
    const float* q_w     = (const float*)d_in[4];
    const float* q_b     = (const float*)d_in[5];
    const float* k_w     = (const float*)d_in[6];
    const float* k_b     = (const float*)d_in[7];
    const float* v_w     = (const float*)d_in[8];
    const float* v_b     = (const float*)d_in[9];
    const float* q_gamma = (const float*)d_in[10];
    const float* k_gamma = (const float*)d_in[11];
    const float* o_w     = (const float*)d_in[12];
    float* out = (float*)d_out;

    float* scratch = nullptr;
    cudaGetSymbolAddress((void**)&scratch, g_scratch);
    float* geff = scratch + OFF_EFF;
    float* bias = scratch + OFF_BIAS;
    __half* Apack = (__half*)(scratch + OFF_APK);
    __half* Bqkv  = (__half*)(scratch + OFF_BQKV);
    __half* Bow   = (__half*)(scratch + OFF_BOW);
    __half* Qpk   = (__half*)(scratch + OFF_QPK);
    __half* Kpk   = (__half*)(scratch + OFF_KPK);
    __half* Vpk   = (__half*)(scratch + OFF_VPK);

    cudaFuncSetAttribute(gemm_mma_kernel, cudaFuncAttributeMaxDynamicSharedMemorySize, GEMM_SMEM);
    cudaFuncSetAttribute(gemm_qkv_fused,  cudaFuncAttributeMaxDynamicSharedMemorySize, GEMM_SMEM);
    cudaFuncSetAttribute(attn_tc_kernel,  cudaFuncAttributeMaxDynamicSharedMemorySize, ATTN_SMEM);

    // launch order: ncu (-s 5 -c 1) captures index 5 = O-proj GEMM
    prep_kernel<<<12, 256>>>(mask, q_b, k_b, v_b, geff, bias);                      // 0
    convA_kernel<<<2048, 256>>>(x, Apack);                                          // 1
    convB_all<<<dim3(144, 64), 256>>>(q_w, k_w, v_w, o_w, Bqkv, Bow);               // 2
    gemm_qkv_fused<<<dim3(NQKV / 128, 16), 256, GEMM_SMEM>>>(                        // 3
        Apack, Bqkv, bias, cosb, sinb, mask, q_gamma, k_gamma, Qpk, Kpk, Vpk);
    attn_tc_kernel<<<512, 128, ATTN_SMEM>>>(Qpk, Kpk, Vpk, geff, Apack);            // 4
    gemm_mma_kernel<<<dim3(16, 16), 256, GEMM_SMEM>>>(Apack, Bow, out, 2048);       // 5
}

// round 11
// speedup vs baseline: 2.2340x; 1.0078x over previous
#include <cuda_runtime.h>
#include <cuda_fp16.h>
#include <math.h>
#include <stdint.h>

#define B_   2
#define S_   1024
#define HID_ 2048
#define NH_  16
#define NKV_ 2
#define HD_  128
#define G_   (NH_/NKV_)
#define TOK  (B_*S_)

#define KP   2048
#define NQKV 2560

// ---------------- scratch ----------------
#define OFF_EFF  0
#define OFF_BIAS 4
#define OFF_APK  2564
#define OFF_BQKV 2099716
#define OFF_BOW  4721156
#define OFF_QPK  6818308
#define OFF_KPK  8915460
#define OFF_VPK  9177604
#define SCRATCH_F 9439748
__device__ __align__(256) float g_scratch[SCRATCH_F];

// ---------------- helpers ----------------
__device__ __forceinline__ uint32_t smem_u32(const void* p) {
    uint32_t a;
    asm("{ .reg .u64 t; cvta.to.shared.u64 t, %1; cvt.u32.u64 %0, t; }" : "=r"(a) : "l"(p));
    return a;
}
__device__ __forceinline__ void split_h(float f, unsigned short& h, unsigned short& l) {
    __half hh = __float2half_rn(f);
    float r = f - __half2float(hh);
    __half ll = __float2half_rn(r);
    h = __half_as_ushort(hh);
    l = __half_as_ushort(ll);
}
__device__ __forceinline__ uint32_t pack2(unsigned short a, unsigned short b) {
    return (uint32_t)a | ((uint32_t)b << 16);
}
__device__ __forceinline__ void cp_async16(uint32_t saddr, const void* gaddr) {
    asm volatile("cp.async.cg.shared.global [%0], [%1], 16;" :: "r"(saddr), "l"(gaddr));
}
__device__ __forceinline__ void cp_commit() {
    asm volatile("cp.async.commit_group;");
}
template <int N>
__device__ __forceinline__ void cp_wait() {
    asm volatile("cp.async.wait_group %0;" :: "n"(N));
}
__device__ __forceinline__ void ldsm_x4(uint32_t* f, uint32_t addr) {
    asm volatile("ldmatrix.sync.aligned.m8n8.x4.shared.b16 {%0,%1,%2,%3}, [%4];"
                 : "=r"(f[0]), "=r"(f[1]), "=r"(f[2]), "=r"(f[3]) : "r"(addr));
}
__device__ __forceinline__ void ldsm_x4_t(uint32_t* f, uint32_t addr) {
    asm volatile("ldmatrix.sync.aligned.m8n8.x4.trans.shared.b16 {%0,%1,%2,%3}, [%4];"
                 : "=r"(f[0]), "=r"(f[1]), "=r"(f[2]), "=r"(f[3]) : "r"(addr));
}
__device__ __forceinline__ void mma_16816(float* c, const uint32_t* a, uint32_t b0, uint32_t b1) {
    asm volatile(
        "mma.sync.aligned.m16n8k16.row.col.f32.f16.f16.f32 "
        "{%0,%1,%2,%3}, {%4,%5,%6,%7}, {%8,%9}, {%0,%1,%2,%3};"
        : "+f"(c[0]), "+f"(c[1]), "+f"(c[2]), "+f"(c[3])
        : "r"(a[0]), "r"(a[1]), "r"(a[2]), "r"(a[3]), "r"(b0), "r"(b1));
}
__device__ __forceinline__ uint32_t csw8(uint32_t c, uint32_t row) {
    return (c & 0x8u) | ((c ^ (row & 7u)) & 0x7u);
}

// ---------------- prep ----------------
__global__ void prep_kernel(const float* __restrict__ mask,
                            const float* __restrict__ qb, const float* __restrict__ kb,
                            const float* __restrict__ vb,
                            float* __restrict__ eff, float* __restrict__ bias) {
    int bx = blockIdx.x;
    if (bx < 2) {
        float s = 0.f;
        for (int i = threadIdx.x; i < S_; i += blockDim.x) s += mask[bx * S_ + i];
        #pragma unroll
        for (int off = 16; off; off >>= 1) s += __shfl_xor_sync(0xffffffffu, s, off);
        __shared__ float red[8];
        if ((threadIdx.x & 31) == 0) red[threadIdx.x >> 5] = s;
        __syncthreads();
        if (threadIdx.x == 0) {
            float t = 0.f;
            for (int i = 0; i < 8; i++) t += red[i];
            eff[bx] = t;
        }
    } else {
        int i = (bx - 2) * 256 + threadIdx.x;
        if (i < 2048) bias[i] = qb[i];
        else if (i < 2304) bias[i] = kb[i - 2048];
        else if (i < 2560) bias[i] = vb[i - 2304];
    }
}

// ---------------- convA ----------------
__global__ void __launch_bounds__(256) convA_kernel(const float* __restrict__ X,
                                                    __half* __restrict__ Ap) {
    int g = blockIdx.x * 256 + threadIdx.x;
    int m = g >> 8;
    int kg = (g & 255) << 3;
    const float* xp = X + ((size_t)m << 11) + kg;
    float f[8];
    *(float4*)f       = *(const float4*)xp;
    *(float4*)(f + 4) = *(const float4*)(xp + 4);
    unsigned short h[8];
    #pragma unroll
    for (int i = 0; i < 8; i++) h[i] = __half_as_ushort(__float2half_rn(f[i]));
    uint4 Hi = make_uint4(pack2(h[0],h[1]), pack2(h[2],h[3]), pack2(h[4],h[5]), pack2(h[6],h[7]));
    *(uint4*)(Ap + (size_t)m * KP + kg) = Hi;
}

// ---------------- convB ----------------
__global__ void __launch_bounds__(256) convB_all(
    const float* __restrict__ qw, const float* __restrict__ kw,
    const float* __restrict__ vw, const float* __restrict__ ow,
    __half* __restrict__ Bqkv, __half* __restrict__ Bow)
{
    __shared__ float s[32][33];
    int bx = blockIdx.x;
    const float* W; __half* Bp; int N, noff, nx;
    if (bx < 64)      { W = qw; Bp = Bqkv; N = 2048; noff = 0;    nx = bx; }
    else if (bx < 72) { W = kw; Bp = Bqkv; N = 256;  noff = 2048; nx = bx - 64; }
    else if (bx < 80) { W = vw; Bp = Bqkv; N = 256;  noff = 2304; nx = bx - 72; }
    else              { W = ow; Bp = Bow;  N = 2048; noff = 0;    nx = bx - 80; }
    int n0 = nx << 5, k0 = blockIdx.y << 5;
    int tid = threadIdx.x;
    #pragma unroll
    for (int p = 0; p < 4; p++) {
        int e = tid + p * 256;
        int ki = e >> 5, ni = e & 31;
        s[ki][ni] = W[(size_t)(k0 + ki) * N + n0 + ni];
    }
    __syncthreads();
    if (tid < 128) {
        int ni = tid >> 2, kg = (tid & 3) << 3;
        unsigned short h[8];
        #pragma unroll
        for (int j = 0; j < 8; j++) h[j] = __half_as_ushort(__float2half_rn(s[kg + j][ni]));
        uint4 Hi = make_uint4(pack2(h[0],h[1]), pack2(h[2],h[3]), pack2(h[4],h[5]), pack2(h[6],h[7]));
        *(uint4*)(Bp + (size_t)(noff + n0 + ni) * KP + k0 + kg) = Hi;
    }
}

// ================= O-proj GEMM: 128x128 CTA, 8 warps, BK=32, 4-stage (unchanged) =================
#define BKC 32
#define STAGE_B 16384
#define GEMM_SMEM 65536
#define KITERS (KP / BKC)   // 64

__device__ __forceinline__ void stage_load(uint32_t sbase, int stage,
                                           const __half* Ag, const __half* Bg,
                                           int k0, int lrow, int lchunk) {
    uint32_t sa = sbase + stage * STAGE_B;
    #pragma unroll
    for (int i = 0; i < 2; i++) {
        int row = lrow + i * 64;
        uint32_t sw = (uint32_t)((lchunk ^ ((row >> 1) & 3)) << 4);
        cp_async16(sa + row * 64 + sw,        Ag + (size_t)row * KP + k0 + lchunk * 8);
        cp_async16(sa + 8192 + row * 64 + sw, Bg + (size_t)row * KP + k0 + lchunk * 8);
    }
}

__global__ void __launch_bounds__(256, 2) gemm_mma_kernel(
    const __half* __restrict__ A, const __half* __restrict__ Bm,
    float* __restrict__ C, int Ntot)
{
    extern __shared__ char smc[];
    uint32_t sbase = smem_u32(smc);
    const int tid = threadIdx.x;
    const int mt = blockIdx.y, nt = blockIdx.x;
    const int warp = tid >> 5, lane = tid & 31;
    const int wm = warp >> 2, wn = warp & 3;
    const int lrow = tid >> 2;
    const int lchunk = tid & 3;
    const int arow = wm * 64 + ((lane >> 3) & 1) * 8 + (lane & 7);
    const int achi = (lane >> 4) & 1;
    const uint32_t asw = (uint32_t)((arow >> 1) & 3);
    const uint32_t abase = (uint32_t)(arow * 64);
    const int brow = wn * 32 + ((lane >> 4) & 1) * 8 + (lane & 7);
    const int bclo = (lane >> 3) & 1;
    const uint32_t bsw = (uint32_t)((brow >> 1) & 3);
    const uint32_t bbase = (uint32_t)(brow * 64);
    float acc[16][4];
    #pragma unroll
    for (int i = 0; i < 16; i++) { acc[i][0]=0.f; acc[i][1]=0.f; acc[i][2]=0.f; acc[i][3]=0.f; }

    const __half* Ag = A  + (size_t)(mt * 128) * KP;
    const __half* Bg = Bm + (size_t)(nt * 128) * KP;

    #pragma unroll
    for (int s = 0; s < 3; s++) { stage_load(sbase, s, Ag, Bg, s * BKC, lrow, lchunk); cp_commit(); }
    for (int kt = 0; kt < KITERS; kt++) {
        cp_wait<2>();
        __syncthreads();
        int nxt = kt + 3;
        if (nxt < KITERS) stage_load(sbase, nxt & 3, Ag, Bg, nxt * BKC, lrow, lchunk);
        cp_commit();
        uint32_t sa = sbase + (kt & 3) * STAGE_B;
        uint32_t sb = sa + 8192;
        #pragma unroll
        for (int ks = 0; ks < 2; ks++) {
            uint32_t af[4][4];
            #pragma unroll
            for (int m = 0; m < 4; m++)
                ldsm_x4(af[m], sa + abase + m * 1024 + ((((uint32_t)(ks * 2 + achi)) ^ asw) << 4));
            uint32_t bf0[4], bf1[4];
            ldsm_x4(bf0, sb + bbase +        ((((uint32_t)(ks * 2 + bclo)) ^ bsw) << 4));
            ldsm_x4(bf1, sb + bbase + 1024 + ((((uint32_t)(ks * 2 + bclo)) ^ bsw) << 4));
            #pragma unroll
            for (int m = 0; m < 4; m++) {
                mma_16816(acc[m * 4 + 0], af[m], bf0[0], bf0[1]);
                mma_16816(acc[m * 4 + 1], af[m], bf0[2], bf0[3]);
                mma_16816(acc[m * 4 + 2], af[m], bf1[0], bf1[1]);
                mma_16816(acc[m * 4 + 3], af[m], bf1[2], bf1[3]);
            }
        }
    }

    #pragma unroll
    for (int n = 0; n < 4; n++) {
        int col = nt * 128 + wn * 32 + n * 8 + (lane & 3) * 2;
        #pragma unroll
        for (int m = 0; m < 4; m++) {
            int row = mt * 128 + wm * 64 + m * 16 + (lane >> 2);
            *(float2*)(C + (size_t)row * Ntot + col)       = make_float2(acc[m*4+n][0], acc[m*4+n][1]);
            *(float2*)(C + (size_t)(row + 8) * Ntot + col) = make_float2(acc[m*4+n][2], acc[m*4+n][3]);
        }
    }
}

// ================= fused QKV GEMM: 64x128 CTA, 8 warps (32x32 tile), BK=32, 4-stage, 3 CTAs/SM =================
#define QSTAGE_B 12288          // A 4KB + B 8KB
#define QKV_SMEM 49152

__device__ __forceinline__ void qstage_load(uint32_t sbase, int stage,
                                            const __half* Ag, const __half* Bg,
                                            int k0, int tid) {
    uint32_t sa = sbase + stage * QSTAGE_B;
    uint32_t sb = sa + 4096;
    int r = tid >> 2, c = tid & 3;
    uint32_t swa = (uint32_t)((c ^ ((r >> 1) & 3)) << 4);
    if (r < 64)
        cp_async16(sa + r * 64 + swa, Ag + (size_t)r * KP + k0 + c * 8);
    #pragma unroll
    for (int i = 0; i < 2; i++) {
        int rb = r + i * 64;
        uint32_t swb = (uint32_t)((c ^ ((rb >> 1) & 3)) << 4);
        cp_async16(sb + rb * 64 + swb, Bg + (size_t)rb * KP + k0 + c * 8);
    }
}

__global__ void __launch_bounds__(256, 3) gemm_qkv_fused(
    const __half* __restrict__ A, const __half* __restrict__ Bm,
    const float* __restrict__ bias,
    const float* __restrict__ cosb, const float* __restrict__ sinb,
    const float* __restrict__ mask,
    const float* __restrict__ q_gamma, const float* __restrict__ k_gamma,
    __half* __restrict__ Qpk, __half* __restrict__ Kpk, __half* __restrict__ Vpk)
{
    extern __shared__ char smc[];
    __shared__ float ssq[4][64];
    uint32_t sbase = smem_u32(smc);
    const int tid = threadIdx.x;
    const int nt = blockIdx.x, mt = blockIdx.y;
    const int warp = tid >> 5, lane = tid & 31;
    const int wm = warp >> 2, wn = warp & 3;    // wm in {0,1}, wn in {0..3}

    const int arow = wm * 32 + ((lane >> 3) & 1) * 8 + (lane & 7);
    const int achi = (lane >> 4) & 1;
    const uint32_t asw = (uint32_t)((arow >> 1) & 3);
    const uint32_t abase = (uint32_t)(arow * 64);
    const int brow = wn * 32 + ((lane >> 4) & 1) * 8 + (lane & 7);
    const int bclo = (lane >> 3) & 1;
    const uint32_t bsw = (uint32_t)((brow >> 1) & 3);
    const uint32_t bbase = (uint32_t)(brow * 64);

    float acc[8][4];
    #pragma unroll
    for (int i = 0; i < 8; i++) { acc[i][0]=0.f; acc[i][1]=0.f; acc[i][2]=0.f; acc[i][3]=0.f; }

    const __half* Ag = A  + (size_t)(mt * 64) * KP;
    const __half* Bg = Bm + (size_t)(nt * 128) * KP;

    #pragma unroll
    for (int s = 0; s < 3; s++) { qstage_load(sbase, s, Ag, Bg, s * BKC, tid); cp_commit(); }
    for (int kt = 0; kt < KITERS; kt++) {
        cp_wait<2>();
        __syncthreads();
        int nxt = kt + 3;
        if (nxt < KITERS) qstage_load(sbase, nxt & 3, Ag, Bg, nxt * BKC, tid);
        cp_commit();
        uint32_t sa = sbase + (kt & 3) * QSTAGE_B;
        uint32_t sb = sa + 4096;
        #pragma unroll
        for (int ks = 0; ks < 2; ks++) {
            uint32_t af[2][4];
            #pragma unroll
            for (int m = 0; m < 2; m++)
                ldsm_x4(af[m], sa + abase + m * 1024 + ((((uint32_t)(ks * 2 + achi)) ^ asw) << 4));
            uint32_t bf0[4], bf1[4];
            ldsm_x4(bf0, sb + bbase +        ((((uint32_t)(ks * 2 + bclo)) ^ bsw) << 4));
            ldsm_x4(bf1, sb + bbase + 1024 + ((((uint32_t)(ks * 2 + bclo)) ^ bsw) << 4));
            #pragma unroll
            for (int m = 0; m < 2; m++) {
                mma_16816(acc[m * 4 + 0], af[m], bf0[0], bf0[1]);
                mma_16816(acc[m * 4 + 1], af[m], bf0[2], bf0[3]);
                mma_16816(acc[m * 4 + 2], af[m], bf1[0], bf1[1]);
                mma_16816(acc[m * 4 + 3], af[m], bf1[2], bf1[3]);
            }
        }
    }

    cp_wait<0>();
    __syncthreads();   // pipeline smem reusable

    // bias add
    #pragma unroll
    for (int n = 0; n < 4; n++) {
        int col = wn * 32 + n * 8 + (lane & 3) * 2;
        float b0 = bias[nt * 128 + col];
        float b1 = bias[nt * 128 + col + 1];
        #pragma unroll
        for (int m = 0; m < 2; m++) {
            acc[m*4+n][0] += b0; acc[m*4+n][1] += b1;
            acc[m*4+n][2] += b0; acc[m*4+n][3] += b1;
        }
    }

    if (nt >= 18) {
        // ---- V ----
        int kh = nt - 18;
        #pragma unroll
        for (int m = 0; m < 2; m++) {
            int t0 = mt * 64 + wm * 32 + m * 16 + (lane >> 2);
            int b0g = t0 >> 10, s0g = t0 & 1023;
            float mv0 = mask[t0], mv1 = mask[t0 + 8];
            __half* vp0 = Vpk + ((size_t)(b0g * NKV_ + kh) * S_ + s0g) * 128;
            __half* vp1 = vp0 + 8 * 128;
            #pragma unroll
            for (int n = 0; n < 4; n++) {
                int col = wn * 32 + n * 8 + (lane & 3) * 2;
                *(__half2*)(vp0 + col) = __floats2half2_rn(acc[m*4+n][0] * mv0, acc[m*4+n][1] * mv0);
                *(__half2*)(vp1 + col) = __floats2half2_rn(acc[m*4+n][2] * mv1, acc[m*4+n][3] * mv1);
            }
        }
        return;
    }

    // ---- Q or K: RMSNorm over 128 head dims ----
    const bool isQ = (nt < 16);
    const float* gamma = isQ ? q_gamma : k_gamma;
    float* snv = (float*)smc;   // 64 x 128 f32, col rotated by 4*row (32KB <= 48KB)

    #pragma unroll
    for (int m = 0; m < 2; m++) {
        float a0 = 0.f, a1 = 0.f;
        #pragma unroll
        for (int n = 0; n < 4; n++) {
            a0 += acc[m*4+n][0]*acc[m*4+n][0] + acc[m*4+n][1]*acc[m*4+n][1];
            a1 += acc[m*4+n][2]*acc[m*4+n][2] + acc[m*4+n][3]*acc[m*4+n][3];
        }
        a0 += __shfl_xor_sync(0xffffffffu, a0, 1);
        a0 += __shfl_xor_sync(0xffffffffu, a0, 2);
        a1 += __shfl_xor_sync(0xffffffffu, a1, 1);
        a1 += __shfl_xor_sync(0xffffffffu, a1, 2);
        if ((lane & 3) == 0) {
            int r0 = wm * 32 + m * 16 + (lane >> 2);
            ssq[wn][r0]     = a0;
            ssq[wn][r0 + 8] = a1;
        }
    }
    __syncthreads();

    #pragma unroll
    for (int m = 0; m < 2; m++) {
        int r0 = wm * 32 + m * 16 + (lane >> 2);
        int r1 = r0 + 8;
        float tot0 = ssq[0][r0] + ssq[1][r0] + ssq[2][r0] + ssq[3][r0];
        float tot1 = ssq[0][r1] + ssq[1][r1] + ssq[2][r1] + ssq[3][r1];
        float rms0 = rsqrtf(tot0 * (1.0f / HD_) + 1e-6f);
        float rms1 = rsqrtf(tot1 * (1.0f / HD_) + 1e-6f);
        #pragma unroll
        for (int n = 0; n < 4; n++) {
            int d0 = wn * 32 + n * 8 + (lane & 3) * 2;
            float g0 = gamma[d0], g1 = gamma[d0 + 1];
            snv[r0 * 128 + ((d0     + 4 * r0) & 127)] = acc[m*4+n][0] * rms0 * g0;
            snv[r0 * 128 + ((d0 + 1 + 4 * r0) & 127)] = acc[m*4+n][1] * rms0 * g1;
            snv[r1 * 128 + ((d0     + 4 * r1) & 127)] = acc[m*4+n][2] * rms1 * g0;
            snv[r1 * 128 + ((d0 + 1 + 4 * r1) & 127)] = acc[m*4+n][3] * rms1 * g1;
        }
    }
    __syncthreads();

    // RoPE + pack + write: warp owns 8 rows, lane owns 4 dims
    int hh = isQ ? nt : (nt - 16);
    int d0 = lane * 4;
    int sec = (d0 < 16) ? 0 : (d0 < 40) ? 1 : (d0 < 64) ? 2 : (d0 < 80) ? 0 : (d0 < 104) ? 1 : 2;
    #pragma unroll 1
    for (int rr = 0; rr < 8; rr++) {
        int row = warp * 8 + rr;
        int t = mt * 64 + row;
        int bb = t >> 10, s = t & 1023;
        size_t ci = (((size_t)sec * B_ + bb) * S_ + s) * HD_ + d0;
        float c4[4], s4[4];
        *(float4*)c4 = *(const float4*)(cosb + ci);
        *(float4*)s4 = *(const float4*)(sinb + ci);
        float outv[4];
        #pragma unroll
        for (int j = 0; j < 4; j++) {
            int d = d0 + j;
            float nv = snv[row * 128 + ((d + 4 * row) & 127)];
            float pn = snv[row * 128 + (((d ^ 64) + 4 * row) & 127)];
            float part = (d < 64) ? -pn : pn;
            outv[j] = nv * c4[j] + part * s4[j];
        }
        unsigned short h[4];
        if (isQ) {
            #pragma unroll
            for (int j = 0; j < 4; j++) h[j] = __half_as_ushort(__float2half_rn(outv[j]));
            __half* qp = Qpk + ((size_t)(bb * NH_ + hh) * S_ + s) * 128;
            *(uint2*)(qp + d0) = make_uint2(pack2(h[0], h[1]), pack2(h[2], h[3]));
        } else {
            float mval = mask[t];
            #pragma unroll
            for (int j = 0; j < 4; j++) h[j] = __half_as_ushort(__float2half_rn(outv[j] * mval));
            __half* kp = Kpk + ((size_t)(bb * NKV_ + hh) * S_ + s) * 128;
            *(uint2*)(kp + d0) = make_uint2(pack2(h[0], h[1]), pack2(h[2], h[3]));
        }
    }
}

// ---------------- tensor-core flash attention (unchanged) ----------------
#define ATTN_SMEM 81920

__global__ void __launch_bounds__(128, 2) attn_tc_kernel(
    const __half* __restrict__ Qpk, const __half* __restrict__ Kpk,
    const __half* __restrict__ Vpk, const float* __restrict__ eff,
    __half* __restrict__ Apk)
{
    extern __shared__ char smc[];
    uint32_t sbase = smem_u32(smc);

    int bid = blockIdx.x;
    int qt = 15 - (bid >> 5);
    int rem = bid & 31;
    int h = rem >> 1, b = rem & 1;
    int kvh = h / G_;
    int tid = threadIdx.x, warp = tid >> 5, lane = tid & 31;

    const __half* Qg = Qpk + ((size_t)(b * NH_ + h) * S_ + qt * 64) * 128;
    const __half* Kg = Kpk + ((size_t)(b * NKV_ + kvh) * S_) * 128;
    const __half* Vg = Vpk + ((size_t)(b * NKV_ + kvh) * S_) * 128;

    #pragma unroll
    for (int it = 0; it < 8; it++) {
        int idx = it * 128 + tid;
        int r = idx >> 4, c = idx & 15;
        cp_async16(sbase + r * 256 + csw8(c, r) * 16, Qg + (size_t)r * 128 + c * 8);
    }
    cp_commit();
    cp_wait<0>();
    __syncthreads();

    uint32_t qh[8][4];
    {
        int row = warp * 16 + ((lane >> 3) & 1) * 8 + (lane & 7);
        uint32_t roff = sbase + row * 256;
        uint32_t r7 = row & 7;
        int chi = (lane >> 4) & 1;
        #pragma unroll
        for (int j = 0; j < 8; j++) {
            uint32_t ch = 2 * j + chi;
            ldsm_x4(qh[j], roff + ((ch & 8u) | ((ch ^ r7) & 7u)) * 16);
        }
    }

    int ntiles = qt + 1;
    int eff_i = (int)(eff[b] + 0.5f);

    #pragma unroll
    for (int pt = 0; pt < 2; pt++) {
        if (pt < ntiles) {
            #pragma unroll
            for (int it = 0; it < 8; it++) {
                int idx = it * 128 + tid;
                int r = idx >> 4, c = idx & 15;
                uint32_t ds = 16384u + (uint32_t)pt * 32768 + r * 256 + csw8(c, r) * 16;
                size_t go = (size_t)(pt * 64 + r) * 128 + c * 8;
                cp_async16(sbase + ds,         Kg + go);
                cp_async16(sbase + ds + 16384, Vg + go);
            }
        }
        cp_commit();
    }

    float m0 = -1e30f, m1 = -1e30f, ls0 = 0.f, ls1 = 0.f;
    float o[16][4];
    #pragma unroll
    for (int i = 0; i < 16; i++) { o[i][0] = o[i][1] = o[i][2] = o[i][3] = 0.f; }

    const float scale = 0.08838834764831845f;
    int row0 = qt * 64 + warp * 16 + (lane >> 2);
    int colb = (lane & 3) * 2;
    int krbase = ((lane >> 4) & 1) * 8 + (lane & 7);
    int kchi = (lane >> 3) & 1;
    int vrbase = ((lane >> 3) & 1) * 8 + (lane & 7);
    int vchi = (lane >> 4) & 1;

    for (int kt = 0; kt < ntiles; kt++) {
        cp_wait<1>();
        __syncthreads();
        uint32_t sk = sbase + 16384u + (uint32_t)(kt & 1) * 32768;
        uint32_t sv = sk + 16384;

        float s[8][4];
        #pragma unroll
        for (int i = 0; i < 8; i++) { s[i][0] = s[i][1] = s[i][2] = s[i][3] = 0.f; }

        #pragma unroll
        for (int nbp = 0; nbp < 4; nbp++) {
            int krow = nbp * 16 + krbase;
            uint32_t kroff = sk + krow * 256;
            uint32_t kr7 = krow & 7;
            #pragma unroll
            for (int j = 0; j < 8; j++) {
                uint32_t ch = 2 * j + kchi;
                uint32_t kf[4];
                ldsm_x4(kf, kroff + ((ch & 8u) | ((ch ^ kr7) & 7u)) * 16);
                mma_16816(s[2*nbp],   qh[j], kf[0], kf[1]);
                mma_16816(s[2*nbp+1], qh[j], kf[2], kf[3]);
            }
        }

        float mx0 = -1e30f, mx1 = -1e30f;
        #pragma unroll
        for (int nb = 0; nb < 8; nb++) {
            int c0 = kt * 64 + nb * 8 + colb;
            #pragma unroll
            for (int e = 0; e < 2; e++) {
                int cc = c0 + e;
                float v0 = (cc <= row0     && cc < eff_i) ? s[nb][e]   * scale : -1e9f;
                float v1 = (cc <= row0 + 8 && cc < eff_i) ? s[nb][2+e] * scale : -1e9f;
                s[nb][e] = v0; s[nb][2+e] = v1;
                mx0 = fmaxf(mx0, v0); mx1 = fmaxf(mx1, v1);
            }
        }
        mx0 = fmaxf(mx0, __shfl_xor_sync(0xffffffffu, mx0, 1));
        mx0 = fmaxf(mx0, __shfl_xor_sync(0xffffffffu, mx0, 2));
        mx1 = fmaxf(mx1, __shfl_xor_sync(0xffffffffu, mx1, 1));
        mx1 = fmaxf(mx1, __shfl_xor_sync(0xffffffffu, mx1, 2));
        float m0n = fmaxf(m0, mx0), m1n = fmaxf(m1, mx1);
        float cr0 = __expf(m0 - m0n), cr1 = __expf(m1 - m1n);
        float sum0 = 0.f, sum1 = 0.f;
        #pragma unroll
        for (int nb = 0; nb < 8; nb++) {
            #pragma unroll
            for (int e = 0; e < 2; e++) {
                float p0 = __expf(s[nb][e]   - m0n);
                float p1 = __expf(s[nb][2+e] - m1n);
                s[nb][e] = p0; s[nb][2+e] = p1;
                sum0 += p0; sum1 += p1;
            }
        }
        sum0 += __shfl_xor_sync(0xffffffffu, sum0, 1);
        sum0 += __shfl_xor_sync(0xffffffffu, sum0, 2);
        sum1 += __shfl_xor_sync(0xffffffffu, sum1, 1);
        sum1 += __shfl_xor_sync(0xffffffffu, sum1, 2);
        ls0 = ls0 * cr0 + sum0; m0 = m0n;
        ls1 = ls1 * cr1 + sum1; m1 = m1n;
        #pragma unroll
        for (int i = 0; i < 16; i++) {
            o[i][0] *= cr0; o[i][1] *= cr0;
            o[i][2] *= cr1; o[i][3] *= cr1;
        }

        uint32_t ph[4][4], pl[4][4];
        #pragma unroll
        for (int j2 = 0; j2 < 4; j2++) {
            #pragma unroll
            for (int q = 0; q < 4; q++) {
                int nb = 2 * j2 + (q >> 1);
                int e  = (q & 1) * 2;
                unsigned short ha, la, hb, lb2;
                split_h(s[nb][e],     ha, la);
                split_h(s[nb][e + 1], hb, lb2);
                int slot = (q >> 1) * 2 + (q & 1);
                ph[j2][slot] = pack2(ha, hb);
                pl[j2][slot] = pack2(la, lb2);
            }
        }

        #pragma unroll
        for (int j2 = 0; j2 < 4; j2++) {
            int vrow = j2 * 16 + vrbase;
            uint32_t vroff = sv + vrow * 256;
            uint32_t vr7 = vrow & 7;
            #pragma unroll
            for (int nbp = 0; nbp < 8; nbp++) {
                uint32_t ch = 2 * nbp + vchi;
                uint32_t vf[4];
                ldsm_x4_t(vf, vroff + ((ch & 8u) | ((ch ^ vr7) & 7u)) * 16);
                mma_16816(o[2*nbp],   ph[j2], vf[0], vf[1]);
                mma_16816(o[2*nbp+1], ph[j2], vf[2], vf[3]);
                mma_16816(o[2*nbp],   pl[j2], vf[0], vf[1]);
                mma_16816(o[2*nbp+1], pl[j2], vf[2], vf[3]);
            }
        }

        __syncthreads();
        int nxt = kt + 2;
        if (nxt < ntiles) {
            #pragma unroll
            for (int it = 0; it < 8; it++) {
                int idx = it * 128 + tid;
                int r = idx >> 4, c = idx & 15;
                uint32_t ds = 16384u + (uint32_t)(kt & 1) * 32768 + r * 256 + csw8(c, r) * 16;
                size_t go = (size_t)(nxt * 64 + r) * 128 + c * 8;
                cp_async16(sbase + ds,         Kg + go);
                cp_async16(sbase + ds + 16384, Vg + go);
            }
        }
        cp_commit();
    }

    float inv0 = 1.0f / ls0, inv1 = 1.0f / ls1;
    int t0 = b * S_ + qt * 64 + warp * 16 + (lane >> 2);
    size_t r0b = (size_t)t0 * KP;
    size_t r1b = (size_t)(t0 + 8) * KP;
    #pragma unroll
    for (int db = 0; db < 16; db++) {
        int c = h * 128 + db * 8 + colb;
        __half h0 = __float2half_rn(o[db][0] * inv0);
        __half h1 = __float2half_rn(o[db][1] * inv0);
        *(uint32_t*)(Apk + r0b + c) = pack2(__half_as_ushort(h0), __half_as_ushort(h1));
        h0 = __float2half_rn(o[db][2] * inv1);
        h1 = __float2half_rn(o[db][3] * inv1);
        *(uint32_t*)(Apk + r1b + c) = pack2(__half_as_ushort(h0), __half_as_ushort(h1));
    }
}

// ---------------- launcher ----------------
extern "C" void kernel_launch(void* const* d_in, const int* in_sizes, int n_in,
                              void* d_out, int out_size)
{
    const float* x       = (const float*)d_in[0];
    const float* cosb    = (const float*)d_in[1];
    const float* sinb    = (const float*)d_in[2];
    const float* mask    = (const float*)d_in[3];
    const float* q_w     = (const float*)d_in[4];
    const float* q_b     = (const float*)d_in[5];
    const float* k_w     = (const float*)d_in[6];
    const float* k_b     = (const float*)d_in[7];
    const float* v_w     = (const float*)d_in[8];
    const float* v_b     = (const float*)d_in[9];
    const float* q_gamma = (const float*)d_in[10];
    const float* k_gamma = (const float*)d_in[11];
    const float* o_w     = (const float*)d_in[12];
    float* out = (float*)d_out;

    float* scratch = nullptr;
    cudaGetSymbolAddress((void**)&scratch, g_scratch);
    float* geff = scratch + OFF_EFF;
    float* bias = scratch + OFF_BIAS;
    __half* Apack = (__half*)(scratch + OFF_APK);
    __half* Bqkv  = (__half*)(scratch + OFF_BQKV);
    __half* Bow   = (__half*)(scratch + OFF_BOW);
    __half* Qpk   = (__half*)(scratch + OFF_QPK);
    __half* Kpk   = (__half*)(scratch + OFF_KPK);
    __half* Vpk   = (__half*)(scratch + OFF_VPK);

    cudaFuncSetAttribute(gemm_mma_kernel, cudaFuncAttributeMaxDynamicSharedMemorySize, GEMM_SMEM);
    cudaFuncSetAttribute(gemm_qkv_fused,  cudaFuncAttributeMaxDynamicSharedMemorySize, QKV_SMEM);
    cudaFuncSetAttribute(attn_tc_kernel,  cudaFuncAttributeMaxDynamicSharedMemorySize, ATTN_SMEM);

    // launch order: ncu (-s 5 -c 1) captures index 5 = O-proj GEMM
    prep_kernel<<<12, 256>>>(mask, q_b, k_b, v_b, geff, bias);                      // 0
    convA_kernel<<<2048, 256>>>(x, Apack);                                          // 1
    convB_all<<<dim3(144, 64), 256>>>(q_w, k_w, v_w, o_w, Bqkv, Bow);               // 2
    gemm_qkv_fused<<<dim3(NQKV / 128, 32), 256, QKV_SMEM>>>(                         // 3
        Apack, Bqkv, bias, cosb, sinb, mask, q_gamma, k_gamma, Qpk, Kpk, Vpk);
    attn_tc_kernel<<<512, 128, ATTN_SMEM>>>(Qpk, Kpk, Vpk, geff, Apack);            // 4
    gemm_mma_kernel<<<dim3(16, 16), 256, GEMM_SMEM>>>(Apack, Bow, out, 2048);       // 5
}

// round 12
// speedup vs baseline: 2.2722x; 1.0171x over previous
#include <cuda_runtime.h>
#include <cuda_fp16.h>
#include <math.h>
#include <stdint.h>

#define B_   2
#define S_   1024
#define HID_ 2048
#define NH_  16
#define NKV_ 2
#define HD_  128
#define G_   (NH_/NKV_)
#define TOK  (B_*S_)

#define KP   2048
#define NQKV 2560

// ---------------- scratch ----------------
#define OFF_EFF  0
#define OFF_BIAS 4
#define OFF_APK  2564
#define OFF_BQKV 2099716
#define OFF_BOW  4721156
#define OFF_QPK  6818308
#define OFF_KPK  8915460
#define OFF_VPK  9177604
#define SCRATCH_F 9439748
__device__ __align__(256) float g_scratch[SCRATCH_F];

// ---------------- helpers ----------------
__device__ __forceinline__ uint32_t smem_u32(const void* p) {
    uint32_t a;
    asm("{ .reg .u64 t; cvta.to.shared.u64 t, %1; cvt.u32.u64 %0, t; }" : "=r"(a) : "l"(p));
    return a;
}
__device__ __forceinline__ void split_h(float f, unsigned short& h, unsigned short& l) {
    __half hh = __float2half_rn(f);
    float r = f - __half2float(hh);
    __half ll = __float2half_rn(r);
    h = __half_as_ushort(hh);
    l = __half_as_ushort(ll);
}
__device__ __forceinline__ uint32_t pack2(unsigned short a, unsigned short b) {
    return (uint32_t)a | ((uint32_t)b << 16);
}
__device__ __forceinline__ void cp_async16(uint32_t saddr, const void* gaddr) {
    asm volatile("cp.async.cg.shared.global [%0], [%1], 16;" :: "r"(saddr), "l"(gaddr));
}
__device__ __forceinline__ void cp_commit() {
    asm volatile("cp.async.commit_group;");
}
template <int N>
__device__ __forceinline__ void cp_wait() {
    asm volatile("cp.async.wait_group %0;" :: "n"(N));
}
__device__ __forceinline__ void ldsm_x4(uint32_t* f, uint32_t addr) {
    asm volatile("ldmatrix.sync.aligned.m8n8.x4.shared.b16 {%0,%1,%2,%3}, [%4];"
                 : "=r"(f[0]), "=r"(f[1]), "=r"(f[2]), "=r"(f[3]) : "r"(addr));
}
__device__ __forceinline__ void ldsm_x4_t(uint32_t* f, uint32_t addr) {
    asm volatile("ldmatrix.sync.aligned.m8n8.x4.trans.shared.b16 {%0,%1,%2,%3}, [%4];"
                 : "=r"(f[0]), "=r"(f[1]), "=r"(f[2]), "=r"(f[3]) : "r"(addr));
}
__device__ __forceinline__ void mma_16816(float* c, const uint32_t* a, uint32_t b0, uint32_t b1) {
    asm volatile(
        "mma.sync.aligned.m16n8k16.row.col.f32.f16.f16.f32 "
        "{%0,%1,%2,%3}, {%4,%5,%6,%7}, {%8,%9}, {%0,%1,%2,%3};"
        : "+f"(c[0]), "+f"(c[1]), "+f"(c[2]), "+f"(c[3])
        : "r"(a[0]), "r"(a[1]), "r"(a[2]), "r"(a[3]), "r"(b0), "r"(b1));
}
__device__ __forceinline__ uint32_t csw8(uint32_t c, uint32_t row) {
    return (c & 0x8u) | ((c ^ (row & 7u)) & 0x7u);
}

// ---------------- prep ----------------
__global__ void prep_kernel(const float* __restrict__ mask,
                            const float* __restrict__ qb, const float* __restrict__ kb,
                            const float* __restrict__ vb,
                            float* __restrict__ eff, float* __restrict__ bias) {
    int bx = blockIdx.x;
    if (bx < 2) {
        float s = 0.f;
        for (int i = threadIdx.x; i < S_; i += blockDim.x) s += mask[bx * S_ + i];
        #pragma unroll
        for (int off = 16; off; off >>= 1) s += __shfl_xor_sync(0xffffffffu, s, off);
        __shared__ float red[8];
        if ((threadIdx.x & 31) == 0) red[threadIdx.x >> 5] = s;
        __syncthreads();
        if (threadIdx.x == 0) {
            float t = 0.f;
            for (int i = 0; i < 8; i++) t += red[i];
            eff[bx] = t;
        }
    } else {
        int i = (bx - 2) * 256 + threadIdx.x;
        if (i < 2048) bias[i] = qb[i];
        else if (i < 2304) bias[i] = kb[i - 2048];
        else if (i < 2560) bias[i] = vb[i - 2304];
    }
}

// ---------------- convA ----------------
__global__ void __launch_bounds__(256) convA_kernel(const float* __restrict__ X,
                                                    __half* __restrict__ Ap) {
    int g = blockIdx.x * 256 + threadIdx.x;
    int m = g >> 8;
    int kg = (g & 255) << 3;
    const float* xp = X + ((size_t)m << 11) + kg;
    float f[8];
    *(float4*)f       = *(const float4*)xp;
    *(float4*)(f + 4) = *(const float4*)(xp + 4);
    unsigned short h[8];
    #pragma unroll
    for (int i = 0; i < 8; i++) h[i] = __half_as_ushort(__float2half_rn(f[i]));
    uint4 Hi = make_uint4(pack2(h[0],h[1]), pack2(h[2],h[3]), pack2(h[4],h[5]), pack2(h[6],h[7]));
    *(uint4*)(Ap + (size_t)m * KP + kg) = Hi;
}

// ---------------- convB ----------------
__global__ void __launch_bounds__(256) convB_all(
    const float* __restrict__ qw, const float* __restrict__ kw,
    const float* __restrict__ vw, const float* __restrict__ ow,
    __half* __restrict__ Bqkv, __half* __restrict__ Bow)
{
    __shared__ float s[32][33];
    int bx = blockIdx.x;
    const float* W; __half* Bp; int N, noff, nx;
    if (bx < 64)      { W = qw; Bp = Bqkv; N = 2048; noff = 0;    nx = bx; }
    else if (bx < 72) { W = kw; Bp = Bqkv; N = 256;  noff = 2048; nx = bx - 64; }
    else if (bx < 80) { W = vw; Bp = Bqkv; N = 256;  noff = 2304; nx = bx - 72; }
    else              { W = ow; Bp = Bow;  N = 2048; noff = 0;    nx = bx - 80; }
    int n0 = nx << 5, k0 = blockIdx.y << 5;
    int tid = threadIdx.x;
    #pragma unroll
    for (int p = 0; p < 4; p++) {
        int e = tid + p * 256;
        int ki = e >> 5, ni = e & 31;
        s[ki][ni] = W[(size_t)(k0 + ki) * N + n0 + ni];
    }
    __syncthreads();
    if (tid < 128) {
        int ni = tid >> 2, kg = (tid & 3) << 3;
        unsigned short h[8];
        #pragma unroll
        for (int j = 0; j < 8; j++) h[j] = __half_as_ushort(__float2half_rn(s[kg + j][ni]));
        uint4 Hi = make_uint4(pack2(h[0],h[1]), pack2(h[2],h[3]), pack2(h[4],h[5]), pack2(h[6],h[7]));
        *(uint4*)(Bp + (size_t)(noff + n0 + ni) * KP + k0 + kg) = Hi;
    }
}

// ================= O-proj GEMM: 128x128 CTA, 8 warps, BK=32, 4-stage, pipelined frags =================
#define BKC 32
#define STAGE_B 16384
#define GEMM_SMEM 65536
#define KITERS (KP / BKC)   // 64

__device__ __forceinline__ void stage_load(uint32_t sbase, int stage,
                                           const __half* Ag, const __half* Bg,
                                           int k0, int lrow, int lchunk) {
    uint32_t sa = sbase + stage * STAGE_B;
    #pragma unroll
    for (int i = 0; i < 2; i++) {
        int row = lrow + i * 64;
        uint32_t sw = (uint32_t)((lchunk ^ ((row >> 1) & 3)) << 4);
        cp_async16(sa + row * 64 + sw,        Ag + (size_t)row * KP + k0 + lchunk * 8);
        cp_async16(sa + 8192 + row * 64 + sw, Bg + (size_t)row * KP + k0 + lchunk * 8);
    }
}

__global__ void __launch_bounds__(256, 2) gemm_mma_kernel(
    const __half* __restrict__ A, const __half* __restrict__ Bm,
    float* __restrict__ C, int Ntot)
{
    extern __shared__ char smc[];
    uint32_t sbase = smem_u32(smc);
    const int tid = threadIdx.x;
    const int mt = blockIdx.y, nt = blockIdx.x;
    const int warp = tid >> 5, lane = tid & 31;
    const int wm = warp >> 2, wn = warp & 3;
    const int lrow = tid >> 2;
    const int lchunk = tid & 3;
    const int arow = wm * 64 + ((lane >> 3) & 1) * 8 + (lane & 7);
    const int achi = (lane >> 4) & 1;
    const uint32_t asw = (uint32_t)((arow >> 1) & 3);
    const uint32_t abase = (uint32_t)(arow * 64);
    const int brow = wn * 32 + ((lane >> 4) & 1) * 8 + (lane & 7);
    const int bclo = (lane >> 3) & 1;
    const uint32_t bsw = (uint32_t)((brow >> 1) & 3);
    const uint32_t bbase = (uint32_t)(brow * 64);
    float acc[16][4];
    #pragma unroll
    for (int i = 0; i < 16; i++) { acc[i][0]=0.f; acc[i][1]=0.f; acc[i][2]=0.f; acc[i][3]=0.f; }

    const __half* Ag = A  + (size_t)(mt * 128) * KP;
    const __half* Bg = Bm + (size_t)(nt * 128) * KP;

    #pragma unroll
    for (int s = 0; s < 3; s++) { stage_load(sbase, s, Ag, Bg, s * BKC, lrow, lchunk); cp_commit(); }
    cp_wait<2>();
    __syncthreads();   // stage 0 visible to all threads

    for (int kt = 0; kt < KITERS; kt++) {
        uint32_t sa = sbase + (kt & 3) * STAGE_B;
        uint32_t sb = sa + 8192;

        // early fragment loads from stage kt (guaranteed ready & visible)
        uint32_t af0[4][4], af1[4][4], bf00[4], bf01[4];
        #pragma unroll
        for (int m = 0; m < 4; m++)
            ldsm_x4(af0[m], sa + abase + m * 1024 + ((((uint32_t)achi) ^ asw) << 4));
        ldsm_x4(bf00, sb + bbase +        ((((uint32_t)bclo) ^ bsw) << 4));
        ldsm_x4(bf01, sb + bbase + 1024 + ((((uint32_t)bclo) ^ bsw) << 4));
        #pragma unroll
        for (int m = 0; m < 4; m++)
            ldsm_x4(af1[m], sa + abase + m * 1024 + ((((uint32_t)(2 + achi)) ^ asw) << 4));

        cp_wait<1>();      // stage kt+1 complete (own thread)
        __syncthreads();   // propagate; also write-safety for prefetch below

        int nxt = kt + 3;
        if (nxt < KITERS) stage_load(sbase, nxt & 3, Ag, Bg, nxt * BKC, lrow, lchunk);
        cp_commit();

        // ks0 MMAs
        #pragma unroll
        for (int m = 0; m < 4; m++) {
            mma_16816(acc[m * 4 + 0], af0[m], bf00[0], bf00[1]);
            mma_16816(acc[m * 4 + 1], af0[m], bf00[2], bf00[3]);
            mma_16816(acc[m * 4 + 2], af0[m], bf01[0], bf01[1]);
            mma_16816(acc[m * 4 + 3], af0[m], bf01[2], bf01[3]);
        }
        // ks1 B frags behind ks0 MMAs
        uint32_t bf10[4], bf11[4];
        ldsm_x4(bf10, sb + bbase +        ((((uint32_t)(2 + bclo)) ^ bsw) << 4));
        ldsm_x4(bf11, sb + bbase + 1024 + ((((uint32_t)(2 + bclo)) ^ bsw) << 4));
        #pragma unroll
        for (int m = 0; m < 4; m++) {
            mma_16816(acc[m * 4 + 0], af1[m], bf10[0], bf10[1]);
            mma_16816(acc[m * 4 + 1], af1[m], bf10[2], bf10[3]);
            mma_16816(acc[m * 4 + 2], af1[m], bf11[0], bf11[1]);
            mma_16816(acc[m * 4 + 3], af1[m], bf11[2], bf11[3]);
        }
    }

    #pragma unroll
    for (int n = 0; n < 4; n++) {
        int col = nt * 128 + wn * 32 + n * 8 + (lane & 3) * 2;
        #pragma unroll
        for (int m = 0; m < 4; m++) {
            int row = mt * 128 + wm * 64 + m * 16 + (lane >> 2);
            *(float2*)(C + (size_t)row * Ntot + col)       = make_float2(acc[m*4+n][0], acc[m*4+n][1]);
            *(float2*)(C + (size_t)(row + 8) * Ntot + col) = make_float2(acc[m*4+n][2], acc[m*4+n][3]);
        }
    }
}

// ================= fused QKV GEMM: 64x128 CTA, 8 warps (32x32), BK=32, 4-stage, pipelined =================
#define QSTAGE_B 12288
#define QKV_SMEM 49152

__device__ __forceinline__ void qstage_load(uint32_t sbase, int stage,
                                            const __half* Ag, const __half* Bg,
                                            int k0, int tid) {
    uint32_t sa = sbase + stage * QSTAGE_B;
    uint32_t sb = sa + 4096;
    int r = tid >> 2, c = tid & 3;
    uint32_t swa = (uint32_t)((c ^ ((r >> 1) & 3)) << 4);
    if (r < 64)
        cp_async16(sa + r * 64 + swa, Ag + (size_t)r * KP + k0 + c * 8);
    #pragma unroll
    for (int i = 0; i < 2; i++) {
        int rb = r + i * 64;
        uint32_t swb = (uint32_t)((c ^ ((rb >> 1) & 3)) << 4);
        cp_async16(sb + rb * 64 + swb, Bg + (size_t)rb * KP + k0 + c * 8);
    }
}

__global__ void __launch_bounds__(256, 2) gemm_qkv_fused(
    const __half* __restrict__ A, const __half* __restrict__ Bm,
    const float* __restrict__ bias,
    const float* __restrict__ cosb, const float* __restrict__ sinb,
    const float* __restrict__ mask,
    const float* __restrict__ q_gamma, const float* __restrict__ k_gamma,
    __half* __restrict__ Qpk, __half* __restrict__ Kpk, __half* __restrict__ Vpk)
{
    extern __shared__ char smc[];
    __shared__ float ssq[4][64];
    uint32_t sbase = smem_u32(smc);
    const int tid = threadIdx.x;
    const int nt = blockIdx.x, mt = blockIdx.y;
    const int warp = tid >> 5, lane = tid & 31;
    const int wm = warp >> 2, wn = warp & 3;

    const int arow = wm * 32 + ((lane >> 3) & 1) * 8 + (lane & 7);
    const int achi = (lane >> 4) & 1;
    const uint32_t asw = (uint32_t)((arow >> 1) & 3);
    const uint32_t abase = (uint32_t)(arow * 64);
    const int brow = wn * 32 + ((lane >> 4) & 1) * 8 + (lane & 7);
    const int bclo = (lane >> 3) & 1;
    const uint32_t bsw = (uint32_t)((brow >> 1) & 3);
    const uint32_t bbase = (uint32_t)(brow * 64);

    float acc[8][4];
    #pragma unroll
    for (int i = 0; i < 8; i++) { acc[i][0]=0.f; acc[i][1]=0.f; acc[i][2]=0.f; acc[i][3]=0.f; }

    const __half* Ag = A  + (size_t)(mt * 64) * KP;
    const __half* Bg = Bm + (size_t)(nt * 128) * KP;

    #pragma unroll
    for (int s = 0; s < 3; s++) { qstage_load(sbase, s, Ag, Bg, s * BKC, tid); cp_commit(); }
    cp_wait<2>();
    __syncthreads();

    for (int kt = 0; kt < KITERS; kt++) {
        uint32_t sa = sbase + (kt & 3) * QSTAGE_B;
        uint32_t sb = sa + 4096;

        uint32_t af0[2][4], af1[2][4], bf00[4], bf01[4];
        #pragma unroll
        for (int m = 0; m < 2; m++)
            ldsm_x4(af0[m], sa + abase + m * 1024 + ((((uint32_t)achi) ^ asw) << 4));
        ldsm_x4(bf00, sb + bbase +        ((((uint32_t)bclo) ^ bsw) << 4));
        ldsm_x4(bf01, sb + bbase + 1024 + ((((uint32_t)bclo) ^ bsw) << 4));
        #pragma unroll
        for (int m = 0; m < 2; m++)
            ldsm_x4(af1[m], sa + abase + m * 1024 + ((((uint32_t)(2 + achi)) ^ asw) << 4));

        cp_wait<1>();
        __syncthreads();

        int nxt = kt + 3;
        if (nxt < KITERS) qstage_load(sbase, nxt & 3, Ag, Bg, nxt * BKC, tid);
        cp_commit();

        #pragma unroll
        for (int m = 0; m < 2; m++) {
            mma_16816(acc[m * 4 + 0], af0[m], bf00[0], bf00[1]);
            mma_16816(acc[m * 4 + 1], af0[m], bf00[2], bf00[3]);
            mma_16816(acc[m * 4 + 2], af0[m], bf01[0], bf01[1]);
            mma_16816(acc[m * 4 + 3], af0[m], bf01[2], bf01[3]);
        }
        uint32_t bf10[4], bf11[4];
        ldsm_x4(bf10, sb + bbase +        ((((uint32_t)(2 + bclo)) ^ bsw) << 4));
        ldsm_x4(bf11, sb + bbase + 1024 + ((((uint32_t)(2 + bclo)) ^ bsw) << 4));
        #pragma unroll
        for (int m = 0; m < 2; m++) {
            mma_16816(acc[m * 4 + 0], af1[m], bf10[0], bf10[1]);
            mma_16816(acc[m * 4 + 1], af1[m], bf10[2], bf10[3]);
            mma_16816(acc[m * 4 + 2], af1[m], bf11[0], bf11[1]);
            mma_16816(acc[m * 4 + 3], af1[m], bf11[2], bf11[3]);
        }
    }

    cp_wait<0>();
    __syncthreads();   // pipeline smem reusable

    // bias add
    #pragma unroll
    for (int n = 0; n < 4; n++) {
        int col = wn * 32 + n * 8 + (lane & 3) * 2;
        float b0 = bias[nt * 128 + col];
        float b1 = bias[nt * 128 + col + 1];
        #pragma unroll
        for (int m = 0; m < 2; m++) {
            acc[m*4+n][0] += b0; acc[m*4+n][1] += b1;
            acc[m*4+n][2] += b0; acc[m*4+n][3] += b1;
        }
    }

    if (nt >= 18) {
        int kh = nt - 18;
        #pragma unroll
        for (int m = 0; m < 2; m++) {
            int t0 = mt * 64 + wm * 32 + m * 16 + (lane >> 2);
            int b0g = t0 >> 10, s0g = t0 & 1023;
            float mv0 = mask[t0], mv1 = mask[t0 + 8];
            __half* vp0 = Vpk + ((size_t)(b0g * NKV_ + kh) * S_ + s0g) * 128;
            __half* vp1 = vp0 + 8 * 128;
            #pragma unroll
            for (int n = 0; n < 4; n++) {
                int col = wn * 32 + n * 8 + (lane & 3) * 2;
                *(__half2*)(vp0 + col) = __floats2half2_rn(acc[m*4+n][0] * mv0, acc[m*4+n][1] * mv0);
                *(__half2*)(vp1 + col) = __floats2half2_rn(acc[m*4+n][2] * mv1, acc[m*4+n][3] * mv1);
            }
        }
        return;
    }

    const bool isQ = (nt < 16);
    const float* gamma = isQ ? q_gamma : k_gamma;
    float* snv = (float*)smc;

    #pragma unroll
    for (int m = 0; m < 2; m++) {
        float a0 = 0.f, a1 = 0.f;
        #pragma unroll
        for (int n = 0; n < 4; n++) {
            a0 += acc[m*4+n][0]*acc[m*4+n][0] + acc[m*4+n][1]*acc[m*4+n][1];
            a1 += acc[m*4+n][2]*acc[m*4+n][2] + acc[m*4+n][3]*acc[m*4+n][3];
        }
        a0 += __shfl_xor_sync(0xffffffffu, a0, 1);
        a0 += __shfl_xor_sync(0xffffffffu, a0, 2);
        a1 += __shfl_xor_sync(0xffffffffu, a1, 1);
        a1 += __shfl_xor_sync(0xffffffffu, a1, 2);
        if ((lane & 3) == 0) {
            int r0 = wm * 32 + m * 16 + (lane >> 2);
            ssq[wn][r0]     = a0;
            ssq[wn][r0 + 8] = a1;
        }
    }
    __syncthreads();

    #pragma unroll
    for (int m = 0; m < 2; m++) {
        int r0 = wm * 32 + m * 16 + (lane >> 2);
        int r1 = r0 + 8;
        float tot0 = ssq[0][r0] + ssq[1][r0] + ssq[2][r0] + ssq[3][r0];
        float tot1 = ssq[0][r1] + ssq[1][r1] + ssq[2][r1] + ssq[3][r1];
        float rms0 = rsqrtf(tot0 * (1.0f / HD_) + 1e-6f);
        float rms1 = rsqrtf(tot1 * (1.0f / HD_) + 1e-6f);
        #pragma unroll
        for (int n = 0; n < 4; n++) {
            int d0 = wn * 32 + n * 8 + (lane & 3) * 2;
            float g0 = gamma[d0], g1 = gamma[d0 + 1];
            snv[r0 * 128 + ((d0     + 4 * r0) & 127)] = acc[m*4+n][0] * rms0 * g0;
            snv[r0 * 128 + ((d0 + 1 + 4 * r0) & 127)] = acc[m*4+n][1] * rms0 * g1;
            snv[r1 * 128 + ((d0     + 4 * r1) & 127)] = acc[m*4+n][2] * rms1 * g0;
            snv[r1 * 128 + ((d0 + 1 + 4 * r1) & 127)] = acc[m*4+n][3] * rms1 * g1;
        }
    }
    __syncthreads();

    int hh = isQ ? nt : (nt - 16);
    int d0 = lane * 4;
    int sec = (d0 < 16) ? 0 : (d0 < 40) ? 1 : (d0 < 64) ? 2 : (d0 < 80) ? 0 : (d0 < 104) ? 1 : 2;
    #pragma unroll 1
    for (int rr = 0; rr < 8; rr++) {
        int row = warp * 8 + rr;
        int t = mt * 64 + row;
        int bb = t >> 10, s = t & 1023;
        size_t ci = (((size_t)sec * B_ + bb) * S_ + s) * HD_ + d0;
        float c4[4], s4[4];
        *(float4*)c4 = *(const float4*)(cosb + ci);
        *(float4*)s4 = *(const float4*)(sinb + ci);
        float outv[4];
        #pragma unroll
        for (int j = 0; j < 4; j++) {
            int d = d0 + j;
            float nv = snv[row * 128 + ((d + 4 * row) & 127)];
            float pn = snv[row * 128 + (((d ^ 64) + 4 * row) & 127)];
            float part = (d < 64) ? -pn : pn;
            outv[j] = nv * c4[j] + part * s4[j];
        }
        unsigned short h[4];
        if (isQ) {
            #pragma unroll
            for (int j = 0; j < 4; j++) h[j] = __half_as_ushort(__float2half_rn(outv[j]));
            __half* qp = Qpk + ((size_t)(bb * NH_ + hh) * S_ + s) * 128;
            *(uint2*)(qp + d0) = make_uint2(pack2(h[0], h[1]), pack2(h[2], h[3]));
        } else {
            float mval = mask[t];
            #pragma unroll
            for (int j = 0; j < 4; j++) h[j] = __half_as_ushort(__float2half_rn(outv[j] * mval));
            __half* kp = Kpk + ((size_t)(bb * NKV_ + hh) * S_ + s) * 128;
            *(uint2*)(kp + d0) = make_uint2(pack2(h[0], h[1]), pack2(h[2], h[3]));
        }
    }
}

// ---------------- tensor-core flash attention (unchanged) ----------------
#define ATTN_SMEM 81920

__global__ void __launch_bounds__(128, 2) attn_tc_kernel(
    const __half* __restrict__ Qpk, const __half* __restrict__ Kpk,
    const __half* __restrict__ Vpk, const float* __restrict__ eff,
    __half* __restrict__ Apk)
{
    extern __shared__ char smc[];
    uint32_t sbase = smem_u32(smc);

    int bid = blockIdx.x;
    int qt = 15 - (bid >> 5);
    int rem = bid & 31;
    int h = rem >> 1, b = rem & 1;
    int kvh = h / G_;
    int tid = threadIdx.x, warp = tid >> 5, lane = tid & 31;

    const __half* Qg = Qpk + ((size_t)(b * NH_ + h) * S_ + qt * 64) * 128;
    const __half* Kg = Kpk + ((size_t)(b * NKV_ + kvh) * S_) * 128;
    const __half* Vg = Vpk + ((size_t)(b * NKV_ + kvh) * S_) * 128;

    #pragma unroll
    for (int it = 0; it < 8; it++) {
        int idx = it * 128 + tid;
        int r = idx >> 4, c = idx & 15;
        cp_async16(sbase + r * 256 + csw8(c, r) * 16, Qg + (size_t)r * 128 + c * 8);
    }
    cp_commit();
    cp_wait<0>();
    __syncthreads();

    uint32_t qh[8][4];
    {
        int row = warp * 16 + ((lane >> 3) & 1) * 8 + (lane & 7);
        uint32_t roff = sbase + row * 256;
        uint32_t r7 = row & 7;
        int chi = (lane >> 4) & 1;
        #pragma unroll
        for (int j = 0; j < 8; j++) {
            uint32_t ch = 2 * j + chi;
            ldsm_x4(qh[j], roff + ((ch & 8u) | ((ch ^ r7) & 7u)) * 16);
        }
    }

    int ntiles = qt + 1;
    int eff_i = (int)(eff[b] + 0.5f);

    #pragma unroll
    for (int pt = 0; pt < 2; pt++) {
        if (pt < ntiles) {
            #pragma unroll
            for (int it = 0; it < 8; it++) {
                int idx = it * 128 + tid;
                int r = idx >> 4, c = idx & 15;
                uint32_t ds = 16384u + (uint32_t)pt * 32768 + r * 256 + csw8(c, r) * 16;
                size_t go = (size_t)(pt * 64 + r) * 128 + c * 8;
                cp_async16(sbase + ds,         Kg + go);
                cp_async16(sbase + ds + 16384, Vg + go);
            }
        }
        cp_commit();
    }

    float m0 = -1e30f, m1 = -1e30f, ls0 = 0.f, ls1 = 0.f;
    float o[16][4];
    #pragma unroll
    for (int i = 0; i < 16; i++) { o[i][0] = o[i][1] = o[i][2] = o[i][3] = 0.f; }

    const float scale = 0.08838834764831845f;
    int row0 = qt * 64 + warp * 16 + (lane >> 2);
    int colb = (lane & 3) * 2;
    int krbase = ((lane >> 4) & 1) * 8 + (lane & 7);
    int kchi = (lane >> 3) & 1;
    int vrbase = ((lane >> 3) & 1) * 8 + (lane & 7);
    int vchi = (lane >> 4) & 1;

    for (int kt = 0; kt < ntiles; kt++) {
        cp_wait<1>();
        __syncthreads();
        uint32_t sk = sbase + 16384u + (uint32_t)(kt & 1) * 32768;
        uint32_t sv = sk + 16384;

        float s[8][4];
        #pragma unroll
        for (int i = 0; i < 8; i++) { s[i][0] = s[i][1] = s[i][2] = s[i][3] = 0.f; }

        #pragma unroll
        for (int nbp = 0; nbp < 4; nbp++) {
            int krow = nbp * 16 + krbase;
            uint32_t kroff = sk + krow * 256;
            uint32_t kr7 = krow & 7;
            #pragma unroll
            for (int j = 0; j < 8; j++) {
                uint32_t ch = 2 * j + kchi;
                uint32_t kf[4];
                ldsm_x4(kf, kroff + ((ch & 8u) | ((ch ^ kr7) & 7u)) * 16);
                mma_16816(s[2*nbp],   qh[j], kf[0], kf[1]);
                mma_16816(s[2*nbp+1], qh[j], kf[2], kf[3]);
            }
        }

        float mx0 = -1e30f, mx1 = -1e30f;
        #pragma unroll
        for (int nb = 0; nb < 8; nb++) {
            int c0 = kt * 64 + nb * 8 + colb;
            #pragma unroll
            for (int e = 0; e < 2; e++) {
                int cc = c0 + e;
                float v0 = (cc <= row0     && cc < eff_i) ? s[nb][e]   * scale : -1e9f;
                float v1 = (cc <= row0 + 8 && cc < eff_i) ? s[nb][2+e] * scale : -1e9f;
                s[nb][e] = v0; s[nb][2+e] = v1;
                mx0 = fmaxf(mx0, v0); mx1 = fmaxf(mx1, v1);
            }
        }
        mx0 = fmaxf(mx0, __shfl_xor_sync(0xffffffffu, mx0, 1));
        mx0 = fmaxf(mx0, __shfl_xor_sync(0xffffffffu, mx0, 2));
        mx1 = fmaxf(mx1, __shfl_xor_sync(0xffffffffu, mx1, 1));
        mx1 = fmaxf(mx1, __shfl_xor_sync(0xffffffffu, mx1, 2));
        float m0n = fmaxf(m0, mx0), m1n = fmaxf(m1, mx1);
        float cr0 = __expf(m0 - m0n), cr1 = __expf(m1 - m1n);
        float sum0 = 0.f, sum1 = 0.f;
        #pragma unroll
        for (int nb = 0; nb < 8; nb++) {
            #pragma unroll
            for (int e = 0; e < 2; e++) {
                float p0 = __expf(s[nb][e]   - m0n);
                float p1 = __expf(s[nb][2+e] - m1n);
                s[nb][e] = p0; s[nb][2+e] = p1;
                sum0 += p0; sum1 += p1;
            }
        }
        sum0 += __shfl_xor_sync(0xffffffffu, sum0, 1);
        sum0 += __shfl_xor_sync(0xffffffffu, sum0, 2);
        sum1 += __shfl_xor_sync(0xffffffffu, sum1, 1);
        sum1 += __shfl_xor_sync(0xffffffffu, sum1, 2);
        ls0 = ls0 * cr0 + sum0; m0 = m0n;
        ls1 = ls1 * cr1 + sum1; m1 = m1n;
        #pragma unroll
        for (int i = 0; i < 16; i++) {
            o[i][0] *= cr0; o[i][1] *= cr0;
            o[i][2] *= cr1; o[i][3] *= cr1;
        }

        uint32_t ph[4][4], pl[4][4];
        #pragma unroll
        for (int j2 = 0; j2 < 4; j2++) {
            #pragma unroll
            for (int q = 0; q < 4; q++) {
                int nb = 2 * j2 + (q >> 1);
                int e  = (q & 1) * 2;
                unsigned short ha, la, hb, lb2;
                split_h(s[nb][e],     ha, la);
                split_h(s[nb][e + 1], hb, lb2);
                int slot = (q >> 1) * 2 + (q & 1);
                ph[j2][slot] = pack2(ha, hb);
                pl[j2][slot] = pack2(la, lb2);
            }
        }

        #pragma unroll
        for (int j2 = 0; j2 < 4; j2++) {
            int vrow = j2 * 16 + vrbase;
            uint32_t vroff = sv + vrow * 256;
            uint32_t vr7 = vrow & 7;
            #pragma unroll
            for (int nbp = 0; nbp < 8; nbp++) {
                uint32_t ch = 2 * nbp + vchi;
                uint32_t vf[4];
                ldsm_x4_t(vf, vroff + ((ch & 8u) | ((ch ^ vr7) & 7u)) * 16);
                mma_16816(o[2*nbp],   ph[j2], vf[0], vf[1]);
                mma_16816(o[2*nbp+1], ph[j2], vf[2], vf[3]);
                mma_16816(o[2*nbp],   pl[j2], vf[0], vf[1]);
                mma_16816(o[2*nbp+1], pl[j2], vf[2], vf[3]);
            }
        }

        __syncthreads();
        int nxt = kt + 2;
        if (nxt < ntiles) {
            #pragma unroll
            for (int it = 0; it < 8; it++) {
                int idx = it * 128 + tid;
                int r = idx >> 4, c = idx & 15;
                uint32_t ds = 16384u + (uint32_t)(kt & 1) * 32768 + r * 256 + csw8(c, r) * 16;
                size_t go = (size_t)(nxt * 64 + r) * 128 + c * 8;
                cp_async16(sbase + ds,         Kg + go);
                cp_async16(sbase + ds + 16384, Vg + go);
            }
        }
        cp_commit();
    }

    float inv0 = 1.0f / ls0, inv1 = 1.0f / ls1;
    int t0 = b * S_ + qt * 64 + warp * 16 + (lane >> 2);
    size_t r0b = (size_t)t0 * KP;
    size_t r1b = (size_t)(t0 + 8) * KP;
    #pragma unroll
    for (int db = 0; db < 16; db++) {
        int c = h * 128 + db * 8 + colb;
        __half h0 = __float2half_rn(o[db][0] * inv0);
        __half h1 = __float2half_rn(o[db][1] * inv0);
        *(uint32_t*)(Apk + r0b + c) = pack2(__half_as_ushort(h0), __half_as_ushort(h1));
        h0 = __float2half_rn(o[db][2] * inv1);
        h1 = __float2half_rn(o[db][3] * inv1);
        *(uint32_t*)(Apk + r1b + c) = pack2(__half_as_ushort(h0), __half_as_ushort(h1));
    }
}

// ---------------- launcher ----------------
extern "C" void kernel_launch(void* const* d_in, const int* in_sizes, int n_in,
                              void* d_out, int out_size)
{
    const float* x       = (const float*)d_in[0];
    const float* cosb    = (const float*)d_in[1];
    const float* sinb    = (const float*)d_in[2];
    const float* mask    = (const float*)d_in[3];
    const float* q_w     = (const float*)d_in[4];
    const float* q_b     = (const float*)d_in[5];
    const float* k_w     = (const float*)d_in[6];
    const float* k_b     = (const float*)d_in[7];
    const float* v_w     = (const float*)d_in[8];
    const float* v_b     = (const float*)d_in[9];
    const float* q_gamma = (const float*)d_in[10];
    const float* k_gamma = (const float*)d_in[11];
    const float* o_w     = (const float*)d_in[12];
    float* out = (float*)d_out;

    float* scratch = nullptr;
    cudaGetSymbolAddress((void**)&scratch, g_scratch);
    float* geff = scratch + OFF_EFF;
    float* bias = scratch + OFF_BIAS;
    __half* Apack = (__half*)(scratch + OFF_APK);
    __half* Bqkv  = (__half*)(scratch + OFF_BQKV);
    __half* Bow   = (__half*)(scratch + OFF_BOW);
    __half* Qpk   = (__half*)(scratch + OFF_QPK);
    __half* Kpk   = (__half*)(scratch + OFF_KPK);
    __half* Vpk   = (__half*)(scratch + OFF_VPK);

    cudaFuncSetAttribute(gemm_mma_kernel, cudaFuncAttributeMaxDynamicSharedMemorySize, GEMM_SMEM);
    cudaFuncSetAttribute(gemm_qkv_fused,  cudaFuncAttributeMaxDynamicSharedMemorySize, QKV_SMEM);
    cudaFuncSetAttribute(attn_tc_kernel,  cudaFuncAttributeMaxDynamicSharedMemorySize, ATTN_SMEM);

    // launch order: ncu (-s 5 -c 1) captures index 5 = O-proj GEMM
    prep_kernel<<<12, 256>>>(mask, q_b, k_b, v_b, geff, bias);                      // 0
    convA_kernel<<<2048, 256>>>(x, Apack);                                          // 1
    convB_all<<<dim3(144, 64), 256>>>(q_w, k_w, v_w, o_w, Bqkv, Bow);               // 2
    gemm_qkv_fused<<<dim3(NQKV / 128, 32), 256, QKV_SMEM>>>(                         // 3
        Apack, Bqkv, bias, cosb, sinb, mask, q_gamma, k_gamma, Qpk, Kpk, Vpk);
    attn_tc_kernel<<<512, 128, ATTN_SMEM>>>(Qpk, Kpk, Vpk, geff, Apack);            // 4
    gemm_mma_kernel<<<dim3(16, 16), 256, GEMM_SMEM>>>(Apack, Bow, out, 2048);       // 5
}

// round 13
// speedup vs baseline: 2.4177x; 1.0640x over previous
#include <cuda_runtime.h>
#include <cuda_fp16.h>
#include <math.h>
#include <stdint.h>

#define B_   2
#define S_   1024
#define HID_ 2048
#define NH_  16
#define NKV_ 2
#define HD_  128
#define G_   (NH_/NKV_)
#define TOK  (B_*S_)

#define KP   2048
#define NQKV 2560

// ---------------- scratch ----------------
#define OFF_EFF  0
#define OFF_BIAS 4
#define OFF_APK  2564
#define OFF_BQKV 2099716
#define OFF_BOW  4721156
#define OFF_QPK  6818308
#define OFF_KPK  8915460
#define OFF_VPK  9177604
#define SCRATCH_F 9439748
__device__ __align__(256) float g_scratch[SCRATCH_F];

// ---------------- helpers ----------------
__device__ __forceinline__ uint32_t smem_u32(const void* p) {
    uint32_t a;
    asm("{ .reg .u64 t; cvta.to.shared.u64 t, %1; cvt.u32.u64 %0, t; }" : "=r"(a) : "l"(p));
    return a;
}
__device__ __forceinline__ uint32_t pack2(unsigned short a, unsigned short b) {
    return (uint32_t)a | ((uint32_t)b << 16);
}
__device__ __forceinline__ void cp_async16(uint32_t saddr, const void* gaddr) {
    asm volatile("cp.async.cg.shared.global [%0], [%1], 16;" :: "r"(saddr), "l"(gaddr));
}
__device__ __forceinline__ void cp_commit() {
    asm volatile("cp.async.commit_group;");
}
template <int N>
__device__ __forceinline__ void cp_wait() {
    asm volatile("cp.async.wait_group %0;" :: "n"(N));
}
__device__ __forceinline__ void ldsm_x4(uint32_t* f, uint32_t addr) {
    asm volatile("ldmatrix.sync.aligned.m8n8.x4.shared.b16 {%0,%1,%2,%3}, [%4];"
                 : "=r"(f[0]), "=r"(f[1]), "=r"(f[2]), "=r"(f[3]) : "r"(addr));
}
__device__ __forceinline__ void ldsm_x4_t(uint32_t* f, uint32_t addr) {
    asm volatile("ldmatrix.sync.aligned.m8n8.x4.trans.shared.b16 {%0,%1,%2,%3}, [%4];"
                 : "=r"(f[0]), "=r"(f[1]), "=r"(f[2]), "=r"(f[3]) : "r"(addr));
}
__device__ __forceinline__ void mma_16816(float* c, const uint32_t* a, uint32_t b0, uint32_t b1) {
    asm volatile(
        "mma.sync.aligned.m16n8k16.row.col.f32.f16.f16.f32 "
        "{%0,%1,%2,%3}, {%4,%5,%6,%7}, {%8,%9}, {%0,%1,%2,%3};"
        : "+f"(c[0]), "+f"(c[1]), "+f"(c[2]), "+f"(c[3])
        : "r"(a[0]), "r"(a[1]), "r"(a[2]), "r"(a[3]), "r"(b0), "r"(b1));
}
__device__ __forceinline__ uint32_t csw8(uint32_t c, uint32_t row) {
    return (c & 0x8u) | ((c ^ (row & 7u)) & 0x7u);
}

// ---------------- fused prep + convA + convB (one launch) ----------------
// blocks: [0,2048) convA; [2048,2048+9216) convB (144 x 64 flattened); last 12: prep
#define CONVB_BLKS (144 * 64)
__global__ void __launch_bounds__(256) conv_all_kernel(
    const float* __restrict__ X,
    const float* __restrict__ qw, const float* __restrict__ kw,
    const float* __restrict__ vw, const float* __restrict__ ow,
    const float* __restrict__ mask,
    const float* __restrict__ qb, const float* __restrict__ kb,
    const float* __restrict__ vb,
    __half* __restrict__ Ap, __half* __restrict__ Bqkv, __half* __restrict__ Bow,
    float* __restrict__ eff, float* __restrict__ bias)
{
    int blk = blockIdx.x;
    int tid = threadIdx.x;

    if (blk < 2048) {
        // ---- convA ----
        int g = blk * 256 + tid;
        int m = g >> 8;
        int kg = (g & 255) << 3;
        const float* xp = X + ((size_t)m << 11) + kg;
        float f[8];
        *(float4*)f       = *(const float4*)xp;
        *(float4*)(f + 4) = *(const float4*)(xp + 4);
        unsigned short h[8];
        #pragma unroll
        for (int i = 0; i < 8; i++) h[i] = __half_as_ushort(__float2half_rn(f[i]));
        *(uint4*)(Ap + (size_t)m * KP + kg) =
            make_uint4(pack2(h[0],h[1]), pack2(h[2],h[3]), pack2(h[4],h[5]), pack2(h[6],h[7]));
        return;
    }
    blk -= 2048;
    if (blk < CONVB_BLKS) {
        // ---- convB ----
        __shared__ float s[32][33];
        int bx = blk % 144, by = blk / 144;
        const float* W; __half* Bp; int N, noff, nx;
        if (bx < 64)      { W = qw; Bp = Bqkv; N = 2048; noff = 0;    nx = bx; }
        else if (bx < 72) { W = kw; Bp = Bqkv; N = 256;  noff = 2048; nx = bx - 64; }
        else if (bx < 80) { W = vw; Bp = Bqkv; N = 256;  noff = 2304; nx = bx - 72; }
        else              { W = ow; Bp = Bow;  N = 2048; noff = 0;    nx = bx - 80; }
        int n0 = nx << 5, k0 = by << 5;
        #pragma unroll
        for (int p = 0; p < 4; p++) {
            int e = tid + p * 256;
            int ki = e >> 5, ni = e & 31;
            s[ki][ni] = W[(size_t)(k0 + ki) * N + n0 + ni];
        }
        __syncthreads();
        if (tid < 128) {
            int ni = tid >> 2, kg = (tid & 3) << 3;
            unsigned short h[8];
            #pragma unroll
            for (int j = 0; j < 8; j++) h[j] = __half_as_ushort(__float2half_rn(s[kg + j][ni]));
            *(uint4*)(Bp + (size_t)(noff + n0 + ni) * KP + k0 + kg) =
                make_uint4(pack2(h[0],h[1]), pack2(h[2],h[3]), pack2(h[4],h[5]), pack2(h[6],h[7]));
        }
        return;
    }
    blk -= CONVB_BLKS;
    // ---- prep ----
    if (blk < 2) {
        float s = 0.f;
        for (int i = tid; i < S_; i += blockDim.x) s += mask[blk * S_ + i];
        #pragma unroll
        for (int off = 16; off; off >>= 1) s += __shfl_xor_sync(0xffffffffu, s, off);
        __shared__ float red[8];
        if ((tid & 31) == 0) red[tid >> 5] = s;
        __syncthreads();
        if (tid == 0) {
            float t = 0.f;
            for (int i = 0; i < 8; i++) t += red[i];
            eff[blk] = t;
        }
    } else {
        int i = (blk - 2) * 256 + tid;
        if (i < 2048) bias[i] = qb[i];
        else if (i < 2304) bias[i] = kb[i - 2048];
        else if (i < 2560) bias[i] = vb[i - 2304];
    }
}

// ================= O-proj GEMM (unchanged from R12) =================
#define BKC 32
#define STAGE_B 16384
#define GEMM_SMEM 65536
#define KITERS (KP / BKC)

__device__ __forceinline__ void stage_load(uint32_t sbase, int stage,
                                           const __half* Ag, const __half* Bg,
                                           int k0, int lrow, int lchunk) {
    uint32_t sa = sbase + stage * STAGE_B;
    #pragma unroll
    for (int i = 0; i < 2; i++) {
        int row = lrow + i * 64;
        uint32_t sw = (uint32_t)((lchunk ^ ((row >> 1) & 3)) << 4);
        cp_async16(sa + row * 64 + sw,        Ag + (size_t)row * KP + k0 + lchunk * 8);
        cp_async16(sa + 8192 + row * 64 + sw, Bg + (size_t)row * KP + k0 + lchunk * 8);
    }
}

__global__ void __launch_bounds__(256, 2) gemm_mma_kernel(
    const __half* __restrict__ A, const __half* __restrict__ Bm,
    float* __restrict__ C, int Ntot)
{
    extern __shared__ char smc[];
    uint32_t sbase = smem_u32(smc);
    const int tid = threadIdx.x;
    const int mt = blockIdx.y, nt = blockIdx.x;
    const int warp = tid >> 5, lane = tid & 31;
    const int wm = warp >> 2, wn = warp & 3;
    const int lrow = tid >> 2;
    const int lchunk = tid & 3;
    const int arow = wm * 64 + ((lane >> 3) & 1) * 8 + (lane & 7);
    const int achi = (lane >> 4) & 1;
    const uint32_t asw = (uint32_t)((arow >> 1) & 3);
    const uint32_t abase = (uint32_t)(arow * 64);
    const int brow = wn * 32 + ((lane >> 4) & 1) * 8 + (lane & 7);
    const int bclo = (lane >> 3) & 1;
    const uint32_t bsw = (uint32_t)((brow >> 1) & 3);
    const uint32_t bbase = (uint32_t)(brow * 64);
    float acc[16][4];
    #pragma unroll
    for (int i = 0; i < 16; i++) { acc[i][0]=0.f; acc[i][1]=0.f; acc[i][2]=0.f; acc[i][3]=0.f; }

    const __half* Ag = A  + (size_t)(mt * 128) * KP;
    const __half* Bg = Bm + (size_t)(nt * 128) * KP;

    #pragma unroll
    for (int s = 0; s < 3; s++) { stage_load(sbase, s, Ag, Bg, s * BKC, lrow, lchunk); cp_commit(); }
    cp_wait<2>();
    __syncthreads();

    for (int kt = 0; kt < KITERS; kt++) {
        uint32_t sa = sbase + (kt & 3) * STAGE_B;
        uint32_t sb = sa + 8192;

        uint32_t af0[4][4], af1[4][4], bf00[4], bf01[4];
        #pragma unroll
        for (int m = 0; m < 4; m++)
            ldsm_x4(af0[m], sa + abase + m * 1024 + ((((uint32_t)achi) ^ asw) << 4));
        ldsm_x4(bf00, sb + bbase +        ((((uint32_t)bclo) ^ bsw) << 4));
        ldsm_x4(bf01, sb + bbase + 1024 + ((((uint32_t)bclo) ^ bsw) << 4));
        #pragma unroll
        for (int m = 0; m < 4; m++)
            ldsm_x4(af1[m], sa + abase + m * 1024 + ((((uint32_t)(2 + achi)) ^ asw) << 4));

        cp_wait<1>();
        __syncthreads();

        int nxt = kt + 3;
        if (nxt < KITERS) stage_load(sbase, nxt & 3, Ag, Bg, nxt * BKC, lrow, lchunk);
        cp_commit();

        #pragma unroll
        for (int m = 0; m < 4; m++) {
            mma_16816(acc[m * 4 + 0], af0[m], bf00[0], bf00[1]);
            mma_16816(acc[m * 4 + 1], af0[m], bf00[2], bf00[3]);
            mma_16816(acc[m * 4 + 2], af0[m], bf01[0], bf01[1]);
            mma_16816(acc[m * 4 + 3], af0[m], bf01[2], bf01[3]);
        }
        uint32_t bf10[4], bf11[4];
        ldsm_x4(bf10, sb + bbase +        ((((uint32_t)(2 + bclo)) ^ bsw) << 4));
        ldsm_x4(bf11, sb + bbase + 1024 + ((((uint32_t)(2 + bclo)) ^ bsw) << 4));
        #pragma unroll
        for (int m = 0; m < 4; m++) {
            mma_16816(acc[m * 4 + 0], af1[m], bf10[0], bf10[1]);
            mma_16816(acc[m * 4 + 1], af1[m], bf10[2], bf10[3]);
            mma_16816(acc[m * 4 + 2], af1[m], bf11[0], bf11[1]);
            mma_16816(acc[m * 4 + 3], af1[m], bf11[2], bf11[3]);
        }
    }

    #pragma unroll
    for (int n = 0; n < 4; n++) {
        int col = nt * 128 + wn * 32 + n * 8 + (lane & 3) * 2;
        #pragma unroll
        for (int m = 0; m < 4; m++) {
            int row = mt * 128 + wm * 64 + m * 16 + (lane >> 2);
            *(float2*)(C + (size_t)row * Ntot + col)       = make_float2(acc[m*4+n][0], acc[m*4+n][1]);
            *(float2*)(C + (size_t)(row + 8) * Ntot + col) = make_float2(acc[m*4+n][2], acc[m*4+n][3]);
        }
    }
}

// ================= fused QKV GEMM (unchanged from R12) =================
#define QSTAGE_B 12288
#define QKV_SMEM 49152

__device__ __forceinline__ void qstage_load(uint32_t sbase, int stage,
                                            const __half* Ag, const __half* Bg,
                                            int k0, int tid) {
    uint32_t sa = sbase + stage * QSTAGE_B;
    uint32_t sb = sa + 4096;
    int r = tid >> 2, c = tid & 3;
    uint32_t swa = (uint32_t)((c ^ ((r >> 1) & 3)) << 4);
    if (r < 64)
        cp_async16(sa + r * 64 + swa, Ag + (size_t)r * KP + k0 + c * 8);
    #pragma unroll
    for (int i = 0; i < 2; i++) {
        int rb = r + i * 64;
        uint32_t swb = (uint32_t)((c ^ ((rb >> 1) & 3)) << 4);
        cp_async16(sb + rb * 64 + swb, Bg + (size_t)rb * KP + k0 + c * 8);
    }
}

__global__ void __launch_bounds__(256, 2) gemm_qkv_fused(
    const __half* __restrict__ A, const __half* __restrict__ Bm,
    const float* __restrict__ bias,
    const float* __restrict__ cosb, const float* __restrict__ sinb,
    const float* __restrict__ mask,
    const float* __restrict__ q_gamma, const float* __restrict__ k_gamma,
    __half* __restrict__ Qpk, __half* __restrict__ Kpk, __half* __restrict__ Vpk)
{
    extern __shared__ char smc[];
    __shared__ float ssq[4][64];
    uint32_t sbase = smem_u32(smc);
    const int tid = threadIdx.x;
    const int nt = blockIdx.x, mt = blockIdx.y;
    const int warp = tid >> 5, lane = tid & 31;
    const int wm = warp >> 2, wn = warp & 3;

    const int arow = wm * 32 + ((lane >> 3) & 1) * 8 + (lane & 7);
    const int achi = (lane >> 4) & 1;
    const uint32_t asw = (uint32_t)((arow >> 1) & 3);
    const uint32_t abase = (uint32_t)(arow * 64);
    const int brow = wn * 32 + ((lane >> 4) & 1) * 8 + (lane & 7);
    const int bclo = (lane >> 3) & 1;
    const uint32_t bsw = (uint32_t)((brow >> 1) & 3);
    const uint32_t bbase = (uint32_t)(brow * 64);

    float acc[8][4];
    #pragma unroll
    for (int i = 0; i < 8; i++) { acc[i][0]=0.f; acc[i][1]=0.f; acc[i][2]=0.f; acc[i][3]=0.f; }

    const __half* Ag = A  + (size_t)(mt * 64) * KP;
    const __half* Bg = Bm + (size_t)(nt * 128) * KP;

    #pragma unroll
    for (int s = 0; s < 3; s++) { qstage_load(sbase, s, Ag, Bg, s * BKC, tid); cp_commit(); }
    cp_wait<2>();
    __syncthreads();

    for (int kt = 0; kt < KITERS; kt++) {
        uint32_t sa = sbase + (kt & 3) * QSTAGE_B;
        uint32_t sb = sa + 4096;

        uint32_t af0[2][4], af1[2][4], bf00[4], bf01[4];
        #pragma unroll
        for (int m = 0; m < 2; m++)
            ldsm_x4(af0[m], sa + abase + m * 1024 + ((((uint32_t)achi) ^ asw) << 4));
        ldsm_x4(bf00, sb + bbase +        ((((uint32_t)bclo) ^ bsw) << 4));
        ldsm_x4(bf01, sb + bbase + 1024 + ((((uint32_t)bclo) ^ bsw) << 4));
        #pragma unroll
        for (int m = 0; m < 2; m++)
            ldsm_x4(af1[m], sa + abase + m * 1024 + ((((uint32_t)(2 + achi)) ^ asw) << 4));

        cp_wait<1>();
        __syncthreads();

        int nxt = kt + 3;
        if (nxt < KITERS) qstage_load(sbase, nxt & 3, Ag, Bg, nxt * BKC, tid);
        cp_commit();

        #pragma unroll
        for (int m = 0; m < 2; m++) {
            mma_16816(acc[m * 4 + 0], af0[m], bf00[0], bf00[1]);
            mma_16816(acc[m * 4 + 1], af0[m], bf00[2], bf00[3]);
            mma_16816(acc[m * 4 + 2], af0[m], bf01[0], bf01[1]);
            mma_16816(acc[m * 4 + 3], af0[m], bf01[2], bf01[3]);
        }
        uint32_t bf10[4], bf11[4];
        ldsm_x4(bf10, sb + bbase +        ((((uint32_t)(2 + bclo)) ^ bsw) << 4));
        ldsm_x4(bf11, sb + bbase + 1024 + ((((uint32_t)(2 + bclo)) ^ bsw) << 4));
        #pragma unroll
        for (int m = 0; m < 2; m++) {
            mma_16816(acc[m * 4 + 0], af1[m], bf10[0], bf10[1]);
            mma_16816(acc[m * 4 + 1], af1[m], bf10[2], bf10[3]);
            mma_16816(acc[m * 4 + 2], af1[m], bf11[0], bf11[1]);
            mma_16816(acc[m * 4 + 3], af1[m], bf11[2], bf11[3]);
        }
    }

    cp_wait<0>();
    __syncthreads();

    #pragma unroll
    for (int n = 0; n < 4; n++) {
        int col = wn * 32 + n * 8 + (lane & 3) * 2;
        float b0 = bias[nt * 128 + col];
        float b1 = bias[nt * 128 + col + 1];
        #pragma unroll
        for (int m = 0; m < 2; m++) {
            acc[m*4+n][0] += b0; acc[m*4+n][1] += b1;
            acc[m*4+n][2] += b0; acc[m*4+n][3] += b1;
        }
    }

    if (nt >= 18) {
        int kh = nt - 18;
        #pragma unroll
        for (int m = 0; m < 2; m++) {
            int t0 = mt * 64 + wm * 32 + m * 16 + (lane >> 2);
            int b0g = t0 >> 10, s0g = t0 & 1023;
            float mv0 = mask[t0], mv1 = mask[t0 + 8];
            __half* vp0 = Vpk + ((size_t)(b0g * NKV_ + kh) * S_ + s0g) * 128;
            __half* vp1 = vp0 + 8 * 128;
            #pragma unroll
            for (int n = 0; n < 4; n++) {
                int col = wn * 32 + n * 8 + (lane & 3) * 2;
                *(__half2*)(vp0 + col) = __floats2half2_rn(acc[m*4+n][0] * mv0, acc[m*4+n][1] * mv0);
                *(__half2*)(vp1 + col) = __floats2half2_rn(acc[m*4+n][2] * mv1, acc[m*4+n][3] * mv1);
            }
        }
        return;
    }

    const bool isQ = (nt < 16);
    const float* gamma = isQ ? q_gamma : k_gamma;
    float* snv = (float*)smc;

    #pragma unroll
    for (int m = 0; m < 2; m++) {
        float a0 = 0.f, a1 = 0.f;
        #pragma unroll
        for (int n = 0; n < 4; n++) {
            a0 += acc[m*4+n][0]*acc[m*4+n][0] + acc[m*4+n][1]*acc[m*4+n][1];
            a1 += acc[m*4+n][2]*acc[m*4+n][2] + acc[m*4+n][3]*acc[m*4+n][3];
        }
        a0 += __shfl_xor_sync(0xffffffffu, a0, 1);
        a0 += __shfl_xor_sync(0xffffffffu, a0, 2);
        a1 += __shfl_xor_sync(0xffffffffu, a1, 1);
        a1 += __shfl_xor_sync(0xffffffffu, a1, 2);
        if ((lane & 3) == 0) {
            int r0 = wm * 32 + m * 16 + (lane >> 2);
            ssq[wn][r0]     = a0;
            ssq[wn][r0 + 8] = a1;
        }
    }
    __syncthreads();

    #pragma unroll
    for (int m = 0; m < 2; m++) {
        int r0 = wm * 32 + m * 16 + (lane >> 2);
        int r1 = r0 + 8;
        float tot0 = ssq[0][r0] + ssq[1][r0] + ssq[2][r0] + ssq[3][r0];
        float tot1 = ssq[0][r1] + ssq[1][r1] + ssq[2][r1] + ssq[3][r1];
        float rms0 = rsqrtf(tot0 * (1.0f / HD_) + 1e-6f);
        float rms1 = rsqrtf(tot1 * (1.0f / HD_) + 1e-6f);
        #pragma unroll
        for (int n = 0; n < 4; n++) {
            int d0 = wn * 32 + n * 8 + (lane & 3) * 2;
            float g0 = gamma[d0], g1 = gamma[d0 + 1];
            snv[r0 * 128 + ((d0     + 4 * r0) & 127)] = acc[m*4+n][0] * rms0 * g0;
            snv[r0 * 128 + ((d0 + 1 + 4 * r0) & 127)] = acc[m*4+n][1] * rms0 * g1;
            snv[r1 * 128 + ((d0     + 4 * r1) & 127)] = acc[m*4+n][2] * rms1 * g0;
            snv[r1 * 128 + ((d0 + 1 + 4 * r1) & 127)] = acc[m*4+n][3] * rms1 * g1;
        }
    }
    __syncthreads();

    int hh = isQ ? nt : (nt - 16);
    int d0 = lane * 4;
    int sec = (d0 < 16) ? 0 : (d0 < 40) ? 1 : (d0 < 64) ? 2 : (d0 < 80) ? 0 : (d0 < 104) ? 1 : 2;
    #pragma unroll 1
    for (int rr = 0; rr < 8; rr++) {
        int row = warp * 8 + rr;
        int t = mt * 64 + row;
        int bb = t >> 10, s = t & 1023;
        size_t ci = (((size_t)sec * B_ + bb) * S_ + s) * HD_ + d0;
        float c4[4], s4[4];
        *(float4*)c4 = *(const float4*)(cosb + ci);
        *(float4*)s4 = *(const float4*)(sinb + ci);
        float outv[4];
        #pragma unroll
        for (int j = 0; j < 4; j++) {
            int d = d0 + j;
            float nv = snv[row * 128 + ((d + 4 * row) & 127)];
            float pn = snv[row * 128 + (((d ^ 64) + 4 * row) & 127)];
            float part = (d < 64) ? -pn : pn;
            outv[j] = nv * c4[j] + part * s4[j];
        }
        unsigned short h[4];
        if (isQ) {
            #pragma unroll
            for (int j = 0; j < 4; j++) h[j] = __half_as_ushort(__float2half_rn(outv[j]));
            __half* qp = Qpk + ((size_t)(bb * NH_ + hh) * S_ + s) * 128;
            *(uint2*)(qp + d0) = make_uint2(pack2(h[0], h[1]), pack2(h[2], h[3]));
        } else {
            float mval = mask[t];
            #pragma unroll
            for (int j = 0; j < 4; j++) h[j] = __half_as_ushort(__float2half_rn(outv[j] * mval));
            __half* kp = Kpk + ((size_t)(bb * NKV_ + hh) * S_ + s) * 128;
            *(uint2*)(kp + d0) = make_uint2(pack2(h[0], h[1]), pack2(h[2], h[3]));
        }
    }
}

// ---------------- tensor-core flash attention (P plain fp16, no Pl term) ----------------
#define ATTN_SMEM 81920

__global__ void __launch_bounds__(128, 2) attn_tc_kernel(
    const __half* __restrict__ Qpk, const __half* __restrict__ Kpk,
    const __half* __restrict__ Vpk, const float* __restrict__ eff,
    __half* __restrict__ Apk)
{
    extern __shared__ char smc[];
    uint32_t sbase = smem_u32(smc);

    int bid = blockIdx.x;
    int qt = 15 - (bid >> 5);
    int rem = bid & 31;
    int h = rem >> 1, b = rem & 1;
    int kvh = h / G_;
    int tid = threadIdx.x, warp = tid >> 5, lane = tid & 31;

    const __half* Qg = Qpk + ((size_t)(b * NH_ + h) * S_ + qt * 64) * 128;
    const __half* Kg = Kpk + ((size_t)(b * NKV_ + kvh) * S_) * 128;
    const __half* Vg = Vpk + ((size_t)(b * NKV_ + kvh) * S_) * 128;

    #pragma unroll
    for (int it = 0; it < 8; it++) {
        int idx = it * 128 + tid;
        int r = idx >> 4, c = idx & 15;
        cp_async16(sbase + r * 256 + csw8(c, r) * 16, Qg + (size_t)r * 128 + c * 8);
    }
    cp_commit();
    cp_wait<0>();
    __syncthreads();

    uint32_t qh[8][4];
    {
        int row = warp * 16 + ((lane >> 3) & 1) * 8 + (lane & 7);
        uint32_t roff = sbase + row * 256;
        uint32_t r7 = row & 7;
        int chi = (lane >> 4) & 1;
        #pragma unroll
        for (int j = 0; j < 8; j++) {
            uint32_t ch = 2 * j + chi;
            ldsm_x4(qh[j], roff + ((ch & 8u) | ((ch ^ r7) & 7u)) * 16);
        }
    }

    int ntiles = qt + 1;
    int eff_i = (int)(eff[b] + 0.5f);

    #pragma unroll
    for (int pt = 0; pt < 2; pt++) {
        if (pt < ntiles) {
            #pragma unroll
            for (int it = 0; it < 8; it++) {
                int idx = it * 128 + tid;
                int r = idx >> 4, c = idx & 15;
                uint32_t ds = 16384u + (uint32_t)pt * 32768 + r * 256 + csw8(c, r) * 16;
                size_t go = (size_t)(pt * 64 + r) * 128 + c * 8;
                cp_async16(sbase + ds,         Kg + go);
                cp_async16(sbase + ds + 16384, Vg + go);
            }
        }
        cp_commit();
    }

    float m0 = -1e30f, m1 = -1e30f, ls0 = 0.f, ls1 = 0.f;
    float o[16][4];
    #pragma unroll
    for (int i = 0; i < 16; i++) { o[i][0] = o[i][1] = o[i][2] = o[i][3] = 0.f; }

    const float scale = 0.08838834764831845f;
    int row0 = qt * 64 + warp * 16 + (lane >> 2);
    int colb = (lane & 3) * 2;
    int krbase = ((lane >> 4) & 1) * 8 + (lane & 7);
    int kchi = (lane >> 3) & 1;
    int vrbase = ((lane >> 3) & 1) * 8 + (lane & 7);
    int vchi = (lane >> 4) & 1;

    for (int kt = 0; kt < ntiles; kt++) {
        cp_wait<1>();
        __syncthreads();
        uint32_t sk = sbase + 16384u + (uint32_t)(kt & 1) * 32768;
        uint32_t sv = sk + 16384;

        float s[8][4];
        #pragma unroll
        for (int i = 0; i < 8; i++) { s[i][0] = s[i][1] = s[i][2] = s[i][3] = 0.f; }

        #pragma unroll
        for (int nbp = 0; nbp < 4; nbp++) {
            int krow = nbp * 16 + krbase;
            uint32_t kroff = sk + krow * 256;
            uint32_t kr7 = krow & 7;
            #pragma unroll
            for (int j = 0; j < 8; j++) {
                uint32_t ch = 2 * j + kchi;
                uint32_t kf[4];
                ldsm_x4(kf, kroff + ((ch & 8u) | ((ch ^ kr7) & 7u)) * 16);
                mma_16816(s[2*nbp],   qh[j], kf[0], kf[1]);
                mma_16816(s[2*nbp+1], qh[j], kf[2], kf[3]);
            }
        }

        float mx0 = -1e30f, mx1 = -1e30f;
        #pragma unroll
        for (int nb = 0; nb < 8; nb++) {
            int c0 = kt * 64 + nb * 8 + colb;
            #pragma unroll
            for (int e = 0; e < 2; e++) {
                int cc = c0 + e;
                float v0 = (cc <= row0     && cc < eff_i) ? s[nb][e]   * scale : -1e9f;
                float v1 = (cc <= row0 + 8 && cc < eff_i) ? s[nb][2+e] * scale : -1e9f;
                s[nb][e] = v0; s[nb][2+e] = v1;
                mx0 = fmaxf(mx0, v0); mx1 = fmaxf(mx1, v1);
            }
        }
        mx0 = fmaxf(mx0, __shfl_xor_sync(0xffffffffu, mx0, 1));
        mx0 = fmaxf(mx0, __shfl_xor_sync(0xffffffffu, mx0, 2));
        mx1 = fmaxf(mx1, __shfl_xor_sync(0xffffffffu, mx1, 1));
        mx1 = fmaxf(mx1, __shfl_xor_sync(0xffffffffu, mx1, 2));
        float m0n = fmaxf(m0, mx0), m1n = fmaxf(m1, mx1);
        float cr0 = __expf(m0 - m0n), cr1 = __expf(m1 - m1n);
        float sum0 = 0.f, sum1 = 0.f;
        #pragma unroll
        for (int nb = 0; nb < 8; nb++) {
            #pragma unroll
            for (int e = 0; e < 2; e++) {
                float p0 = __expf(s[nb][e]   - m0n);
                float p1 = __expf(s[nb][2+e] - m1n);
                s[nb][e] = p0; s[nb][2+e] = p1;
                sum0 += p0; sum1 += p1;
            }
        }
        sum0 += __shfl_xor_sync(0xffffffffu, sum0, 1);
        sum0 += __shfl_xor_sync(0xffffffffu, sum0, 2);
        sum1 += __shfl_xor_sync(0xffffffffu, sum1, 1);
        sum1 += __shfl_xor_sync(0xffffffffu, sum1, 2);
        ls0 = ls0 * cr0 + sum0; m0 = m0n;
        ls1 = ls1 * cr1 + sum1; m1 = m1n;
        #pragma unroll
        for (int i = 0; i < 16; i++) {
            o[i][0] *= cr0; o[i][1] *= cr0;
            o[i][2] *= cr1; o[i][3] *= cr1;
        }

        // ---- P -> plain fp16 A-fragments ----
        uint32_t ph[4][4];
        #pragma unroll
        for (int j2 = 0; j2 < 4; j2++) {
            #pragma unroll
            for (int q = 0; q < 4; q++) {
                int nb = 2 * j2 + (q >> 1);
                int e  = (q & 1) * 2;
                unsigned short ha = __half_as_ushort(__float2half_rn(s[nb][e]));
                unsigned short hb = __half_as_ushort(__float2half_rn(s[nb][e + 1]));
                ph[j2][(q >> 1) * 2 + (q & 1)] = pack2(ha, hb);
            }
        }

        // ---- O += Ph V ----
        #pragma unroll
        for (int j2 = 0; j2 < 4; j2++) {
            int vrow = j2 * 16 + vrbase;
            uint32_t vroff = sv + vrow * 256;
            uint32_t vr7 = vrow & 7;
            #pragma unroll
            for (int nbp = 0; nbp < 8; nbp++) {
                uint32_t ch = 2 * nbp + vchi;
                uint32_t vf[4];
                ldsm_x4_t(vf, vroff + ((ch & 8u) | ((ch ^ vr7) & 7u)) * 16);
                mma_16816(o[2*nbp],   ph[j2], vf[0], vf[1]);
                mma_16816(o[2*nbp+1], ph[j2], vf[2], vf[3]);
            }
        }

        __syncthreads();
        int nxt = kt + 2;
        if (nxt < ntiles) {
            #pragma unroll
            for (int it = 0; it < 8; it++) {
                int idx = it * 128 + tid;
                int r = idx >> 4, c = idx & 15;
                uint32_t ds = 16384u + (uint32_t)(kt & 1) * 32768 + r * 256 + csw8(c, r) * 16;
                size_t go = (size_t)(nxt * 64 + r) * 128 + c * 8;
                cp_async16(sbase + ds,         Kg + go);
                cp_async16(sbase + ds + 16384, Vg + go);
            }
        }
        cp_commit();
    }

    float inv0 = 1.0f / ls0, inv1 = 1.0f / ls1;
    int t0 = b * S_ + qt * 64 + warp * 16 + (lane >> 2);
    size_t r0b = (size_t)t0 * KP;
    size_t r1b = (size_t)(t0 + 8) * KP;
    #pragma unroll
    for (int db = 0; db < 16; db++) {
        int c = h * 128 + db * 8 + colb;
        __half h0 = __float2half_rn(o[db][0] * inv0);
        __half h1 = __float2half_rn(o[db][1] * inv0);
        *(uint32_t*)(Apk + r0b + c) = pack2(__half_as_ushort(h0), __half_as_ushort(h1));
        h0 = __float2half_rn(o[db][2] * inv1);
        h1 = __float2half_rn(o[db][3] * inv1);
        *(uint32_t*)(Apk + r1b + c) = pack2(__half_as_ushort(h0), __half_as_ushort(h1));
    }
}

// ---------------- launcher ----------------
extern "C" void kernel_launch(void* const* d_in, const int* in_sizes, int n_in,
                              void* d_out, int out_size)
{
    const float* x       = (const float*)d_in[0];
    const float* cosb    = (const float*)d_in[1];
    const float* sinb    = (const float*)d_in[2];
    const float* mask    = (const float*)d_in[3];
    const float* q_w     = (const float*)d_in[4];
    const float* q_b     = (const float*)d_in[5];
    const float* k_w     = (const float*)d_in[6];
    const float* k_b     = (const float*)d_in[7];
    const float* v_w     = (const float*)d_in[8];
    const float* v_b     = (const float*)d_in[9];
    const float* q_gamma = (const float*)d_in[10];
    const float* k_gamma = (const float*)d_in[11];
    const float* o_w     = (const float*)d_in[12];
    float* out = (float*)d_out;

    float* scratch = nullptr;
    cudaGetSymbolAddress((void**)&scratch, g_scratch);
    float* geff = scratch + OFF_EFF;
    float* bias = scratch + OFF_BIAS;
    __half* Apack = (__half*)(scratch + OFF_APK);
    __half* Bqkv  = (__half*)(scratch + OFF_BQKV);
    __half* Bow   = (__half*)(scratch + OFF_BOW);
    __half* Qpk   = (__half*)(scratch + OFF_QPK);
    __half* Kpk   = (__half*)(scratch + OFF_KPK);
    __half* Vpk   = (__half*)(scratch + OFF_VPK);

    cudaFuncSetAttribute(gemm_mma_kernel, cudaFuncAttributeMaxDynamicSharedMemorySize, GEMM_SMEM);
    cudaFuncSetAttribute(gemm_qkv_fused,  cudaFuncAttributeMaxDynamicSharedMemorySize, QKV_SMEM);
    cudaFuncSetAttribute(attn_tc_kernel,  cudaFuncAttributeMaxDynamicSharedMemorySize, ATTN_SMEM);

    conv_all_kernel<<<2048 + CONVB_BLKS + 12, 256>>>(
        x, q_w, k_w, v_w, o_w, mask, q_b, k_b, v_b,
        Apack, Bqkv, Bow, geff, bias);
    gemm_qkv_fused<<<dim3(NQKV / 128, 32), 256, QKV_SMEM>>>(
        Apack, Bqkv, bias, cosb, sinb, mask, q_gamma, k_gamma, Qpk, Kpk, Vpk);
    attn_tc_kernel<<<512, 128, ATTN_SMEM>>>(Qpk, Kpk, Vpk, geff, Apack);
    gemm_mma_kernel<<<dim3(16, 16), 256, GEMM_SMEM>>>(Apack, Bow, out, 2048);
}